// round 4
// baseline (speedup 1.0000x reference)
#include <cuda_runtime.h>
#include <math.h>

#define BB 4
#define CC 64
#define HH 256
#define WWD 256
#define HW 65536
#define NF (BB*CC*HW)       /* 16777216 */
#define W129 129
#define PF (HH*W129)        /* 33024 */

// ---------------- scratch ----------------
__device__ float g_fre[NF];
__device__ float g_spa[NF];
__device__ float g_q[NF];
__device__ float g_tmpA[2*NF];
__device__ float g_tmpB[2*NF];
__device__ float g_fqA[(size_t)BB*2*CC*PF];
__device__ float g_fqB[(size_t)BB*2*CC*PF];
__device__ float g_sumsq[2*BB*CC];   // 512: [0..255]=q, [256..511]=k
__device__ float g_gram[BB*8*64];    // 2048
__device__ float g_M[BB*CC*CC];      // 16384

// ---------------- full 3x3 conv (C=64 fixed) ----------------
__global__ void conv3x3_kernel(const float* __restrict__ in, float* __restrict__ out,
                               const float* __restrict__ W, const float* __restrict__ bias,
                               const float* __restrict__ residual, int relu)
{
    __shared__ float sIn[18*18];
    __shared__ float sW[16*9];
    int b  = blockIdx.z >> 2;
    int og = (blockIdx.z & 3) * 16;
    int ty0 = blockIdx.y * 16, tx0 = blockIdx.x * 16;
    int tx = threadIdx.x & 15, ty = threadIdx.x >> 4;
    float acc[16];
#pragma unroll
    for (int o = 0; o < 16; o++) acc[o] = 0.f;

    for (int ci = 0; ci < 64; ci++) {
        for (int idx = threadIdx.x; idx < 324; idx += 256) {
            int iy = idx / 18, ix = idx % 18;
            int gy = ty0 - 1 + iy, gx = tx0 - 1 + ix;
            float v = 0.f;
            if (gy >= 0 && gy < 256 && gx >= 0 && gx < 256)
                v = in[((size_t)(b*64 + ci)*256 + gy)*256 + gx];
            sIn[idx] = v;
        }
        if (threadIdx.x < 144) {
            int o = threadIdx.x / 9, k = threadIdx.x % 9;
            sW[threadIdx.x] = W[((size_t)(og + o)*64 + ci)*9 + k];
        }
        __syncthreads();
        float r[9];
#pragma unroll
        for (int dy = 0; dy < 3; dy++)
#pragma unroll
            for (int dx = 0; dx < 3; dx++)
                r[dy*3+dx] = sIn[(ty+dy)*18 + tx+dx];
#pragma unroll
        for (int o = 0; o < 16; o++) {
            float a = acc[o];
#pragma unroll
            for (int k = 0; k < 9; k++) a += sW[o*9+k]*r[k];
            acc[o] = a;
        }
        __syncthreads();
    }
    int gy = ty0 + ty, gx = tx0 + tx;
#pragma unroll
    for (int o = 0; o < 16; o++) {
        int oc = og + o;
        float v = acc[o] + bias[oc];
        if (relu) v = fmaxf(v, 0.f);
        size_t idx = ((size_t)(b*64 + oc)*256 + gy)*256 + gx;
        if (residual) v += residual[idx];
        out[idx] = v;
    }
}

// ---------------- generic 1x1 conv (matmul over pixels) ----------------
// in[((b*CinTot + cInOff + i))*P + p], out[((b*CoutTot + cOutOff + o))*P + p]
// act: 0 none, 1 relu, 2 sigmoid. perBatchW: W += b*Cout*Cin. residual added last.
__global__ void conv1x1_kernel(const float* __restrict__ in, float* __restrict__ out,
                               const float* __restrict__ W, const float* __restrict__ bias,
                               const float* __restrict__ residual,
                               int Cin, int CinTot, int cInOff,
                               int Cout, int CoutTot, int cOutOff,
                               int P, int act, int perBatchW)
{
    __shared__ float Ws[32*128];
    __shared__ float Ins[128*32];
    int b  = blockIdx.z;
    int og = blockIdx.y * 32;
    int p0 = blockIdx.x * 32;
    const float* Wb = W + (perBatchW ? (size_t)b*Cout*Cin : 0);

    for (int idx = threadIdx.x; idx < 32*Cin; idx += 256) {
        int o = idx / Cin, i = idx % Cin;
        Ws[o*Cin + i] = Wb[(size_t)(og + o)*Cin + i];
    }
    for (int idx = threadIdx.x; idx < Cin*32; idx += 256) {
        int i = idx >> 5, p = idx & 31;
        int gp = p0 + p;
        Ins[i*32 + p] = (gp < P) ? in[((size_t)b*CinTot + cInOff + i)*P + gp] : 0.f;
    }
    __syncthreads();
    int pl = threadIdx.x & 31;
    int ob = (threadIdx.x >> 5) * 4;
    float a0 = 0.f, a1 = 0.f, a2 = 0.f, a3 = 0.f;
#pragma unroll 8
    for (int i = 0; i < Cin; i++) {
        float x = Ins[i*32 + pl];
        a0 += Ws[(ob+0)*Cin + i]*x;
        a1 += Ws[(ob+1)*Cin + i]*x;
        a2 += Ws[(ob+2)*Cin + i]*x;
        a3 += Ws[(ob+3)*Cin + i]*x;
    }
    int gp = p0 + pl;
    if (gp < P) {
        float accs[4] = {a0, a1, a2, a3};
#pragma unroll
        for (int j = 0; j < 4; j++) {
            int o = og + ob + j;
            float v = accs[j];
            if (bias) v += bias[o];
            if (act == 1) v = fmaxf(v, 0.f);
            else if (act == 2) v = 1.f/(1.f + expf(-v));
            size_t oi = ((size_t)b*CoutTot + cOutOff + o)*P + gp;
            if (residual) v += residual[oi];
            out[oi] = v;
        }
    }
}

// ---------------- depthwise 3x3 (pad 1) on 256x256 ----------------
__global__ void dw3x3_kernel(const float* __restrict__ in, float* __restrict__ out,
                             const float* __restrict__ w, const float* __restrict__ bias,
                             int CinTot, int cInOff, int CoutTot, int cOutOff)
{
    int b = blockIdx.z, c = blockIdx.y;
    int p = blockIdx.x*256 + threadIdx.x;
    int y = p >> 8, x = p & 255;
    const float* ip = in + ((size_t)b*CinTot + cInOff + c)*HW;
    float acc = bias ? bias[c] : 0.f;
#pragma unroll
    for (int dy = 0; dy < 3; dy++) {
        int gy = y + dy - 1;
        if ((unsigned)gy >= 256u) continue;
#pragma unroll
        for (int dx = 0; dx < 3; dx++) {
            int gx = x + dx - 1;
            if ((unsigned)gx >= 256u) continue;
            acc += w[c*9 + dy*3 + dx] * ip[gy*256 + gx];
        }
    }
    out[((size_t)b*CoutTot + cOutOff + c)*HW + p] = acc;
}

// ---------------- 256-pt shared-memory FFT ----------------
__device__ void fft256(float* sr, float* si, int tid, float dir)
{
    __syncthreads();
    for (int k = tid; k < 256; k += 128) {
        int r = __brev((unsigned)k) >> 24;
        if (r > k) {
            float a = sr[k]; sr[k] = sr[r]; sr[r] = a;
            a = si[k]; si[k] = si[r]; si[r] = a;
        }
    }
    __syncthreads();
    for (int len = 2; len <= 256; len <<= 1) {
        int half = len >> 1;
        int g = tid / half, pidx = tid - g*half;
        int i0 = g*len + pidx, i1 = i0 + half;
        float ang = dir * 6.283185307179586f * (float)pidx / (float)len;
        float wi, wr;
        sincosf(ang, &wi, &wr);
        float ar = sr[i1], ai = si[i1];
        float tr = wr*ar - wi*ai, ti = wr*ai + wi*ar;
        float br = sr[i0], bi = si[i0];
        sr[i0] = br + tr; si[i0] = bi + ti;
        sr[i1] = br - tr; si[i1] = bi - ti;
        __syncthreads();
    }
}

__global__ void fft_row_fwd(const float* __restrict__ x, float* __restrict__ fq)
{
    __shared__ float sr[256], si[256];
    int row = blockIdx.x;               // b*64*256 + c*256 + h
    int b = row >> 14, c = (row >> 8) & 63, h = row & 255;
    const float* xp = x + (size_t)row*256;
    for (int w = threadIdx.x; w < 256; w += 128) { sr[w] = xp[w]; si[w] = 0.f; }
    fft256(sr, si, threadIdx.x, -1.f);
    float* fr = fq + ((size_t)(b*128 + c)*HH + h)*W129;
    float* fi = fq + ((size_t)(b*128 + 64 + c)*HH + h)*W129;
    for (int w = threadIdx.x; w < 129; w += 128) { fr[w] = sr[w]; fi[w] = si[w]; }
}

__global__ void fft_col(float* fq, float dir, float scale)
{
    __shared__ float sr[256], si[256];
    int id = blockIdx.x;                // b*64*129 + c*129 + w
    int b = id / (64*129);
    int r = id - b*(64*129);
    int c = r / 129, w = r - c*129;
    float* fr = fq + ((size_t)(b*128 + c)*HH)*W129 + w;
    float* fi = fq + ((size_t)(b*128 + 64 + c)*HH)*W129 + w;
    for (int h = threadIdx.x; h < 256; h += 128) {
        sr[h] = fr[(size_t)h*W129];
        si[h] = fi[(size_t)h*W129];
    }
    fft256(sr, si, threadIdx.x, dir);
    for (int h = threadIdx.x; h < 256; h += 128) {
        fr[(size_t)h*W129] = sr[h]*scale;
        fi[(size_t)h*W129] = si[h]*scale;
    }
}

__global__ void ifft_row_real(const float* __restrict__ fq, float* __restrict__ out)
{
    __shared__ float sr[256], si[256];
    int row = blockIdx.x;
    int b = row >> 14, c = (row >> 8) & 63, h = row & 255;
    const float* fr = fq + ((size_t)(b*128 + c)*HH + h)*W129;
    const float* fi = fq + ((size_t)(b*128 + 64 + c)*HH + h)*W129;
    for (int k = threadIdx.x; k < 129; k += 128) { sr[k] = fr[k]; si[k] = fi[k]; }
    __syncthreads();
    for (int k = 129 + threadIdx.x; k < 256; k += 128) {
        sr[k] =  sr[256 - k];
        si[k] = -si[256 - k];
    }
    fft256(sr, si, threadIdx.x, +1.f);
    float* op = out + (size_t)row*256;
    const float s = 1.f/256.f;
    for (int w = threadIdx.x; w < 256; w += 128) op[w] = sr[w]*s;
}

// ---------------- attention small kernels ----------------
__global__ void zero_small_kernel()
{
    int t = blockIdx.x*256 + threadIdx.x;
    if (t < 512)  g_sumsq[t] = 0.f;
    if (t < 2048) g_gram[t]  = 0.f;
}

__global__ void sumsq_kernel(const float* __restrict__ q, const float* __restrict__ k)
{
    int ch = blockIdx.x;                // 0..511
    const float* base;
    if (ch < 256) base = q + (size_t)ch*HW;
    else {
        int c2 = ch - 256, b = c2 >> 6, c = c2 & 63;
        base = k + ((size_t)b*128 + c)*HW;
    }
    int start = blockIdx.y*8192;
    float s = 0.f;
    for (int n = start + threadIdx.x; n < start + 8192; n += 256) {
        float v = base[n];
        s += v*v;
    }
#pragma unroll
    for (int off = 16; off > 0; off >>= 1) s += __shfl_down_sync(0xffffffffu, s, off);
    __shared__ float ws[8];
    if ((threadIdx.x & 31) == 0) ws[threadIdx.x >> 5] = s;
    __syncthreads();
    if (threadIdx.x == 0) {
        float t = 0.f;
#pragma unroll
        for (int i = 0; i < 8; i++) t += ws[i];
        atomicAdd(&g_sumsq[ch], t);
    }
}

__global__ void gram_kernel(const float* __restrict__ q, const float* __restrict__ k)
{
    int bh = blockIdx.x;                // b*8 + head
    int b = bh >> 3, head = bh & 7;
    const float* qb = q + ((size_t)b*64  + head*8)*HW;
    const float* kb = k + ((size_t)b*128 + head*8)*HW;
    float acc[64];
#pragma unroll
    for (int t = 0; t < 64; t++) acc[t] = 0.f;
    int start = blockIdx.y*4096;
    for (int n = start + threadIdx.x; n < start + 4096; n += 256) {
        float qv[8], kv[8];
#pragma unroll
        for (int i = 0; i < 8; i++) { qv[i] = qb[(size_t)i*HW + n]; kv[i] = kb[(size_t)i*HW + n]; }
#pragma unroll
        for (int i = 0; i < 8; i++)
#pragma unroll
            for (int j = 0; j < 8; j++)
                acc[i*8+j] += qv[i]*kv[j];
    }
#pragma unroll
    for (int t = 0; t < 64; t++) {
        float v = acc[t];
#pragma unroll
        for (int off = 16; off > 0; off >>= 1) v += __shfl_down_sync(0xffffffffu, v, off);
        if ((threadIdx.x & 31) == 0) atomicAdd(&g_gram[bh*64 + t], v);
    }
}

// softmax + fold proj:  M[b] = P @ blockdiag(A[b])
__global__ void softmaxM_kernel(const float* __restrict__ temp, const float* __restrict__ proj)
{
    __shared__ float A[512];
    __shared__ float dq[64], dk[64];
    int b = blockIdx.x;
    int tid = threadIdx.x;
    if (tid < 64)              dq[tid]      = fmaxf(sqrtf(g_sumsq[b*64 + tid]), 1e-12f);
    else if (tid < 128)        dk[tid - 64] = fmaxf(sqrtf(g_sumsq[256 + b*64 + tid - 64]), 1e-12f);
    __syncthreads();
    for (int t = tid; t < 512; t += 256) {
        int head = t >> 6, i = (t >> 3) & 7, j = t & 7;
        A[t] = g_gram[b*512 + t] / (dq[head*8 + i]*dk[head*8 + j]) * temp[head];
    }
    __syncthreads();
    if (tid < 64) {
        float m = -1e30f;
#pragma unroll
        for (int j = 0; j < 8; j++) m = fmaxf(m, A[tid*8 + j]);
        float s = 0.f;
        float e[8];
#pragma unroll
        for (int j = 0; j < 8; j++) { e[j] = expf(A[tid*8 + j] - m); s += e[j]; }
        float inv = 1.f/s;
#pragma unroll
        for (int j = 0; j < 8; j++) A[tid*8 + j] = e[j]*inv;
    }
    __syncthreads();
    for (int idx = tid; idx < 4096; idx += 256) {
        int co = idx >> 6, cv = idx & 63;
        int hv = cv >> 3, jv = cv & 7;
        float s = 0.f;
#pragma unroll
        for (int i = 0; i < 8; i++)
            s += proj[co*64 + hv*8 + i] * A[hv*64 + i*8 + jv];
        g_M[b*4096 + idx] = s;
    }
}

// ---------------- final gate ----------------
__global__ void final_kernel(const float* __restrict__ fre, const float* __restrict__ spa,
                             const float* __restrict__ g, float* __restrict__ out)
{
    size_t i = (size_t)blockIdx.x*256 + threadIdx.x;
    int b = (int)(i >> 22);
    int c = (int)(i >> 16) & 63;
    int p = (int)i & 65535;
    float fa = g[((size_t)b*128 + c)*HW + p];
    float sa = g[((size_t)b*128 + 64 + c)*HW + p];
    float v = fre[i]*fa + sa*spa[i];
    if (isnan(v) || isinf(v)) v = 1e-5f;
    out[i] = v;
}

// ---------------- host orchestration ----------------
static void run_attention(const float* x, const float* y, float* out_xres,
                          const float* qw, const float* qdw,
                          const float* kvw, const float* kvdw,
                          const float* temp, const float* projw,
                          float* qbuf, float* tA, float* tB, float* M)
{
    // q path: 1x1 then dw3x3
    conv1x1_kernel<<<dim3(2048,2,BB),256>>>(x, tB, qw, nullptr, nullptr,
                                            64,64,0, 64,64,0, HW, 0, 0);
    dw3x3_kernel<<<dim3(256,64,BB),256>>>(tB, qbuf, qdw, nullptr, 64,0, 64,0);
    // kv path
    conv1x1_kernel<<<dim3(2048,4,BB),256>>>(y, tA, kvw, nullptr, nullptr,
                                            64,64,0, 128,128,0, HW, 0, 0);
    dw3x3_kernel<<<dim3(256,128,BB),256>>>(tA, tB, kvdw, nullptr, 128,0, 128,0);
    // reductions
    zero_small_kernel<<<8,256>>>();
    sumsq_kernel<<<dim3(512,8),256>>>(qbuf, tB);
    gram_kernel<<<dim3(32,16),256>>>(qbuf, tB);
    softmaxM_kernel<<<BB,256>>>(temp, projw);
    // out = M[b] @ v + x   (v = tB channels 64..127), written in place over x
    conv1x1_kernel<<<dim3(2048,2,BB),256>>>(tB, out_xres, M, nullptr, x,
                                            64,128,64, 64,64,0, HW, 0, 1);
}

extern "C" void kernel_launch(void* const* d_in, const int* in_sizes, int n_in,
                              void* d_out, int out_size)
{
    const float* x0      = (const float*)d_in[0];
    const float* x1      = (const float*)d_in[1];
    const float* rl_w1   = (const float*)d_in[2];
    const float* rl_b1   = (const float*)d_in[3];
    const float* rl_w2   = (const float*)d_in[4];
    const float* rl_b2   = (const float*)d_in[5];
    const float* rg_w1   = (const float*)d_in[6];
    const float* rg_w2   = (const float*)d_in[7];
    const float* att_temp= (const float*)d_in[8];
    const float* att_kv_w  = (const float*)d_in[9];
    const float* att_kv_dw = (const float*)d_in[10];
    const float* att_q_w   = (const float*)d_in[11];
    const float* att_q_dw  = (const float*)d_in[12];
    const float* att_proj_w= (const float*)d_in[13];
    const float* f1_dw   = (const float*)d_in[14];
    const float* f1_dwb  = (const float*)d_in[15];
    const float* f1_pw   = (const float*)d_in[16];
    const float* f1_pwb  = (const float*)d_in[17];
    const float* f2_dw   = (const float*)d_in[18];
    const float* f2_dwb  = (const float*)d_in[19];
    const float* f2_pw   = (const float*)d_in[20];
    const float* f2_pwb  = (const float*)d_in[21];
    float* out = (float*)d_out;

    float *fre, *spa, *qb, *tA, *tB, *fqA, *fqB, *M;
    cudaGetSymbolAddress((void**)&fre, g_fre);
    cudaGetSymbolAddress((void**)&spa, g_spa);
    cudaGetSymbolAddress((void**)&qb,  g_q);
    cudaGetSymbolAddress((void**)&tA,  g_tmpA);
    cudaGetSymbolAddress((void**)&tB,  g_tmpB);
    cudaGetSymbolAddress((void**)&fqA, g_fqA);
    cudaGetSymbolAddress((void**)&fqB, g_fqB);
    cudaGetSymbolAddress((void**)&M,   g_M);

    // ---- ResBlock_L: fre = relu(conv2(relu(conv1(x0)))) + x0 ----
    conv3x3_kernel<<<dim3(16,16,16),256>>>(x0, tA, rl_w1, rl_b1, nullptr, 1);
    conv3x3_kernel<<<dim3(16,16,16),256>>>(tA, fre, rl_w2, rl_b2, x0, 1);

    // ---- ResBlock_G: spa = irfft2(W2 @ relu(W1 @ rfft2(x1))) ----
    fft_row_fwd<<<65536,128>>>(x1, fqA);
    fft_col<<<33024,128>>>(fqA, -1.f, 1.f);
    conv1x1_kernel<<<dim3((PF+31)/32,4,BB),256>>>(fqA, fqB, rg_w1, nullptr, nullptr,
                                                  128,128,0, 128,128,0, PF, 1, 0);
    conv1x1_kernel<<<dim3((PF+31)/32,4,BB),256>>>(fqB, fqA, rg_w2, nullptr, nullptr,
                                                  128,128,0, 128,128,0, PF, 0, 0);
    fft_col<<<33024,128>>>(fqA, +1.f, 1.f/256.f);
    ifft_row_real<<<65536,128>>>(fqA, spa);

    // ---- attention (shared weights), fre then spa, each with residual ----
    run_attention(fre, spa, fre, att_q_w, att_q_dw, att_kv_w, att_kv_dw,
                  att_temp, att_proj_w, qb, tA, tB, M);
    run_attention(spa, fre, spa, att_q_w, att_q_dw, att_kv_w, att_kv_dw,
                  att_temp, att_proj_w, qb, tA, tB, M);

    // ---- fuse ----
    dw3x3_kernel<<<dim3(256,64,BB),256>>>(fre, tA, f1_dw,        f1_dwb,    64,0, 128,0);
    dw3x3_kernel<<<dim3(256,64,BB),256>>>(spa, tA, f1_dw + 64*9, f1_dwb+64, 64,0, 128,64);
    conv1x1_kernel<<<dim3(2048,2,BB),256>>>(tA, qb, f1_pw, f1_pwb, nullptr,
                                            128,128,0, 64,64,0, HW, 0, 0);
    dw3x3_kernel<<<dim3(256,64,BB),256>>>(qb, tB, f2_dw, f2_dwb, 64,0, 64,0);
    conv1x1_kernel<<<dim3(2048,4,BB),256>>>(tB, tA, f2_pw, f2_pwb, nullptr,
                                            64,64,0, 128,128,0, HW, 2, 0);
    final_kernel<<<NF/256,256>>>(fre, spa, tA, out);
}

// round 5
// speedup vs baseline: 1.2631x; 1.2631x over previous
#include <cuda_runtime.h>
#include <math.h>

#define BB 4
#define CC 64
#define HH 256
#define WWD 256
#define HW 65536
#define NF (BB*CC*HW)       /* 16777216 */
#define W129 129
#define PF (HH*W129)        /* 33024 */

// ---------------- scratch ----------------
__device__ __align__(16) float g_fre[NF];
__device__ __align__(16) float g_spa[NF];
__device__ __align__(16) float g_q[NF];
__device__ __align__(16) float g_tmpA[2*NF];
__device__ __align__(16) float g_tmpB[2*NF];
__device__ __align__(16) float g_fqA[(size_t)BB*2*CC*PF];
__device__ __align__(16) float g_fqB[(size_t)BB*2*CC*PF];
__device__ float g_sumsq[2*BB*CC];   // 512: [0..255]=q, [256..511]=k
__device__ float g_gram[BB*8*64];    // 2048
__device__ __align__(16) float g_M[BB*CC*CC];      // 16384

// ---------------- full 3x3 conv (C=64 fixed), 32x32 px tile, 16 outs, 2x2 px/thread --------
__global__ void __launch_bounds__(256, 2)
conv3x3_kernel(const float* __restrict__ in, float* __restrict__ out,
               const float* __restrict__ W, const float* __restrict__ bias,
               const float* __restrict__ residual, int relu)
{
    __shared__ float sIn[34*35];
    __shared__ float sW[16*9];
    int b  = blockIdx.z >> 2;
    int og = (blockIdx.z & 3) * 16;
    int ty0 = blockIdx.y * 32, tx0 = blockIdx.x * 32;
    int tx = threadIdx.x & 15, ty = threadIdx.x >> 4;
    int x0 = tx * 2, y0 = ty * 2;

    float acc[16][4];
#pragma unroll
    for (int o = 0; o < 16; o++)
#pragma unroll
        for (int p = 0; p < 4; p++) acc[o][p] = 0.f;

    for (int ci = 0; ci < 64; ci++) {
        const float* ip = in + ((size_t)(b*64 + ci)*256)*256;
        for (int idx = threadIdx.x; idx < 34*34; idx += 256) {
            int iy = idx / 34, ix = idx - iy*34;
            int gy = ty0 - 1 + iy, gx = tx0 - 1 + ix;
            float v = 0.f;
            if ((unsigned)gy < 256u && (unsigned)gx < 256u)
                v = ip[gy*256 + gx];
            sIn[iy*35 + ix] = v;
        }
        if (threadIdx.x < 144) {
            int o = threadIdx.x / 9, k = threadIdx.x - o*9;
            sW[threadIdx.x] = W[((size_t)(og + o)*64 + ci)*9 + k];
        }
        __syncthreads();

        float r[16];
#pragma unroll
        for (int dy = 0; dy < 4; dy++)
#pragma unroll
            for (int dx = 0; dx < 4; dx++)
                r[dy*4+dx] = sIn[(y0+dy)*35 + x0+dx];

#pragma unroll
        for (int o = 0; o < 16; o++) {
            const float* wp = &sW[o*9];
            float w0=wp[0],w1=wp[1],w2=wp[2],w3=wp[3],w4=wp[4],w5=wp[5],w6=wp[6],w7=wp[7],w8=wp[8];
            acc[o][0] += w0*r[0]+w1*r[1]+w2*r[2] + w3*r[4]+w4*r[5]+w5*r[6] + w6*r[8]+w7*r[9]+w8*r[10];
            acc[o][1] += w0*r[1]+w1*r[2]+w2*r[3] + w3*r[5]+w4*r[6]+w5*r[7] + w6*r[9]+w7*r[10]+w8*r[11];
            acc[o][2] += w0*r[4]+w1*r[5]+w2*r[6] + w3*r[8]+w4*r[9]+w5*r[10] + w6*r[12]+w7*r[13]+w8*r[14];
            acc[o][3] += w0*r[5]+w1*r[6]+w2*r[7] + w3*r[9]+w4*r[10]+w5*r[11] + w6*r[13]+w7*r[14]+w8*r[15];
        }
        __syncthreads();
    }

    int gy = ty0 + y0, gx = tx0 + x0;
#pragma unroll
    for (int o = 0; o < 16; o++) {
        int oc = og + o;
        float bs = bias[oc];
        float v0 = acc[o][0] + bs, v1 = acc[o][1] + bs, v2 = acc[o][2] + bs, v3 = acc[o][3] + bs;
        if (relu) { v0 = fmaxf(v0,0.f); v1 = fmaxf(v1,0.f); v2 = fmaxf(v2,0.f); v3 = fmaxf(v3,0.f); }
        size_t base = (size_t)(b*64 + oc)*256;
        size_t i0 = (base + gy)*256 + gx;
        size_t i1 = (base + gy + 1)*256 + gx;
        if (residual) {
            v0 += residual[i0]; v1 += residual[i0+1];
            v2 += residual[i1]; v3 += residual[i1+1];
        }
        out[i0] = v0; out[i0+1] = v1;
        out[i1] = v2; out[i1+1] = v3;
    }
}

// ---------------- 1x1 conv as register-tiled SGEMM ----------------
// tile: 128 px x 64 out per block, 256 threads, thread = 8 px x 4 out
// requires: P % 128 == 0, Cout % 64 == 0, Cin % 16 == 0 (holds for all uses)
__global__ void conv1x1_kernel(const float* __restrict__ in, float* __restrict__ out,
                               const float* __restrict__ W, const float* __restrict__ bias,
                               const float* __restrict__ residual,
                               int Cin, int CinTot, int cInOff,
                               int Cout, int CoutTot, int cOutOff,
                               int P, int act, int perBatchW)
{
    __shared__ float sA[16][65];     // [k][o]
    __shared__ float sB[16][128];    // [k][p]
    int b  = blockIdx.z;
    int og = blockIdx.y * 64;
    int p0 = blockIdx.x * 128;
    const float* Wb = W + (perBatchW ? (size_t)b*Cout*Cin : 0);
    int tid = threadIdx.x;
    int px0 = (tid & 15) * 8;
    int ox0 = (tid >> 4) * 4;
    int lo = tid >> 2, lk = (tid & 3) * 4;        // A load: 64 o x 16 k
    int lkB = tid >> 4, lp = (tid & 15) * 8;      // B load: 16 k x 128 p

    float acc[4][8];
#pragma unroll
    for (int j = 0; j < 4; j++)
#pragma unroll
        for (int i = 0; i < 8; i++) acc[j][i] = 0.f;

    for (int k0 = 0; k0 < Cin; k0 += 16) {
        float4 a4 = *(const float4*)&Wb[(size_t)(og + lo)*Cin + k0 + lk];
        sA[lk+0][lo] = a4.x; sA[lk+1][lo] = a4.y; sA[lk+2][lo] = a4.z; sA[lk+3][lo] = a4.w;
        const float* bp = &in[((size_t)b*CinTot + cInOff + k0 + lkB)*P + p0 + lp];
        float4 b0 = *(const float4*)(bp);
        float4 b1 = *(const float4*)(bp + 4);
        *(float4*)&sB[lkB][lp]     = b0;
        *(float4*)&sB[lkB][lp + 4] = b1;
        __syncthreads();
#pragma unroll
        for (int k = 0; k < 16; k++) {
            float4 v0 = *(const float4*)&sB[k][px0];
            float4 v1 = *(const float4*)&sB[k][px0 + 4];
            float a0 = sA[k][ox0], a1 = sA[k][ox0+1], a2 = sA[k][ox0+2], a3 = sA[k][ox0+3];
            acc[0][0]+=a0*v0.x; acc[0][1]+=a0*v0.y; acc[0][2]+=a0*v0.z; acc[0][3]+=a0*v0.w;
            acc[0][4]+=a0*v1.x; acc[0][5]+=a0*v1.y; acc[0][6]+=a0*v1.z; acc[0][7]+=a0*v1.w;
            acc[1][0]+=a1*v0.x; acc[1][1]+=a1*v0.y; acc[1][2]+=a1*v0.z; acc[1][3]+=a1*v0.w;
            acc[1][4]+=a1*v1.x; acc[1][5]+=a1*v1.y; acc[1][6]+=a1*v1.z; acc[1][7]+=a1*v1.w;
            acc[2][0]+=a2*v0.x; acc[2][1]+=a2*v0.y; acc[2][2]+=a2*v0.z; acc[2][3]+=a2*v0.w;
            acc[2][4]+=a2*v1.x; acc[2][5]+=a2*v1.y; acc[2][6]+=a2*v1.z; acc[2][7]+=a2*v1.w;
            acc[3][0]+=a3*v0.x; acc[3][1]+=a3*v0.y; acc[3][2]+=a3*v0.z; acc[3][3]+=a3*v0.w;
            acc[3][4]+=a3*v1.x; acc[3][5]+=a3*v1.y; acc[3][6]+=a3*v1.z; acc[3][7]+=a3*v1.w;
        }
        __syncthreads();
    }

#pragma unroll
    for (int j = 0; j < 4; j++) {
        int o = og + ox0 + j;
        float bs = bias ? bias[o] : 0.f;
        float v[8];
#pragma unroll
        for (int i = 0; i < 8; i++) {
            float t = acc[j][i] + bs;
            if (act == 1) t = fmaxf(t, 0.f);
            else if (act == 2) t = 1.f/(1.f + expf(-t));
            v[i] = t;
        }
        size_t oi = ((size_t)b*CoutTot + cOutOff + o)*P + p0 + px0;
        if (residual) {
            float4 r0 = *(const float4*)&residual[oi];
            float4 r1 = *(const float4*)&residual[oi + 4];
            v[0]+=r0.x; v[1]+=r0.y; v[2]+=r0.z; v[3]+=r0.w;
            v[4]+=r1.x; v[5]+=r1.y; v[6]+=r1.z; v[7]+=r1.w;
        }
        float4 s0 = make_float4(v[0], v[1], v[2], v[3]);
        float4 s1 = make_float4(v[4], v[5], v[6], v[7]);
        *(float4*)&out[oi]     = s0;
        *(float4*)&out[oi + 4] = s1;
    }
}

// ---------------- depthwise 3x3 (pad 1) on 256x256 ----------------
__global__ void dw3x3_kernel(const float* __restrict__ in, float* __restrict__ out,
                             const float* __restrict__ w, const float* __restrict__ bias,
                             int CinTot, int cInOff, int CoutTot, int cOutOff)
{
    int b = blockIdx.z, c = blockIdx.y;
    int p = blockIdx.x*256 + threadIdx.x;
    int y = p >> 8, x = p & 255;
    const float* ip = in + ((size_t)b*CinTot + cInOff + c)*HW;
    float acc = bias ? bias[c] : 0.f;
#pragma unroll
    for (int dy = 0; dy < 3; dy++) {
        int gy = y + dy - 1;
        if ((unsigned)gy >= 256u) continue;
#pragma unroll
        for (int dx = 0; dx < 3; dx++) {
            int gx = x + dx - 1;
            if ((unsigned)gx >= 256u) continue;
            acc += w[c*9 + dy*3 + dx] * ip[gy*256 + gx];
        }
    }
    out[((size_t)b*CoutTot + cOutOff + c)*HW + p] = acc;
}

// ---------------- 256-pt shared-memory FFT (128 threads, row kernels) ----------------
__device__ void fft256(float* sr, float* si, int tid, float dir)
{
    __syncthreads();
    for (int k = tid; k < 256; k += 128) {
        int r = __brev((unsigned)k) >> 24;
        if (r > k) {
            float a = sr[k]; sr[k] = sr[r]; sr[r] = a;
            a = si[k]; si[k] = si[r]; si[r] = a;
        }
    }
    __syncthreads();
    int s = 0;
    for (int len = 2; len <= 256; len <<= 1, s++) {
        int half = 1 << s;
        int pidx = tid & (half - 1);
        int i0 = ((tid >> s) << (s + 1)) + pidx;
        int i1 = i0 + half;
        float theta = dir * 6.2831853071795864f / (float)len;
        float wi, wr;
        __sincosf(theta * (float)pidx, &wi, &wr);
        float ar = sr[i1], ai = si[i1];
        float tr = wr*ar - wi*ai, ti = wr*ai + wi*ar;
        float br = sr[i0], bi = si[i0];
        sr[i0] = br + tr; si[i0] = bi + ti;
        sr[i1] = br - tr; si[i1] = bi - ti;
        __syncthreads();
    }
}

__global__ void fft_row_fwd(const float* __restrict__ x, float* __restrict__ fq)
{
    __shared__ float sr[256], si[256];
    int row = blockIdx.x;               // b*64*256 + c*256 + h
    int b = row >> 14, c = (row >> 8) & 63, h = row & 255;
    const float* xp = x + (size_t)row*256;
    for (int w = threadIdx.x; w < 256; w += 128) { sr[w] = xp[w]; si[w] = 0.f; }
    fft256(sr, si, threadIdx.x, -1.f);
    float* fr = fq + ((size_t)(b*128 + c)*HH + h)*W129;
    float* fi = fq + ((size_t)(b*128 + 64 + c)*HH + h)*W129;
    for (int w = threadIdx.x; w < 129; w += 128) { fr[w] = sr[w]; fi[w] = si[w]; }
}

// ---- tiled column FFT: 8 columns per block, 256 threads (32 threads/column) ----
__global__ void fft_col(float* fq, float dir, float scale)
{
    __shared__ float sr[8*263], si[8*263];
    int b = blockIdx.z, c = blockIdx.y;
    int w0 = blockIdx.x * 8;
    int nw = 129 - w0; if (nw > 8) nw = 8;
    float* fr = fq + ((size_t)(b*128 + c)*HH)*W129;
    float* fi = fq + ((size_t)(b*128 + 64 + c)*HH)*W129;

#pragma unroll
    for (int r = 0; r < 8; r++) {
        int l = threadIdx.x + 256*r;
        int h = l >> 3, w = l & 7;
        if (w < nw) {
            sr[w*263 + h] = fr[(size_t)h*W129 + w0 + w];
            si[w*263 + h] = fi[(size_t)h*W129 + w0 + w];
        }
    }
    __syncthreads();

    int col = threadIdx.x & 7;
    int j   = threadIdx.x >> 3;     // 0..31
    float* R = sr + col*263;
    float* I = si + col*263;

    for (int k = j; k < 256; k += 32) {
        int rv = __brev((unsigned)k) >> 24;
        if (rv > k) {
            float t = R[k]; R[k] = R[rv]; R[rv] = t;
            t = I[k]; I[k] = I[rv]; I[rv] = t;
        }
    }
    __syncthreads();

    int s = 0;
    for (int len = 2; len <= 256; len <<= 1, s++) {
        int half = 1 << s;
        float theta = dir * 6.2831853071795864f / (float)len;
#pragma unroll
        for (int m = j; m < 128; m += 32) {
            int pidx = m & (half - 1);
            int i0 = ((m >> s) << (s + 1)) + pidx;
            int i1 = i0 + half;
            float wi, wr;
            __sincosf(theta * (float)pidx, &wi, &wr);
            float ar = R[i1], ai = I[i1];
            float tr = wr*ar - wi*ai, ti = wr*ai + wi*ar;
            float br = R[i0], bi = I[i0];
            R[i0] = br + tr; I[i0] = bi + ti;
            R[i1] = br - tr; I[i1] = bi - ti;
        }
        __syncthreads();
    }

#pragma unroll
    for (int r = 0; r < 8; r++) {
        int l = threadIdx.x + 256*r;
        int h = l >> 3, w = l & 7;
        if (w < nw) {
            fr[(size_t)h*W129 + w0 + w] = sr[w*263 + h]*scale;
            fi[(size_t)h*W129 + w0 + w] = si[w*263 + h]*scale;
        }
    }
}

__global__ void ifft_row_real(const float* __restrict__ fq, float* __restrict__ out)
{
    __shared__ float sr[256], si[256];
    int row = blockIdx.x;
    int b = row >> 14, c = (row >> 8) & 63, h = row & 255;
    const float* fr = fq + ((size_t)(b*128 + c)*HH + h)*W129;
    const float* fi = fq + ((size_t)(b*128 + 64 + c)*HH + h)*W129;
    for (int k = threadIdx.x; k < 129; k += 128) { sr[k] = fr[k]; si[k] = fi[k]; }
    __syncthreads();
    for (int k = 129 + threadIdx.x; k < 256; k += 128) {
        sr[k] =  sr[256 - k];
        si[k] = -si[256 - k];
    }
    fft256(sr, si, threadIdx.x, +1.f);
    float* op = out + (size_t)row*256;
    const float s = 1.f/256.f;
    for (int w = threadIdx.x; w < 256; w += 128) op[w] = sr[w]*s;
}

// ---------------- attention small kernels ----------------
__global__ void zero_small_kernel()
{
    int t = blockIdx.x*256 + threadIdx.x;
    if (t < 512)  g_sumsq[t] = 0.f;
    if (t < 2048) g_gram[t]  = 0.f;
}

__global__ void sumsq_kernel(const float* __restrict__ q, const float* __restrict__ k)
{
    int ch = blockIdx.x;                // 0..511
    const float* base;
    if (ch < 256) base = q + (size_t)ch*HW;
    else {
        int c2 = ch - 256, b = c2 >> 6, c = c2 & 63;
        base = k + ((size_t)b*128 + c)*HW;
    }
    int start = blockIdx.y*8192;
    float s = 0.f;
    for (int n = start + threadIdx.x; n < start + 8192; n += 256) {
        float v = base[n];
        s += v*v;
    }
#pragma unroll
    for (int off = 16; off > 0; off >>= 1) s += __shfl_down_sync(0xffffffffu, s, off);
    __shared__ float ws[8];
    if ((threadIdx.x & 31) == 0) ws[threadIdx.x >> 5] = s;
    __syncthreads();
    if (threadIdx.x == 0) {
        float t = 0.f;
#pragma unroll
        for (int i = 0; i < 8; i++) t += ws[i];
        atomicAdd(&g_sumsq[ch], t);
    }
}

__global__ void gram_kernel(const float* __restrict__ q, const float* __restrict__ k)
{
    int bh = blockIdx.x;                // b*8 + head
    int b = bh >> 3, head = bh & 7;
    const float* qb = q + ((size_t)b*64  + head*8)*HW;
    const float* kb = k + ((size_t)b*128 + head*8)*HW;
    float acc[64];
#pragma unroll
    for (int t = 0; t < 64; t++) acc[t] = 0.f;
    int start = blockIdx.y*4096;
    for (int n = start + threadIdx.x; n < start + 4096; n += 256) {
        float qv[8], kv[8];
#pragma unroll
        for (int i = 0; i < 8; i++) { qv[i] = qb[(size_t)i*HW + n]; kv[i] = kb[(size_t)i*HW + n]; }
#pragma unroll
        for (int i = 0; i < 8; i++)
#pragma unroll
            for (int j = 0; j < 8; j++)
                acc[i*8+j] += qv[i]*kv[j];
    }
#pragma unroll
    for (int t = 0; t < 64; t++) {
        float v = acc[t];
#pragma unroll
        for (int off = 16; off > 0; off >>= 1) v += __shfl_down_sync(0xffffffffu, v, off);
        if ((threadIdx.x & 31) == 0) atomicAdd(&g_gram[bh*64 + t], v);
    }
}

// softmax + fold proj:  M[b] = P @ blockdiag(A[b])
__global__ void softmaxM_kernel(const float* __restrict__ temp, const float* __restrict__ proj)
{
    __shared__ float A[512];
    __shared__ float dq[64], dk[64];
    int b = blockIdx.x;
    int tid = threadIdx.x;
    if (tid < 64)              dq[tid]      = fmaxf(sqrtf(g_sumsq[b*64 + tid]), 1e-12f);
    else if (tid < 128)        dk[tid - 64] = fmaxf(sqrtf(g_sumsq[256 + b*64 + tid - 64]), 1e-12f);
    __syncthreads();
    for (int t = tid; t < 512; t += 256) {
        int head = t >> 6, i = (t >> 3) & 7, j = t & 7;
        A[t] = g_gram[b*512 + t] / (dq[head*8 + i]*dk[head*8 + j]) * temp[head];
    }
    __syncthreads();
    if (tid < 64) {
        float m = -1e30f;
#pragma unroll
        for (int j = 0; j < 8; j++) m = fmaxf(m, A[tid*8 + j]);
        float s = 0.f;
        float e[8];
#pragma unroll
        for (int j = 0; j < 8; j++) { e[j] = expf(A[tid*8 + j] - m); s += e[j]; }
        float inv = 1.f/s;
#pragma unroll
        for (int j = 0; j < 8; j++) A[tid*8 + j] = e[j]*inv;
    }
    __syncthreads();
    for (int idx = tid; idx < 4096; idx += 256) {
        int co = idx >> 6, cv = idx & 63;
        int hv = cv >> 3, jv = cv & 7;
        float s = 0.f;
#pragma unroll
        for (int i = 0; i < 8; i++)
            s += proj[co*64 + hv*8 + i] * A[hv*64 + i*8 + jv];
        g_M[b*4096 + idx] = s;
    }
}

// ---------------- final gate ----------------
__global__ void final_kernel(const float* __restrict__ fre, const float* __restrict__ spa,
                             const float* __restrict__ g, float* __restrict__ out)
{
    size_t i = (size_t)blockIdx.x*256 + threadIdx.x;
    int b = (int)(i >> 22);
    int c = (int)(i >> 16) & 63;
    int p = (int)i & 65535;
    float fa = g[((size_t)b*128 + c)*HW + p];
    float sa = g[((size_t)b*128 + 64 + c)*HW + p];
    float v = fre[i]*fa + sa*spa[i];
    if (isnan(v) || isinf(v)) v = 1e-5f;
    out[i] = v;
}

// ---------------- host orchestration ----------------
static void run_attention(const float* x, const float* y, float* out_xres,
                          const float* qw, const float* qdw,
                          const float* kvw, const float* kvdw,
                          const float* temp, const float* projw,
                          float* qbuf, float* tA, float* tB, float* M)
{
    // q path: 1x1 then dw3x3
    conv1x1_kernel<<<dim3(HW/128,1,BB),256>>>(x, tB, qw, nullptr, nullptr,
                                              64,64,0, 64,64,0, HW, 0, 0);
    dw3x3_kernel<<<dim3(256,64,BB),256>>>(tB, qbuf, qdw, nullptr, 64,0, 64,0);
    // kv path
    conv1x1_kernel<<<dim3(HW/128,2,BB),256>>>(y, tA, kvw, nullptr, nullptr,
                                              64,64,0, 128,128,0, HW, 0, 0);
    dw3x3_kernel<<<dim3(256,128,BB),256>>>(tA, tB, kvdw, nullptr, 128,0, 128,0);
    // reductions
    zero_small_kernel<<<8,256>>>();
    sumsq_kernel<<<dim3(512,8),256>>>(qbuf, tB);
    gram_kernel<<<dim3(32,16),256>>>(qbuf, tB);
    softmaxM_kernel<<<BB,256>>>(temp, projw);
    // out = M[b] @ v + x   (v = tB channels 64..127), written in place over x
    conv1x1_kernel<<<dim3(HW/128,1,BB),256>>>(tB, out_xres, M, nullptr, x,
                                              64,128,64, 64,64,0, HW, 0, 1);
}

extern "C" void kernel_launch(void* const* d_in, const int* in_sizes, int n_in,
                              void* d_out, int out_size)
{
    const float* x0      = (const float*)d_in[0];
    const float* x1      = (const float*)d_in[1];
    const float* rl_w1   = (const float*)d_in[2];
    const float* rl_b1   = (const float*)d_in[3];
    const float* rl_w2   = (const float*)d_in[4];
    const float* rl_b2   = (const float*)d_in[5];
    const float* rg_w1   = (const float*)d_in[6];
    const float* rg_w2   = (const float*)d_in[7];
    const float* att_temp= (const float*)d_in[8];
    const float* att_kv_w  = (const float*)d_in[9];
    const float* att_kv_dw = (const float*)d_in[10];
    const float* att_q_w   = (const float*)d_in[11];
    const float* att_q_dw  = (const float*)d_in[12];
    const float* att_proj_w= (const float*)d_in[13];
    const float* f1_dw   = (const float*)d_in[14];
    const float* f1_dwb  = (const float*)d_in[15];
    const float* f1_pw   = (const float*)d_in[16];
    const float* f1_pwb  = (const float*)d_in[17];
    const float* f2_dw   = (const float*)d_in[18];
    const float* f2_dwb  = (const float*)d_in[19];
    const float* f2_pw   = (const float*)d_in[20];
    const float* f2_pwb  = (const float*)d_in[21];
    float* out = (float*)d_out;

    float *fre, *spa, *qb, *tA, *tB, *fqA, *fqB, *M;
    cudaGetSymbolAddress((void**)&fre, g_fre);
    cudaGetSymbolAddress((void**)&spa, g_spa);
    cudaGetSymbolAddress((void**)&qb,  g_q);
    cudaGetSymbolAddress((void**)&tA,  g_tmpA);
    cudaGetSymbolAddress((void**)&tB,  g_tmpB);
    cudaGetSymbolAddress((void**)&fqA, g_fqA);
    cudaGetSymbolAddress((void**)&fqB, g_fqB);
    cudaGetSymbolAddress((void**)&M,   g_M);

    // ---- ResBlock_L: fre = relu(conv2(relu(conv1(x0)))) + x0 ----
    conv3x3_kernel<<<dim3(8,8,16),256>>>(x0, tA, rl_w1, rl_b1, nullptr, 1);
    conv3x3_kernel<<<dim3(8,8,16),256>>>(tA, fre, rl_w2, rl_b2, x0, 1);

    // ---- ResBlock_G: spa = irfft2(W2 @ relu(W1 @ rfft2(x1))) ----
    fft_row_fwd<<<65536,128>>>(x1, fqA);
    fft_col<<<dim3(17,64,BB),256>>>(fqA, -1.f, 1.f);
    conv1x1_kernel<<<dim3(PF/128,2,BB),256>>>(fqA, fqB, rg_w1, nullptr, nullptr,
                                              128,128,0, 128,128,0, PF, 1, 0);
    conv1x1_kernel<<<dim3(PF/128,2,BB),256>>>(fqB, fqA, rg_w2, nullptr, nullptr,
                                              128,128,0, 128,128,0, PF, 0, 0);
    fft_col<<<dim3(17,64,BB),256>>>(fqA, +1.f, 1.f/256.f);
    ifft_row_real<<<65536,128>>>(fqA, spa);

    // ---- attention (shared weights), fre then spa, each with residual ----
    run_attention(fre, spa, fre, att_q_w, att_q_dw, att_kv_w, att_kv_dw,
                  att_temp, att_proj_w, qb, tA, tB, M);
    run_attention(spa, fre, spa, att_q_w, att_q_dw, att_kv_w, att_kv_dw,
                  att_temp, att_proj_w, qb, tA, tB, M);

    // ---- fuse ----
    dw3x3_kernel<<<dim3(256,64,BB),256>>>(fre, tA, f1_dw,        f1_dwb,    64,0, 128,0);
    dw3x3_kernel<<<dim3(256,64,BB),256>>>(spa, tA, f1_dw + 64*9, f1_dwb+64, 64,0, 128,64);
    conv1x1_kernel<<<dim3(HW/128,1,BB),256>>>(tA, qb, f1_pw, f1_pwb, nullptr,
                                              128,128,0, 64,64,0, HW, 0, 0);
    dw3x3_kernel<<<dim3(256,64,BB),256>>>(qb, tB, f2_dw, f2_dwb, 64,0, 64,0);
    conv1x1_kernel<<<dim3(HW/128,2,BB),256>>>(tB, tA, f2_pw, f2_pwb, nullptr,
                                              64,64,0, 128,128,0, HW, 2, 0);
    final_kernel<<<NF/256,256>>>(fre, spa, tA, out);
}

// round 8
// speedup vs baseline: 1.4888x; 1.1787x over previous
#include <cuda_runtime.h>
#include <math.h>

#define BB 4
#define CC 64
#define HH 256
#define WWD 256
#define HW 65536
#define NF (BB*CC*HW)       /* 16777216 */
#define W129 129
#define PF (HH*W129)        /* 33024 */

// ---------------- scratch ----------------
__device__ __align__(16) float g_fre[NF];
__device__ __align__(16) float g_spa[NF];
__device__ __align__(16) float g_q[NF];
__device__ __align__(16) float g_tmpA[2*NF];
__device__ __align__(16) float g_tmpB[2*NF];
__device__ __align__(16) float g_fqA[(size_t)BB*2*CC*PF];
__device__ __align__(16) float g_fqB[(size_t)BB*2*CC*PF];
__device__ float g_sumsq[2*BB*CC];   // 512: [0..255]=q, [256..511]=k
__device__ float g_gram[BB*8*64];    // 2048
__device__ __align__(16) float g_M[BB*CC*CC];      // 16384

// ---------------- full 3x3 conv (C=64 fixed), 32x32 px tile, 16 outs, 2x2 px/thread --------
__global__ void __launch_bounds__(256, 2)
conv3x3_kernel(const float* __restrict__ in, float* __restrict__ out,
               const float* __restrict__ W, const float* __restrict__ bias,
               const float* __restrict__ residual, int relu)
{
    __shared__ float sIn[34*35];
    __shared__ float sW[16*9];
    int b  = blockIdx.z >> 2;
    int og = (blockIdx.z & 3) * 16;
    int ty0 = blockIdx.y * 32, tx0 = blockIdx.x * 32;
    int tx = threadIdx.x & 15, ty = threadIdx.x >> 4;
    int x0 = tx * 2, y0 = ty * 2;

    float acc[16][4];
#pragma unroll
    for (int o = 0; o < 16; o++)
#pragma unroll
        for (int p = 0; p < 4; p++) acc[o][p] = 0.f;

    for (int ci = 0; ci < 64; ci++) {
        const float* ip = in + ((size_t)(b*64 + ci)*256)*256;
        for (int idx = threadIdx.x; idx < 34*34; idx += 256) {
            int iy = idx / 34, ix = idx - iy*34;
            int gy = ty0 - 1 + iy, gx = tx0 - 1 + ix;
            float v = 0.f;
            if ((unsigned)gy < 256u && (unsigned)gx < 256u)
                v = ip[gy*256 + gx];
            sIn[iy*35 + ix] = v;
        }
        if (threadIdx.x < 144) {
            int o = threadIdx.x / 9, k = threadIdx.x - o*9;
            sW[threadIdx.x] = W[((size_t)(og + o)*64 + ci)*9 + k];
        }
        __syncthreads();

        float r[16];
#pragma unroll
        for (int dy = 0; dy < 4; dy++)
#pragma unroll
            for (int dx = 0; dx < 4; dx++)
                r[dy*4+dx] = sIn[(y0+dy)*35 + x0+dx];

#pragma unroll
        for (int o = 0; o < 16; o++) {
            const float* wp = &sW[o*9];
            float w0=wp[0],w1=wp[1],w2=wp[2],w3=wp[3],w4=wp[4],w5=wp[5],w6=wp[6],w7=wp[7],w8=wp[8];
            acc[o][0] += w0*r[0]+w1*r[1]+w2*r[2] + w3*r[4]+w4*r[5]+w5*r[6] + w6*r[8]+w7*r[9]+w8*r[10];
            acc[o][1] += w0*r[1]+w1*r[2]+w2*r[3] + w3*r[5]+w4*r[6]+w5*r[7] + w6*r[9]+w7*r[10]+w8*r[11];
            acc[o][2] += w0*r[4]+w1*r[5]+w2*r[6] + w3*r[8]+w4*r[9]+w5*r[10] + w6*r[12]+w7*r[13]+w8*r[14];
            acc[o][3] += w0*r[5]+w1*r[6]+w2*r[7] + w3*r[9]+w4*r[10]+w5*r[11] + w6*r[13]+w7*r[14]+w8*r[15];
        }
        __syncthreads();
    }

    int gy = ty0 + y0, gx = tx0 + x0;
#pragma unroll
    for (int o = 0; o < 16; o++) {
        int oc = og + o;
        float bs = bias[oc];
        float v0 = acc[o][0] + bs, v1 = acc[o][1] + bs, v2 = acc[o][2] + bs, v3 = acc[o][3] + bs;
        if (relu) { v0 = fmaxf(v0,0.f); v1 = fmaxf(v1,0.f); v2 = fmaxf(v2,0.f); v3 = fmaxf(v3,0.f); }
        size_t base = (size_t)(b*64 + oc)*256;
        size_t i0 = (base + gy)*256 + gx;
        size_t i1 = (base + gy + 1)*256 + gx;
        if (residual) {
            v0 += residual[i0]; v1 += residual[i0+1];
            v2 += residual[i1]; v3 += residual[i1+1];
        }
        out[i0] = v0; out[i0+1] = v1;
        out[i1] = v2; out[i1+1] = v3;
    }
}

// ---------------- 1x1 conv: 256 px x 64 out tile, thread = 16 px x 4 out ----------------
// requires: P % 256 == 0, Cout = 64*gridDim.y, Cin % 16 == 0
__global__ void __launch_bounds__(256, 2)
conv1x1_kernel(const float* __restrict__ in, float* __restrict__ out,
               const float* __restrict__ W, const float* __restrict__ bias,
               const float* __restrict__ residual,
               int Cin, int CinTot, int cInOff,
               int CoutTot, int cOutOff,
               int P, int act, int perBatchW)
{
    __shared__ float sA[16][68];
    __shared__ float sB[16][256];
    int b  = blockIdx.z;
    int og = blockIdx.y * 64;
    int pb = blockIdx.x * 256;
    const float* Wb = W + (perBatchW ? (size_t)b*64*gridDim.y*Cin : 0);
    int tid = threadIdx.x;
    int lo = tid & 63, lk4 = (tid >> 6) << 2;
    int rB = tid >> 4, fB = tid & 15;
    int p0 = (tid & 15) << 2;
    int ox0 = (tid >> 4) << 2;

    float acc[4][16];
#pragma unroll
    for (int j = 0; j < 4; j++)
#pragma unroll
        for (int i = 0; i < 16; i++) acc[j][i] = 0.f;

    for (int k0 = 0; k0 < Cin; k0 += 16) {
        float4 a4 = *(const float4*)&Wb[(size_t)(og + lo)*Cin + k0 + lk4];
        sA[lk4+0][lo] = a4.x; sA[lk4+1][lo] = a4.y;
        sA[lk4+2][lo] = a4.z; sA[lk4+3][lo] = a4.w;
        const float* bp = in + ((size_t)b*CinTot + cInOff + k0 + rB)*P + pb;
#pragma unroll
        for (int q = 0; q < 4; q++)
            *(float4*)&sB[rB][(fB + 16*q)*4] = *(const float4*)(bp + (fB + 16*q)*4);
        __syncthreads();
#pragma unroll
        for (int k = 0; k < 16; k++) {
            float vv[16];
            *(float4*)&vv[0]  = *(const float4*)&sB[k][p0];
            *(float4*)&vv[4]  = *(const float4*)&sB[k][p0+64];
            *(float4*)&vv[8]  = *(const float4*)&sB[k][p0+128];
            *(float4*)&vv[12] = *(const float4*)&sB[k][p0+192];
            float aa[4];
            *(float4*)&aa[0] = *(const float4*)&sA[k][ox0];
#pragma unroll
            for (int j = 0; j < 4; j++)
#pragma unroll
                for (int i = 0; i < 16; i++)
                    acc[j][i] += aa[j]*vv[i];
        }
        __syncthreads();
    }

#pragma unroll
    for (int j = 0; j < 4; j++) {
        int o = og + ox0 + j;
        float bs = bias ? bias[o] : 0.f;
        size_t obase = ((size_t)b*CoutTot + cOutOff + o)*P + pb + p0;
#pragma unroll
        for (int c = 0; c < 4; c++) {
            float v[4];
#pragma unroll
            for (int i = 0; i < 4; i++) {
                float t = acc[j][c*4+i] + bs;
                if (act == 1) t = fmaxf(t, 0.f);
                v[i] = t;
            }
            if (residual) {
                float4 r = *(const float4*)&residual[obase + 64*c];
                v[0]+=r.x; v[1]+=r.y; v[2]+=r.z; v[3]+=r.w;
            }
            *(float4*)&out[obase + 64*c] = make_float4(v[0],v[1],v[2],v[3]);
        }
    }
}

// ---------------- fused: f2_pw conv (64->128) + sigmoid + gate + nan_to_num ----------------
// tile: 128 px x 128 outs, thread = 8 px x (4 low + 4 high) outs
__global__ void __launch_bounds__(256, 2)
conv1x1_gate_kernel(const float* __restrict__ in, const float* __restrict__ W,
                    const float* __restrict__ bias,
                    const float* __restrict__ fre, const float* __restrict__ spa,
                    float* __restrict__ out)
{
    __shared__ float sA[16][132];
    __shared__ float sB[16][128];
    int b  = blockIdx.z;
    int pb = blockIdx.x * 128;
    int tid = threadIdx.x;
    int lo = tid & 127, lk8 = (tid >> 7) * 8;
    int rB = tid >> 4, fB = tid & 15;
    int p0 = (tid & 15) << 2;
    int ox0 = (tid >> 4) << 2;

    float acc[8][8];
#pragma unroll
    for (int j = 0; j < 8; j++)
#pragma unroll
        for (int i = 0; i < 8; i++) acc[j][i] = 0.f;

    for (int k0 = 0; k0 < 64; k0 += 16) {
        float4 w0 = *(const float4*)&W[(size_t)lo*64 + k0 + lk8];
        float4 w1 = *(const float4*)&W[(size_t)lo*64 + k0 + lk8 + 4];
        sA[lk8+0][lo]=w0.x; sA[lk8+1][lo]=w0.y; sA[lk8+2][lo]=w0.z; sA[lk8+3][lo]=w0.w;
        sA[lk8+4][lo]=w1.x; sA[lk8+5][lo]=w1.y; sA[lk8+6][lo]=w1.z; sA[lk8+7][lo]=w1.w;
        const float* bp = in + ((size_t)b*64 + k0 + rB)*HW + pb + fB*8;
        *(float4*)&sB[rB][fB*8]     = *(const float4*)bp;
        *(float4*)&sB[rB][fB*8 + 4] = *(const float4*)(bp + 4);
        __syncthreads();
#pragma unroll
        for (int k = 0; k < 16; k++) {
            float vv[8];
            *(float4*)&vv[0] = *(const float4*)&sB[k][p0];
            *(float4*)&vv[4] = *(const float4*)&sB[k][p0+64];
            float aL[4], aH[4];
            *(float4*)&aL[0] = *(const float4*)&sA[k][ox0];
            *(float4*)&aH[0] = *(const float4*)&sA[k][ox0+64];
#pragma unroll
            for (int j = 0; j < 4; j++)
#pragma unroll
                for (int i = 0; i < 8; i++) {
                    acc[j][i]   += aL[j]*vv[i];
                    acc[4+j][i] += aH[j]*vv[i];
                }
        }
        __syncthreads();
    }

#pragma unroll
    for (int j = 0; j < 4; j++) {
        int c = ox0 + j;
        float bL = bias[c], bH = bias[c + 64];
        size_t base = ((size_t)b*64 + c)*HW + pb + p0;
#pragma unroll
        for (int ch = 0; ch < 2; ch++) {
            float4 f4 = *(const float4*)&fre[base + 64*ch];
            float4 s4 = *(const float4*)&spa[base + 64*ch];
            float fv[4] = {f4.x, f4.y, f4.z, f4.w};
            float sv[4] = {s4.x, s4.y, s4.z, s4.w};
            float o4[4];
#pragma unroll
            for (int i = 0; i < 4; i++) {
                float gf = 1.f/(1.f + expf(-(acc[j][ch*4+i]   + bL)));
                float gs = 1.f/(1.f + expf(-(acc[4+j][ch*4+i] + bH)));
                float v = fv[i]*gf + sv[i]*gs;
                if (isnan(v) || isinf(v)) v = 1e-5f;
                o4[i] = v;
            }
            *(float4*)&out[base + 64*ch] = make_float4(o4[0],o4[1],o4[2],o4[3]);
        }
    }
}

// ---------------- depthwise 3x3 (pad 1) on 256x256 ----------------
__global__ void dw3x3_kernel(const float* __restrict__ in, float* __restrict__ out,
                             const float* __restrict__ w, const float* __restrict__ bias,
                             int CinTot, int cInOff, int CoutTot, int cOutOff)
{
    int b = blockIdx.z, c = blockIdx.y;
    int p = blockIdx.x*256 + threadIdx.x;
    int y = p >> 8, x = p & 255;
    const float* ip = in + ((size_t)b*CinTot + cInOff + c)*HW;
    float acc = bias ? bias[c] : 0.f;
#pragma unroll
    for (int dy = 0; dy < 3; dy++) {
        int gy = y + dy - 1;
        if ((unsigned)gy >= 256u) continue;
#pragma unroll
        for (int dx = 0; dx < 3; dx++) {
            int gx = x + dx - 1;
            if ((unsigned)gx >= 256u) continue;
            acc += w[c*9 + dy*3 + dx] * ip[gy*256 + gx];
        }
    }
    out[((size_t)b*CoutTot + cOutOff + c)*HW + p] = acc;
}

// ---------------- twiddle-table 256-pt FFT ----------------
__device__ __forceinline__ void make_twiddle(float* twr, float* twi, int tid, int nthr, float dir)
{
    for (int i = tid; i < 256; i += nthr) {
        float c = 1.f, s = 0.f;
        if (i > 0) {
            int half = 1 << (31 - __clz((unsigned)i));
            float theta = dir * 3.14159265358979323846f * (float)(i - half) / (float)half;
            __sincosf(theta, &s, &c);
        }
        twr[i] = c; twi[i] = s;
    }
}

// 128-thread version (1 butterfly per thread per stage)
__device__ __forceinline__ void fft256_tw(float* sr, float* si, int tid,
                                          const float* twr, const float* twi)
{
    __syncthreads();
    for (int k = tid; k < 256; k += 128) {
        int r = __brev((unsigned)k) >> 24;
        if (r > k) {
            float a = sr[k]; sr[k] = sr[r]; sr[r] = a;
            a = si[k]; si[k] = si[r]; si[r] = a;
        }
    }
    __syncthreads();
#pragma unroll
    for (int s = 0; s < 8; s++) {
        int half = 1 << s;
        int pidx = tid & (half - 1);
        int i0 = ((tid >> s) << (s + 1)) + pidx;
        int i1 = i0 + half;
        float wr = twr[half + pidx], wi = twi[half + pidx];
        float ar = sr[i1], ai = si[i1];
        float tr = wr*ar - wi*ai, ti = wr*ai + wi*ar;
        float br = sr[i0], bi = si[i0];
        sr[i0] = br + tr; si[i0] = bi + ti;
        sr[i1] = br - tr; si[i1] = bi - ti;
        __syncthreads();
    }
}

// forward row rFFT, two real rows (channel pair) packed as one complex FFT
__global__ void fft_row_fwd(const float* __restrict__ x, float* __restrict__ fq)
{
    __shared__ float sr[256], si[256], twr[256], twi[256];
    int blk = blockIdx.x;                // b*32*256 + c2*256 + h
    int b = blk >> 13, c2 = (blk >> 8) & 31, h = blk & 255;
    int tid = threadIdx.x;
    const float* xa = x + ((size_t)(b*64 + 2*c2)*256 + h)*256;
    const float* xb = xa + 65536;
    for (int w = tid; w < 256; w += 128) { sr[w] = xa[w]; si[w] = xb[w]; }
    make_twiddle(twr, twi, tid, 128, -1.f);
    fft256_tw(sr, si, tid, twr, twi);
    float* frA = fq + ((size_t)(b*128 + 2*c2)*HH + h)*W129;
    float* fiA = fq + ((size_t)(b*128 + 64 + 2*c2)*HH + h)*W129;
    float* frB = frA + (size_t)HH*W129;
    float* fiB = fiA + (size_t)HH*W129;
    for (int k = tid; k <= 128; k += 128) {
        int km = (256 - k) & 255;
        float xr = sr[k], xi = si[k], yr = sr[km], yi = si[km];
        frA[k] = 0.5f*(xr + yr);
        fiA[k] = 0.5f*(xi - yi);
        frB[k] = 0.5f*(xi + yi);
        fiB[k] = 0.5f*(yr - xr);
    }
}

// inverse row rFFT, two channels unpacked from one complex inverse FFT.
// NOTE: imaginary parts of DC (k=0) and Nyquist (k=128) bins are IGNORED,
// matching pocketfft/numpy irfft C2R semantics. Without this, the packed
// two-channel trick leaks Im(DC/Nyquist) of one channel into the other.
__global__ void ifft_row_real(const float* __restrict__ fq, float* __restrict__ out)
{
    __shared__ float sr[256], si[256], twr[256], twi[256];
    int blk = blockIdx.x;
    int b = blk >> 13, c2 = (blk >> 8) & 31, h = blk & 255;
    int tid = threadIdx.x;
    const float* frA = fq + ((size_t)(b*128 + 2*c2)*HH + h)*W129;
    const float* fiA = fq + ((size_t)(b*128 + 64 + 2*c2)*HH + h)*W129;
    const float* frB = frA + (size_t)HH*W129;
    const float* fiB = fiA + (size_t)HH*W129;
    make_twiddle(twr, twi, tid, 128, +1.f);
    for (int k = tid; k <= 128; k += 128) {
        float Ar = frA[k], Ai = fiA[k], Br = frB[k], Bi = fiB[k];
        if (k == 0 || k == 128) { Ai = 0.f; Bi = 0.f; }   // C2R: ignore imag of DC/Nyquist
        sr[k] = Ar - Bi;
        si[k] = Ai + Br;
        if (k > 0 && k < 128) {
            sr[256-k] = Ar + Bi;
            si[256-k] = Br - Ai;
        }
    }
    fft256_tw(sr, si, tid, twr, twi);
    float* oa = out + ((size_t)(b*64 + 2*c2)*256 + h)*256;
    float* ob = oa + 65536;
    const float s = 1.f/256.f;
    for (int w = tid; w < 256; w += 128) { oa[w] = sr[w]*s; ob[w] = si[w]*s; }
}

// ---- tiled column FFT: 8 columns per block, 256 threads (32 threads/column) ----
__global__ void fft_col(float* fq, float dir, float scale)
{
    __shared__ float sr[8*263], si[8*263];
    __shared__ float twr[256], twi[256];
    int b = blockIdx.z, c = blockIdx.y;
    int w0 = blockIdx.x * 8;
    int nw = 129 - w0; if (nw > 8) nw = 8;
    float* fr = fq + ((size_t)(b*128 + c)*HH)*W129;
    float* fi = fq + ((size_t)(b*128 + 64 + c)*HH)*W129;

    make_twiddle(twr, twi, threadIdx.x, 256, dir);
#pragma unroll
    for (int r = 0; r < 8; r++) {
        int l = threadIdx.x + 256*r;
        int h = l >> 3, w = l & 7;
        if (w < nw) {
            sr[w*263 + h] = fr[(size_t)h*W129 + w0 + w];
            si[w*263 + h] = fi[(size_t)h*W129 + w0 + w];
        }
    }
    __syncthreads();

    int col = threadIdx.x & 7;
    int j   = threadIdx.x >> 3;     // 0..31
    float* R = sr + col*263;
    float* I = si + col*263;

    for (int k = j; k < 256; k += 32) {
        int rv = __brev((unsigned)k) >> 24;
        if (rv > k) {
            float t = R[k]; R[k] = R[rv]; R[rv] = t;
            t = I[k]; I[k] = I[rv]; I[rv] = t;
        }
    }
    __syncthreads();

#pragma unroll
    for (int s = 0; s < 8; s++) {
        int half = 1 << s;
#pragma unroll
        for (int m = j; m < 128; m += 32) {
            int pidx = m & (half - 1);
            int i0 = ((m >> s) << (s + 1)) + pidx;
            int i1 = i0 + half;
            float wr = twr[half + pidx], wi = twi[half + pidx];
            float ar = R[i1], ai = I[i1];
            float tr = wr*ar - wi*ai, ti = wr*ai + wi*ar;
            float br = R[i0], bi = I[i0];
            R[i0] = br + tr; I[i0] = bi + ti;
            R[i1] = br - tr; I[i1] = bi - ti;
        }
        __syncthreads();
    }

#pragma unroll
    for (int r = 0; r < 8; r++) {
        int l = threadIdx.x + 256*r;
        int h = l >> 3, w = l & 7;
        if (w < nw) {
            fr[(size_t)h*W129 + w0 + w] = sr[w*263 + h]*scale;
            fi[(size_t)h*W129 + w0 + w] = si[w*263 + h]*scale;
        }
    }
}

// ---------------- attention small kernels ----------------
__global__ void zero_small_kernel()
{
    int t = blockIdx.x*256 + threadIdx.x;
    if (t < 512)  g_sumsq[t] = 0.f;
    if (t < 2048) g_gram[t]  = 0.f;
}

// fused gram + sumsq
__global__ void gram_kernel(const float* __restrict__ q, const float* __restrict__ k)
{
    int bh = blockIdx.x;                // b*8 + head
    int b = bh >> 3, head = bh & 7;
    const float* qb = q + ((size_t)b*64  + head*8)*HW;
    const float* kb = k + ((size_t)b*128 + head*8)*HW;
    float acc[64], qs[8], ks[8];
#pragma unroll
    for (int t = 0; t < 64; t++) acc[t] = 0.f;
#pragma unroll
    for (int t = 0; t < 8; t++) { qs[t] = 0.f; ks[t] = 0.f; }
    int start = blockIdx.y*4096;
    for (int n = start + threadIdx.x; n < start + 4096; n += 256) {
        float qv[8], kv[8];
#pragma unroll
        for (int i = 0; i < 8; i++) { qv[i] = qb[(size_t)i*HW + n]; kv[i] = kb[(size_t)i*HW + n]; }
#pragma unroll
        for (int i = 0; i < 8; i++) { qs[i] += qv[i]*qv[i]; ks[i] += kv[i]*kv[i]; }
#pragma unroll
        for (int i = 0; i < 8; i++)
#pragma unroll
            for (int j = 0; j < 8; j++)
                acc[i*8+j] += qv[i]*kv[j];
    }
#pragma unroll
    for (int t = 0; t < 64; t++) {
        float v = acc[t];
#pragma unroll
        for (int off = 16; off > 0; off >>= 1) v += __shfl_down_sync(0xffffffffu, v, off);
        if ((threadIdx.x & 31) == 0) atomicAdd(&g_gram[bh*64 + t], v);
    }
#pragma unroll
    for (int t = 0; t < 8; t++) {
        float v = qs[t];
#pragma unroll
        for (int off = 16; off > 0; off >>= 1) v += __shfl_down_sync(0xffffffffu, v, off);
        if ((threadIdx.x & 31) == 0) atomicAdd(&g_sumsq[b*64 + head*8 + t], v);
        v = ks[t];
#pragma unroll
        for (int off = 16; off > 0; off >>= 1) v += __shfl_down_sync(0xffffffffu, v, off);
        if ((threadIdx.x & 31) == 0) atomicAdd(&g_sumsq[256 + b*64 + head*8 + t], v);
    }
}

// softmax + fold proj:  M[b] = P @ blockdiag(A[b])
__global__ void softmaxM_kernel(const float* __restrict__ temp, const float* __restrict__ proj)
{
    __shared__ float A[512];
    __shared__ float dq[64], dk[64];
    int b = blockIdx.x;
    int tid = threadIdx.x;
    if (tid < 64)              dq[tid]      = fmaxf(sqrtf(g_sumsq[b*64 + tid]), 1e-12f);
    else if (tid < 128)        dk[tid - 64] = fmaxf(sqrtf(g_sumsq[256 + b*64 + tid - 64]), 1e-12f);
    __syncthreads();
    for (int t = tid; t < 512; t += 256) {
        int head = t >> 6, i = (t >> 3) & 7, j = t & 7;
        A[t] = g_gram[b*512 + t] / (dq[head*8 + i]*dk[head*8 + j]) * temp[head];
    }
    __syncthreads();
    if (tid < 64) {
        float m = -1e30f;
#pragma unroll
        for (int j = 0; j < 8; j++) m = fmaxf(m, A[tid*8 + j]);
        float s = 0.f;
        float e[8];
#pragma unroll
        for (int j = 0; j < 8; j++) { e[j] = expf(A[tid*8 + j] - m); s += e[j]; }
        float inv = 1.f/s;
#pragma unroll
        for (int j = 0; j < 8; j++) A[tid*8 + j] = e[j]*inv;
    }
    __syncthreads();
    for (int idx = tid; idx < 4096; idx += 256) {
        int co = idx >> 6, cv = idx & 63;
        int hv = cv >> 3, jv = cv & 7;
        float s = 0.f;
#pragma unroll
        for (int i = 0; i < 8; i++)
            s += proj[co*64 + hv*8 + i] * A[hv*64 + i*8 + jv];
        g_M[b*4096 + idx] = s;
    }
}

// ---------------- host orchestration ----------------
static void run_attention(const float* x, const float* y, float* out_xres,
                          const float* qw, const float* qdw,
                          const float* kvw, const float* kvdw,
                          const float* temp, const float* projw,
                          float* qbuf, float* tA, float* tB, float* M)
{
    // q path: 1x1 then dw3x3
    conv1x1_kernel<<<dim3(HW/256,1,BB),256>>>(x, tB, qw, nullptr, nullptr,
                                              64,64,0, 64,0, HW, 0, 0);
    dw3x3_kernel<<<dim3(256,64,BB),256>>>(tB, qbuf, qdw, nullptr, 64,0, 64,0);
    // kv path
    conv1x1_kernel<<<dim3(HW/256,2,BB),256>>>(y, tA, kvw, nullptr, nullptr,
                                              64,64,0, 128,0, HW, 0, 0);
    dw3x3_kernel<<<dim3(256,128,BB),256>>>(tA, tB, kvdw, nullptr, 128,0, 128,0);
    // reductions
    zero_small_kernel<<<8,256>>>();
    gram_kernel<<<dim3(32,16),256>>>(qbuf, tB);
    softmaxM_kernel<<<BB,256>>>(temp, projw);
    // out = M[b] @ v + x   (v = tB channels 64..127), written in place over x
    conv1x1_kernel<<<dim3(HW/256,1,BB),256>>>(tB, out_xres, M, nullptr, x,
                                              64,128,64, 64,0, HW, 0, 1);
}

extern "C" void kernel_launch(void* const* d_in, const int* in_sizes, int n_in,
                              void* d_out, int out_size)
{
    const float* x0      = (const float*)d_in[0];
    const float* x1      = (const float*)d_in[1];
    const float* rl_w1   = (const float*)d_in[2];
    const float* rl_b1   = (const float*)d_in[3];
    const float* rl_w2   = (const float*)d_in[4];
    const float* rl_b2   = (const float*)d_in[5];
    const float* rg_w1   = (const float*)d_in[6];
    const float* rg_w2   = (const float*)d_in[7];
    const float* att_temp= (const float*)d_in[8];
    const float* att_kv_w  = (const float*)d_in[9];
    const float* att_kv_dw = (const float*)d_in[10];
    const float* att_q_w   = (const float*)d_in[11];
    const float* att_q_dw  = (const float*)d_in[12];
    const float* att_proj_w= (const float*)d_in[13];
    const float* f1_dw   = (const float*)d_in[14];
    const float* f1_dwb  = (const float*)d_in[15];
    const float* f1_pw   = (const float*)d_in[16];
    const float* f1_pwb  = (const float*)d_in[17];
    const float* f2_dw   = (const float*)d_in[18];
    const float* f2_dwb  = (const float*)d_in[19];
    const float* f2_pw   = (const float*)d_in[20];
    const float* f2_pwb  = (const float*)d_in[21];
    float* out = (float*)d_out;

    float *fre, *spa, *qb, *tA, *tB, *fqA, *fqB, *M;
    cudaGetSymbolAddress((void**)&fre, g_fre);
    cudaGetSymbolAddress((void**)&spa, g_spa);
    cudaGetSymbolAddress((void**)&qb,  g_q);
    cudaGetSymbolAddress((void**)&tA,  g_tmpA);
    cudaGetSymbolAddress((void**)&tB,  g_tmpB);
    cudaGetSymbolAddress((void**)&fqA, g_fqA);
    cudaGetSymbolAddress((void**)&fqB, g_fqB);
    cudaGetSymbolAddress((void**)&M,   g_M);

    // ---- ResBlock_L: fre = relu(conv2(relu(conv1(x0)))) + x0 ----
    conv3x3_kernel<<<dim3(8,8,16),256>>>(x0, tA, rl_w1, rl_b1, nullptr, 1);
    conv3x3_kernel<<<dim3(8,8,16),256>>>(tA, fre, rl_w2, rl_b2, x0, 1);

    // ---- ResBlock_G: spa = irfft2(W2 @ relu(W1 @ rfft2(x1))) ----
    fft_row_fwd<<<32768,128>>>(x1, fqA);
    fft_col<<<dim3(17,64,BB),256>>>(fqA, -1.f, 1.f);
    conv1x1_kernel<<<dim3(PF/256,2,BB),256>>>(fqA, fqB, rg_w1, nullptr, nullptr,
                                              128,128,0, 128,0, PF, 1, 0);
    conv1x1_kernel<<<dim3(PF/256,2,BB),256>>>(fqB, fqA, rg_w2, nullptr, nullptr,
                                              128,128,0, 128,0, PF, 0, 0);
    fft_col<<<dim3(17,64,BB),256>>>(fqA, +1.f, 1.f/256.f);
    ifft_row_real<<<32768,128>>>(fqA, spa);

    // ---- attention (shared weights), fre then spa, each with residual ----
    run_attention(fre, spa, fre, att_q_w, att_q_dw, att_kv_w, att_kv_dw,
                  att_temp, att_proj_w, qb, tA, tB, M);
    run_attention(spa, fre, spa, att_q_w, att_q_dw, att_kv_w, att_kv_dw,
                  att_temp, att_proj_w, qb, tA, tB, M);

    // ---- fuse ----
    dw3x3_kernel<<<dim3(256,64,BB),256>>>(fre, tA, f1_dw,        f1_dwb,    64,0, 128,0);
    dw3x3_kernel<<<dim3(256,64,BB),256>>>(spa, tA, f1_dw + 64*9, f1_dwb+64, 64,0, 128,64);
    conv1x1_kernel<<<dim3(HW/256,1,BB),256>>>(tA, qb, f1_pw, f1_pwb, nullptr,
                                              128,128,0, 64,0, HW, 0, 0);
    dw3x3_kernel<<<dim3(256,64,BB),256>>>(qb, tB, f2_dw, f2_dwb, 64,0, 64,0);
    conv1x1_gate_kernel<<<dim3(HW/128,1,BB),256>>>(tB, f2_pw, f2_pwb, fre, spa, out);
}

// round 11
// speedup vs baseline: 1.5470x; 1.0391x over previous
#include <cuda_runtime.h>
#include <math.h>

#define BB 4
#define CC 64
#define HH 256
#define WWD 256
#define HW 65536
#define NF (BB*CC*HW)       /* 16777216 */
#define W129 129
#define PF (HH*W129)        /* 33024 */

// ---------------- scratch ----------------
__device__ __align__(16) float g_fre[NF];
__device__ __align__(16) float g_spa[NF];
__device__ __align__(16) float g_q[NF];
__device__ __align__(16) float g_tmpA[2*NF];
__device__ __align__(16) float g_tmpB[2*NF];
__device__ __align__(16) float g_fqA[(size_t)BB*2*CC*PF];
__device__ __align__(16) float g_fqB[(size_t)BB*2*CC*PF];
__device__ float g_sumsq[2*BB*CC];   // 512: [0..255]=q, [256..511]=k
__device__ float g_gram[BB*8*64];    // 2048
__device__ __align__(16) float g_M[BB*CC*CC];      // 16384

// ---------------- full 3x3 conv (C=64 fixed), 32x32 px tile, 16 outs, 2x2 px/thread --------
__global__ void __launch_bounds__(256, 2)
conv3x3_kernel(const float* __restrict__ in, float* __restrict__ out,
               const float* __restrict__ W, const float* __restrict__ bias,
               const float* __restrict__ residual, int relu)
{
    __shared__ float sIn[34*35];
    __shared__ float sW[16*9];
    int b  = blockIdx.z >> 2;
    int og = (blockIdx.z & 3) * 16;
    int ty0 = blockIdx.y * 32, tx0 = blockIdx.x * 32;
    int tx = threadIdx.x & 15, ty = threadIdx.x >> 4;
    int x0 = tx * 2, y0 = ty * 2;

    float acc[16][4];
#pragma unroll
    for (int o = 0; o < 16; o++)
#pragma unroll
        for (int p = 0; p < 4; p++) acc[o][p] = 0.f;

    for (int ci = 0; ci < 64; ci++) {
        const float* ip = in + ((size_t)(b*64 + ci)*256)*256;
        for (int idx = threadIdx.x; idx < 34*34; idx += 256) {
            int iy = idx / 34, ix = idx - iy*34;
            int gy = ty0 - 1 + iy, gx = tx0 - 1 + ix;
            float v = 0.f;
            if ((unsigned)gy < 256u && (unsigned)gx < 256u)
                v = ip[gy*256 + gx];
            sIn[iy*35 + ix] = v;
        }
        if (threadIdx.x < 144) {
            int o = threadIdx.x / 9, k = threadIdx.x - o*9;
            sW[threadIdx.x] = W[((size_t)(og + o)*64 + ci)*9 + k];
        }
        __syncthreads();

        float r[16];
#pragma unroll
        for (int dy = 0; dy < 4; dy++)
#pragma unroll
            for (int dx = 0; dx < 4; dx++)
                r[dy*4+dx] = sIn[(y0+dy)*35 + x0+dx];

#pragma unroll
        for (int o = 0; o < 16; o++) {
            const float* wp = &sW[o*9];
            float w0=wp[0],w1=wp[1],w2=wp[2],w3=wp[3],w4=wp[4],w5=wp[5],w6=wp[6],w7=wp[7],w8=wp[8];
            acc[o][0] += w0*r[0]+w1*r[1]+w2*r[2] + w3*r[4]+w4*r[5]+w5*r[6] + w6*r[8]+w7*r[9]+w8*r[10];
            acc[o][1] += w0*r[1]+w1*r[2]+w2*r[3] + w3*r[5]+w4*r[6]+w5*r[7] + w6*r[9]+w7*r[10]+w8*r[11];
            acc[o][2] += w0*r[4]+w1*r[5]+w2*r[6] + w3*r[8]+w4*r[9]+w5*r[10] + w6*r[12]+w7*r[13]+w8*r[14];
            acc[o][3] += w0*r[5]+w1*r[6]+w2*r[7] + w3*r[9]+w4*r[10]+w5*r[11] + w6*r[13]+w7*r[14]+w8*r[15];
        }
        __syncthreads();
    }

    int gy = ty0 + y0, gx = tx0 + x0;
#pragma unroll
    for (int o = 0; o < 16; o++) {
        int oc = og + o;
        float bs = bias[oc];
        float v0 = acc[o][0] + bs, v1 = acc[o][1] + bs, v2 = acc[o][2] + bs, v3 = acc[o][3] + bs;
        if (relu) { v0 = fmaxf(v0,0.f); v1 = fmaxf(v1,0.f); v2 = fmaxf(v2,0.f); v3 = fmaxf(v3,0.f); }
        size_t base = (size_t)(b*64 + oc)*256;
        size_t i0 = (base + gy)*256 + gx;
        size_t i1 = (base + gy + 1)*256 + gx;
        if (residual) {
            v0 += residual[i0]; v1 += residual[i0+1];
            v2 += residual[i1]; v3 += residual[i1+1];
        }
        out[i0] = v0; out[i0+1] = v1;
        out[i1] = v2; out[i1+1] = v3;
    }
}

// ---------------- TF32 tensor-core 1x1 conv ----------------
// C[64 x 128px] per block, 8 warps, warp = 16 out x 64 px via mma.m16n8k8 tf32.
// requires: P % 128 == 0, Cout = 64*gridDim.y, Cin % 32 == 0
__device__ __forceinline__ unsigned f2tf(float f)
{
    unsigned r; asm("cvt.rna.tf32.f32 %0, %1;" : "=r"(r) : "f"(f)); return r;
}

__global__ void __launch_bounds__(256, 2)
conv1x1_mma_kernel(const float* __restrict__ in, float* __restrict__ out,
                   const float* __restrict__ W, const float* __restrict__ bias,
                   const float* __restrict__ residual,
                   int Cin, int CinTot, int cInOff,
                   int CoutTot, int cOutOff,
                   int P, int act, int perBatchW)
{
    __shared__ unsigned sW[32][72];    // [k][o], stride%32==8 -> conflict-free frags
    __shared__ unsigned sX[32][136];   // [k][p]
    int b  = blockIdx.z;
    int og = blockIdx.y * 64;
    int pb = blockIdx.x * 128;
    const float* Wb = W + (perBatchW ? (size_t)b*64*gridDim.y*Cin : 0);
    int tid  = threadIdx.x;
    int warp = tid >> 5, lane = tid & 31;
    int gid = lane >> 2, tig = lane & 3;
    int ow = (warp & 3) * 16, pw = (warp >> 2) * 64;

    float c[8][4];
#pragma unroll
    for (int t = 0; t < 8; t++)
#pragma unroll
        for (int i = 0; i < 4; i++) c[t][i] = 0.f;

    int wo = tid >> 2, wk = (tid & 3) * 8;     // W loader: out row wo, k wk..wk+7
    int xk = tid >> 3, xp = (tid & 7) * 16;    // X loader: k row xk, px xp..xp+15

    for (int k0 = 0; k0 < Cin; k0 += 32) {
        const float* wp = &Wb[(size_t)(og + wo)*Cin + k0 + wk];
        float4 w0 = *(const float4*)wp;
        float4 w1 = *(const float4*)(wp + 4);
        sW[wk+0][wo] = f2tf(w0.x); sW[wk+1][wo] = f2tf(w0.y);
        sW[wk+2][wo] = f2tf(w0.z); sW[wk+3][wo] = f2tf(w0.w);
        sW[wk+4][wo] = f2tf(w1.x); sW[wk+5][wo] = f2tf(w1.y);
        sW[wk+6][wo] = f2tf(w1.z); sW[wk+7][wo] = f2tf(w1.w);

        const float* xpt = &in[((size_t)b*CinTot + cInOff + k0 + xk)*P + pb + xp];
#pragma unroll
        for (int q = 0; q < 4; q++) {
            float4 v = *(const float4*)(xpt + 4*q);
            uint4 u = make_uint4(f2tf(v.x), f2tf(v.y), f2tf(v.z), f2tf(v.w));
            *(uint4*)&sX[xk][xp + 4*q] = u;
        }
        __syncthreads();

#pragma unroll
        for (int ks = 0; ks < 4; ks++) {
            int kk = ks * 8;
            unsigned a0 = sW[kk + tig    ][ow + gid];
            unsigned a1 = sW[kk + tig    ][ow + gid + 8];
            unsigned a2 = sW[kk + tig + 4][ow + gid];
            unsigned a3 = sW[kk + tig + 4][ow + gid + 8];
#pragma unroll
            for (int t = 0; t < 8; t++) {
                unsigned b0 = sX[kk + tig    ][pw + t*8 + gid];
                unsigned b1 = sX[kk + tig + 4][pw + t*8 + gid];
                asm("mma.sync.aligned.m16n8k8.row.col.f32.tf32.tf32.f32 "
                    "{%0,%1,%2,%3}, {%4,%5,%6,%7}, {%8,%9}, {%0,%1,%2,%3};"
                    : "+f"(c[t][0]), "+f"(c[t][1]), "+f"(c[t][2]), "+f"(c[t][3])
                    : "r"(a0), "r"(a1), "r"(a2), "r"(a3), "r"(b0), "r"(b1));
            }
        }
        __syncthreads();
    }

    int o0 = og + ow + gid;
    int o1 = o0 + 8;
    float bs0 = bias ? bias[o0] : 0.f;
    float bs1 = bias ? bias[o1] : 0.f;
    size_t r0base = ((size_t)b*CoutTot + cOutOff + o0)*P + pb + pw;
    size_t r1base = ((size_t)b*CoutTot + cOutOff + o1)*P + pb + pw;
#pragma unroll
    for (int t = 0; t < 8; t++) {
        int p = t*8 + 2*tig;
        float v00 = c[t][0] + bs0, v01 = c[t][1] + bs0;
        float v10 = c[t][2] + bs1, v11 = c[t][3] + bs1;
        if (act == 1) {
            v00 = fmaxf(v00, 0.f); v01 = fmaxf(v01, 0.f);
            v10 = fmaxf(v10, 0.f); v11 = fmaxf(v11, 0.f);
        }
        if (residual) {
            float2 r0 = *(const float2*)&residual[r0base + p];
            float2 r1 = *(const float2*)&residual[r1base + p];
            v00 += r0.x; v01 += r0.y; v10 += r1.x; v11 += r1.y;
        }
        *(float2*)&out[r0base + p] = make_float2(v00, v01);
        *(float2*)&out[r1base + p] = make_float2(v10, v11);
    }
}

// ---------------- fused: f2_pw conv (64->128) + sigmoid + gate + nan_to_num ----------------
// tile: 128 px x 128 outs, thread = 8 px x (4 low + 4 high) outs
__global__ void __launch_bounds__(256, 2)
conv1x1_gate_kernel(const float* __restrict__ in, const float* __restrict__ W,
                    const float* __restrict__ bias,
                    const float* __restrict__ fre, const float* __restrict__ spa,
                    float* __restrict__ out)
{
    __shared__ float sA[16][132];
    __shared__ float sB[16][128];
    int b  = blockIdx.z;
    int pb = blockIdx.x * 128;
    int tid = threadIdx.x;
    int lo = tid & 127, lk8 = (tid >> 7) * 8;
    int rB = tid >> 4, fB = tid & 15;
    int p0 = (tid & 15) << 2;
    int ox0 = (tid >> 4) << 2;

    float acc[8][8];
#pragma unroll
    for (int j = 0; j < 8; j++)
#pragma unroll
        for (int i = 0; i < 8; i++) acc[j][i] = 0.f;

    for (int k0 = 0; k0 < 64; k0 += 16) {
        float4 w0 = *(const float4*)&W[(size_t)lo*64 + k0 + lk8];
        float4 w1 = *(const float4*)&W[(size_t)lo*64 + k0 + lk8 + 4];
        sA[lk8+0][lo]=w0.x; sA[lk8+1][lo]=w0.y; sA[lk8+2][lo]=w0.z; sA[lk8+3][lo]=w0.w;
        sA[lk8+4][lo]=w1.x; sA[lk8+5][lo]=w1.y; sA[lk8+6][lo]=w1.z; sA[lk8+7][lo]=w1.w;
        const float* bp = in + ((size_t)b*64 + k0 + rB)*HW + pb + fB*8;
        *(float4*)&sB[rB][fB*8]     = *(const float4*)bp;
        *(float4*)&sB[rB][fB*8 + 4] = *(const float4*)(bp + 4);
        __syncthreads();
#pragma unroll
        for (int k = 0; k < 16; k++) {
            float vv[8];
            *(float4*)&vv[0] = *(const float4*)&sB[k][p0];
            *(float4*)&vv[4] = *(const float4*)&sB[k][p0+64];
            float aL[4], aH[4];
            *(float4*)&aL[0] = *(const float4*)&sA[k][ox0];
            *(float4*)&aH[0] = *(const float4*)&sA[k][ox0+64];
#pragma unroll
            for (int j = 0; j < 4; j++)
#pragma unroll
                for (int i = 0; i < 8; i++) {
                    acc[j][i]   += aL[j]*vv[i];
                    acc[4+j][i] += aH[j]*vv[i];
                }
        }
        __syncthreads();
    }

#pragma unroll
    for (int j = 0; j < 4; j++) {
        int c = ox0 + j;
        float bL = bias[c], bH = bias[c + 64];
        size_t base = ((size_t)b*64 + c)*HW + pb + p0;
#pragma unroll
        for (int ch = 0; ch < 2; ch++) {
            float4 f4 = *(const float4*)&fre[base + 64*ch];
            float4 s4 = *(const float4*)&spa[base + 64*ch];
            float fv[4] = {f4.x, f4.y, f4.z, f4.w};
            float sv[4] = {s4.x, s4.y, s4.z, s4.w};
            float o4[4];
#pragma unroll
            for (int i = 0; i < 4; i++) {
                float gf = 1.f/(1.f + expf(-(acc[j][ch*4+i]   + bL)));
                float gs = 1.f/(1.f + expf(-(acc[4+j][ch*4+i] + bH)));
                float v = fv[i]*gf + sv[i]*gs;
                if (isnan(v) || isinf(v)) v = 1e-5f;
                o4[i] = v;
            }
            *(float4*)&out[base + 64*ch] = make_float4(o4[0],o4[1],o4[2],o4[3]);
        }
    }
}

// ---------------- depthwise 3x3 (pad 1) on 256x256 ----------------
__global__ void dw3x3_kernel(const float* __restrict__ in, float* __restrict__ out,
                             const float* __restrict__ w, const float* __restrict__ bias,
                             int CinTot, int cInOff, int CoutTot, int cOutOff)
{
    int b = blockIdx.z, c = blockIdx.y;
    int p = blockIdx.x*256 + threadIdx.x;
    int y = p >> 8, x = p & 255;
    const float* ip = in + ((size_t)b*CinTot + cInOff + c)*HW;
    float acc = bias ? bias[c] : 0.f;
#pragma unroll
    for (int dy = 0; dy < 3; dy++) {
        int gy = y + dy - 1;
        if ((unsigned)gy >= 256u) continue;
#pragma unroll
        for (int dx = 0; dx < 3; dx++) {
            int gx = x + dx - 1;
            if ((unsigned)gx >= 256u) continue;
            acc += w[c*9 + dy*3 + dx] * ip[gy*256 + gx];
        }
    }
    out[((size_t)b*CoutTot + cOutOff + c)*HW + p] = acc;
}

// ---------------- twiddle-table 256-pt FFT ----------------
__device__ __forceinline__ void make_twiddle(float* twr, float* twi, int tid, int nthr, float dir)
{
    for (int i = tid; i < 256; i += nthr) {
        float c = 1.f, s = 0.f;
        if (i > 0) {
            int half = 1 << (31 - __clz((unsigned)i));
            float theta = dir * 3.14159265358979323846f * (float)(i - half) / (float)half;
            __sincosf(theta, &s, &c);
        }
        twr[i] = c; twi[i] = s;
    }
}

// 128-thread version (1 butterfly per thread per stage)
__device__ __forceinline__ void fft256_tw(float* sr, float* si, int tid,
                                          const float* twr, const float* twi)
{
    __syncthreads();
    for (int k = tid; k < 256; k += 128) {
        int r = __brev((unsigned)k) >> 24;
        if (r > k) {
            float a = sr[k]; sr[k] = sr[r]; sr[r] = a;
            a = si[k]; si[k] = si[r]; si[r] = a;
        }
    }
    __syncthreads();
#pragma unroll
    for (int s = 0; s < 8; s++) {
        int half = 1 << s;
        int pidx = tid & (half - 1);
        int i0 = ((tid >> s) << (s + 1)) + pidx;
        int i1 = i0 + half;
        float wr = twr[half + pidx], wi = twi[half + pidx];
        float ar = sr[i1], ai = si[i1];
        float tr = wr*ar - wi*ai, ti = wr*ai + wi*ar;
        float br = sr[i0], bi = si[i0];
        sr[i0] = br + tr; si[i0] = bi + ti;
        sr[i1] = br - tr; si[i1] = bi - ti;
        __syncthreads();
    }
}

// forward row rFFT, two real rows (channel pair) packed as one complex FFT
__global__ void fft_row_fwd(const float* __restrict__ x, float* __restrict__ fq)
{
    __shared__ float sr[256], si[256], twr[256], twi[256];
    int blk = blockIdx.x;                // b*32*256 + c2*256 + h
    int b = blk >> 13, c2 = (blk >> 8) & 31, h = blk & 255;
    int tid = threadIdx.x;
    const float* xa = x + ((size_t)(b*64 + 2*c2)*256 + h)*256;
    const float* xb = xa + 65536;
    for (int w = tid; w < 256; w += 128) { sr[w] = xa[w]; si[w] = xb[w]; }
    make_twiddle(twr, twi, tid, 128, -1.f);
    fft256_tw(sr, si, tid, twr, twi);
    float* frA = fq + ((size_t)(b*128 + 2*c2)*HH + h)*W129;
    float* fiA = fq + ((size_t)(b*128 + 64 + 2*c2)*HH + h)*W129;
    float* frB = frA + (size_t)HH*W129;
    float* fiB = fiA + (size_t)HH*W129;
    for (int k = tid; k <= 128; k += 128) {
        int km = (256 - k) & 255;
        float xr = sr[k], xi = si[k], yr = sr[km], yi = si[km];
        frA[k] = 0.5f*(xr + yr);
        fiA[k] = 0.5f*(xi - yi);
        frB[k] = 0.5f*(xi + yi);
        fiB[k] = 0.5f*(yr - xr);
    }
}

// inverse row rFFT, two channels unpacked from one complex inverse FFT.
// NOTE: imaginary parts of DC (k=0) and Nyquist (k=128) bins are IGNORED,
// matching pocketfft/numpy irfft C2R semantics.
__global__ void ifft_row_real(const float* __restrict__ fq, float* __restrict__ out)
{
    __shared__ float sr[256], si[256], twr[256], twi[256];
    int blk = blockIdx.x;
    int b = blk >> 13, c2 = (blk >> 8) & 31, h = blk & 255;
    int tid = threadIdx.x;
    const float* frA = fq + ((size_t)(b*128 + 2*c2)*HH + h)*W129;
    const float* fiA = fq + ((size_t)(b*128 + 64 + 2*c2)*HH + h)*W129;
    const float* frB = frA + (size_t)HH*W129;
    const float* fiB = fiA + (size_t)HH*W129;
    make_twiddle(twr, twi, tid, 128, +1.f);
    for (int k = tid; k <= 128; k += 128) {
        float Ar = frA[k], Ai = fiA[k], Br = frB[k], Bi = fiB[k];
        if (k == 0 || k == 128) { Ai = 0.f; Bi = 0.f; }   // C2R: ignore imag of DC/Nyquist
        sr[k] = Ar - Bi;
        si[k] = Ai + Br;
        if (k > 0 && k < 128) {
            sr[256-k] = Ar + Bi;
            si[256-k] = Br - Ai;
        }
    }
    fft256_tw(sr, si, tid, twr, twi);
    float* oa = out + ((size_t)(b*64 + 2*c2)*256 + h)*256;
    float* ob = oa + 65536;
    const float s = 1.f/256.f;
    for (int w = tid; w < 256; w += 128) { oa[w] = sr[w]*s; ob[w] = si[w]*s; }
}

// ---- tiled column FFT: 8 columns per block, 256 threads (32 threads/column) ----
__global__ void fft_col(float* fq, float dir, float scale)
{
    __shared__ float sr[8*263], si[8*263];
    __shared__ float twr[256], twi[256];
    int b = blockIdx.z, c = blockIdx.y;
    int w0 = blockIdx.x * 8;
    int nw = 129 - w0; if (nw > 8) nw = 8;
    float* fr = fq + ((size_t)(b*128 + c)*HH)*W129;
    float* fi = fq + ((size_t)(b*128 + 64 + c)*HH)*W129;

    make_twiddle(twr, twi, threadIdx.x, 256, dir);
#pragma unroll
    for (int r = 0; r < 8; r++) {
        int l = threadIdx.x + 256*r;
        int h = l >> 3, w = l & 7;
        if (w < nw) {
            sr[w*263 + h] = fr[(size_t)h*W129 + w0 + w];
            si[w*263 + h] = fi[(size_t)h*W129 + w0 + w];
        }
    }
    __syncthreads();

    int col = threadIdx.x & 7;
    int j   = threadIdx.x >> 3;     // 0..31
    float* R = sr + col*263;
    float* I = si + col*263;

    for (int k = j; k < 256; k += 32) {
        int rv = __brev((unsigned)k) >> 24;
        if (rv > k) {
            float t = R[k]; R[k] = R[rv]; R[rv] = t;
            t = I[k]; I[k] = I[rv]; I[rv] = t;
        }
    }
    __syncthreads();

#pragma unroll
    for (int s = 0; s < 8; s++) {
        int half = 1 << s;
#pragma unroll
        for (int m = j; m < 128; m += 32) {
            int pidx = m & (half - 1);
            int i0 = ((m >> s) << (s + 1)) + pidx;
            int i1 = i0 + half;
            float wr = twr[half + pidx], wi = twi[half + pidx];
            float ar = R[i1], ai = I[i1];
            float tr = wr*ar - wi*ai, ti = wr*ai + wi*ar;
            float br = R[i0], bi = I[i0];
            R[i0] = br + tr; I[i0] = bi + ti;
            R[i1] = br - tr; I[i1] = bi - ti;
        }
        __syncthreads();
    }

#pragma unroll
    for (int r = 0; r < 8; r++) {
        int l = threadIdx.x + 256*r;
        int h = l >> 3, w = l & 7;
        if (w < nw) {
            fr[(size_t)h*W129 + w0 + w] = sr[w*263 + h]*scale;
            fi[(size_t)h*W129 + w0 + w] = si[w*263 + h]*scale;
        }
    }
}

// ---------------- attention small kernels ----------------
__global__ void zero_small_kernel()
{
    int t = blockIdx.x*256 + threadIdx.x;
    if (t < 512)  g_sumsq[t] = 0.f;
    if (t < 2048) g_gram[t]  = 0.f;
}

// fused gram + sumsq
__global__ void gram_kernel(const float* __restrict__ q, const float* __restrict__ k)
{
    int bh = blockIdx.x;                // b*8 + head
    int b = bh >> 3, head = bh & 7;
    const float* qb = q + ((size_t)b*64  + head*8)*HW;
    const float* kb = k + ((size_t)b*128 + head*8)*HW;
    float acc[64], qs[8], ks[8];
#pragma unroll
    for (int t = 0; t < 64; t++) acc[t] = 0.f;
#pragma unroll
    for (int t = 0; t < 8; t++) { qs[t] = 0.f; ks[t] = 0.f; }
    int start = blockIdx.y*4096;
    for (int n = start + threadIdx.x; n < start + 4096; n += 256) {
        float qv[8], kv[8];
#pragma unroll
        for (int i = 0; i < 8; i++) { qv[i] = qb[(size_t)i*HW + n]; kv[i] = kb[(size_t)i*HW + n]; }
#pragma unroll
        for (int i = 0; i < 8; i++) { qs[i] += qv[i]*qv[i]; ks[i] += kv[i]*kv[i]; }
#pragma unroll
        for (int i = 0; i < 8; i++)
#pragma unroll
            for (int j = 0; j < 8; j++)
                acc[i*8+j] += qv[i]*kv[j];
    }
#pragma unroll
    for (int t = 0; t < 64; t++) {
        float v = acc[t];
#pragma unroll
        for (int off = 16; off > 0; off >>= 1) v += __shfl_down_sync(0xffffffffu, v, off);
        if ((threadIdx.x & 31) == 0) atomicAdd(&g_gram[bh*64 + t], v);
    }
#pragma unroll
    for (int t = 0; t < 8; t++) {
        float v = qs[t];
#pragma unroll
        for (int off = 16; off > 0; off >>= 1) v += __shfl_down_sync(0xffffffffu, v, off);
        if ((threadIdx.x & 31) == 0) atomicAdd(&g_sumsq[b*64 + head*8 + t], v);
        v = ks[t];
#pragma unroll
        for (int off = 16; off > 0; off >>= 1) v += __shfl_down_sync(0xffffffffu, v, off);
        if ((threadIdx.x & 31) == 0) atomicAdd(&g_sumsq[256 + b*64 + head*8 + t], v);
    }
}

// softmax + fold proj:  M[b] = P @ blockdiag(A[b])
__global__ void softmaxM_kernel(const float* __restrict__ temp, const float* __restrict__ proj)
{
    __shared__ float A[512];
    __shared__ float dq[64], dk[64];
    int b = blockIdx.x;
    int tid = threadIdx.x;
    if (tid < 64)              dq[tid]      = fmaxf(sqrtf(g_sumsq[b*64 + tid]), 1e-12f);
    else if (tid < 128)        dk[tid - 64] = fmaxf(sqrtf(g_sumsq[256 + b*64 + tid - 64]), 1e-12f);
    __syncthreads();
    for (int t = tid; t < 512; t += 256) {
        int head = t >> 6, i = (t >> 3) & 7, j = t & 7;
        A[t] = g_gram[b*512 + t] / (dq[head*8 + i]*dk[head*8 + j]) * temp[head];
    }
    __syncthreads();
    if (tid < 64) {
        float m = -1e30f;
#pragma unroll
        for (int j = 0; j < 8; j++) m = fmaxf(m, A[tid*8 + j]);
        float s = 0.f;
        float e[8];
#pragma unroll
        for (int j = 0; j < 8; j++) { e[j] = expf(A[tid*8 + j] - m); s += e[j]; }
        float inv = 1.f/s;
#pragma unroll
        for (int j = 0; j < 8; j++) A[tid*8 + j] = e[j]*inv;
    }
    __syncthreads();
    for (int idx = tid; idx < 4096; idx += 256) {
        int co = idx >> 6, cv = idx & 63;
        int hv = cv >> 3, jv = cv & 7;
        float s = 0.f;
#pragma unroll
        for (int i = 0; i < 8; i++)
            s += proj[co*64 + hv*8 + i] * A[hv*64 + i*8 + jv];
        g_M[b*4096 + idx] = s;
    }
}

// ---------------- host orchestration ----------------
static void run_attention(const float* x, const float* y, float* out_xres,
                          const float* qw, const float* qdw,
                          const float* kvw, const float* kvdw,
                          const float* temp, const float* projw,
                          float* qbuf, float* tA, float* tB, float* M)
{
    // q path: 1x1 then dw3x3
    conv1x1_mma_kernel<<<dim3(HW/128,1,BB),256>>>(x, tB, qw, nullptr, nullptr,
                                                  64,64,0, 64,0, HW, 0, 0);
    dw3x3_kernel<<<dim3(256,64,BB),256>>>(tB, qbuf, qdw, nullptr, 64,0, 64,0);
    // kv path
    conv1x1_mma_kernel<<<dim3(HW/128,2,BB),256>>>(y, tA, kvw, nullptr, nullptr,
                                                  64,64,0, 128,0, HW, 0, 0);
    dw3x3_kernel<<<dim3(256,128,BB),256>>>(tA, tB, kvdw, nullptr, 128,0, 128,0);
    // reductions
    zero_small_kernel<<<8,256>>>();
    gram_kernel<<<dim3(32,16),256>>>(qbuf, tB);
    softmaxM_kernel<<<BB,256>>>(temp, projw);
    // out = M[b] @ v + x   (v = tB channels 64..127), written in place over x
    conv1x1_mma_kernel<<<dim3(HW/128,1,BB),256>>>(tB, out_xres, M, nullptr, x,
                                                  64,128,64, 64,0, HW, 0, 1);
}

extern "C" void kernel_launch(void* const* d_in, const int* in_sizes, int n_in,
                              void* d_out, int out_size)
{
    const float* x0      = (const float*)d_in[0];
    const float* x1      = (const float*)d_in[1];
    const float* rl_w1   = (const float*)d_in[2];
    const float* rl_b1   = (const float*)d_in[3];
    const float* rl_w2   = (const float*)d_in[4];
    const float* rl_b2   = (const float*)d_in[5];
    const float* rg_w1   = (const float*)d_in[6];
    const float* rg_w2   = (const float*)d_in[7];
    const float* att_temp= (const float*)d_in[8];
    const float* att_kv_w  = (const float*)d_in[9];
    const float* att_kv_dw = (const float*)d_in[10];
    const float* att_q_w   = (const float*)d_in[11];
    const float* att_q_dw  = (const float*)d_in[12];
    const float* att_proj_w= (const float*)d_in[13];
    const float* f1_dw   = (const float*)d_in[14];
    const float* f1_dwb  = (const float*)d_in[15];
    const float* f1_pw   = (const float*)d_in[16];
    const float* f1_pwb  = (const float*)d_in[17];
    const float* f2_dw   = (const float*)d_in[18];
    const float* f2_dwb  = (const float*)d_in[19];
    const float* f2_pw   = (const float*)d_in[20];
    const float* f2_pwb  = (const float*)d_in[21];
    float* out = (float*)d_out;

    float *fre, *spa, *qb, *tA, *tB, *fqA, *fqB, *M;
    cudaGetSymbolAddress((void**)&fre, g_fre);
    cudaGetSymbolAddress((void**)&spa, g_spa);
    cudaGetSymbolAddress((void**)&qb,  g_q);
    cudaGetSymbolAddress((void**)&tA,  g_tmpA);
    cudaGetSymbolAddress((void**)&tB,  g_tmpB);
    cudaGetSymbolAddress((void**)&fqA, g_fqA);
    cudaGetSymbolAddress((void**)&fqB, g_fqB);
    cudaGetSymbolAddress((void**)&M,   g_M);

    // ---- ResBlock_L: fre = relu(conv2(relu(conv1(x0)))) + x0 ----
    conv3x3_kernel<<<dim3(8,8,16),256>>>(x0, tA, rl_w1, rl_b1, nullptr, 1);
    conv3x3_kernel<<<dim3(8,8,16),256>>>(tA, fre, rl_w2, rl_b2, x0, 1);

    // ---- ResBlock_G: spa = irfft2(W2 @ relu(W1 @ rfft2(x1))) ----
    fft_row_fwd<<<32768,128>>>(x1, fqA);
    fft_col<<<dim3(17,64,BB),256>>>(fqA, -1.f, 1.f);
    conv1x1_mma_kernel<<<dim3(PF/128,2,BB),256>>>(fqA, fqB, rg_w1, nullptr, nullptr,
                                                  128,128,0, 128,0, PF, 1, 0);
    conv1x1_mma_kernel<<<dim3(PF/128,2,BB),256>>>(fqB, fqA, rg_w2, nullptr, nullptr,
                                                  128,128,0, 128,0, PF, 0, 0);
    fft_col<<<dim3(17,64,BB),256>>>(fqA, +1.f, 1.f/256.f);
    ifft_row_real<<<32768,128>>>(fqA, spa);

    // ---- attention (shared weights), fre then spa, each with residual ----
    run_attention(fre, spa, fre, att_q_w, att_q_dw, att_kv_w, att_kv_dw,
                  att_temp, att_proj_w, qb, tA, tB, M);
    run_attention(spa, fre, spa, att_q_w, att_q_dw, att_kv_w, att_kv_dw,
                  att_temp, att_proj_w, qb, tA, tB, M);

    // ---- fuse ----
    dw3x3_kernel<<<dim3(256,64,BB),256>>>(fre, tA, f1_dw,        f1_dwb,    64,0, 128,0);
    dw3x3_kernel<<<dim3(256,64,BB),256>>>(spa, tA, f1_dw + 64*9, f1_dwb+64, 64,0, 128,64);
    conv1x1_mma_kernel<<<dim3(HW/128,1,BB),256>>>(tA, qb, f1_pw, f1_pwb, nullptr,
                                                  128,128,0, 64,0, HW, 0, 0);
    dw3x3_kernel<<<dim3(256,64,BB),256>>>(qb, tB, f2_dw, f2_dwb, 64,0, 64,0);
    conv1x1_gate_kernel<<<dim3(HW/128,1,BB),256>>>(tB, f2_pw, f2_pwb, fre, spa, out);
}

// round 12
// speedup vs baseline: 2.1462x; 1.3873x over previous
#include <cuda_runtime.h>
#include <math.h>

#define BB 4
#define CC 64
#define HH 256
#define WWD 256
#define HW 65536
#define NF (BB*CC*HW)       /* 16777216 */
#define W129 129
#define PF (HH*W129)        /* 33024 */

// ---------------- scratch ----------------
__device__ __align__(16) float g_fre[NF];
__device__ __align__(16) float g_spa[NF];
__device__ __align__(16) float g_q[NF];
__device__ __align__(16) float g_tmpA[2*NF];
__device__ __align__(16) float g_tmpB[2*NF];
__device__ __align__(16) float g_fqA[(size_t)BB*2*CC*PF];
__device__ __align__(16) float g_fqB[(size_t)BB*2*CC*PF];
__device__ float g_sumsq[2*BB*CC];   // 512: [0..255]=q, [256..511]=k
__device__ float g_gram[BB*8*64];    // 2048
__device__ __align__(16) float g_M[BB*CC*CC];      // 16384
__device__ __align__(16) unsigned g_w3[2][64*9*64]; // conv3x3 weights, [ci][tap][o], tf32

__device__ __forceinline__ unsigned f2tf(float f)
{
    unsigned r; asm("cvt.rna.tf32.f32 %0, %1;" : "=r"(r) : "f"(f)); return r;
}

// ---------------- weight pre-transpose for conv3x3 mma ----------------
// W[o][ci][3][3] (row-major) -> g_w3[sel][(ci*9+tap)*64 + o]  (tf32 bits)
__global__ void prep_w3_kernel(const float* __restrict__ w1, const float* __restrict__ w2)
{
    int idx = blockIdx.x*256 + threadIdx.x;
    if (idx >= 64*9*64) return;
    int o = idx & 63;
    int rt = idx >> 6;          // ci*9 + tap
    int ci = rt / 9, tap = rt - ci*9;
    size_t src = ((size_t)o*64 + ci)*9 + tap;
    g_w3[0][idx] = f2tf(w1[src]);
    g_w3[1][idx] = f2tf(w2[src]);
}

// ---------------- TF32 implicit-GEMM 3x3 conv (C=64) ----------------
// block: 64 out x 128 px of one image row. 8 warps, warp = 16 out x 64 px.
// loop: 8-ci chunks (8 of them) x 9 taps, mma m16n8k8 with shifted smem reads.
__global__ void __launch_bounds__(256, 2)
conv3x3_mma_kernel(const float* __restrict__ in, float* __restrict__ out,
                   const unsigned* __restrict__ Wp, const float* __restrict__ bias,
                   const float* __restrict__ residual, int relu)
{
    __shared__ unsigned sW3[8][9][72];   // [ci][tap][o]; ci stride 648 % 32 == 8
    __shared__ unsigned sX3[8][3][132];  // [ci][dy][col]; ci stride 396 % 32 == 12
    int b  = blockIdx.z;
    int y  = blockIdx.y;
    int xb = blockIdx.x * 128;
    int tid  = threadIdx.x;
    int warp = tid >> 5, lane = tid & 31;
    int gid = lane >> 2, tig = lane & 3;
    int ow = (warp & 3) * 16, pw = (warp >> 2) * 64;

    float c[8][4];
#pragma unroll
    for (int t = 0; t < 8; t++)
#pragma unroll
        for (int i = 0; i < 4; i++) c[t][i] = 0.f;

    unsigned* sWf = &sW3[0][0][0];

    for (int c0 = 0; c0 < 64; c0 += 8) {
        // coalesced weight chunk load (already tf32, [ci][tap][o])
        const unsigned* wsrc = Wp + c0*576;
#pragma unroll
        for (int q = 0; q < 18; q++) {
            int idx = tid + q*256;       // 4608 = 18*256
            int ci = idx / 576, rem = idx - ci*576;
            int tap = rem >> 6, o = rem & 63;
            sW3[ci][tap][o] = wsrc[idx];
        }
        // X halo tile: 8 ci x 3 rows x 130 cols (global x: xb-1 .. xb+128)
        for (int idx = tid; idx < 3168; idx += 256) {
            int col = idx % 132;
            int r = idx / 132;           // ci*3 + dy
            int ci = r / 3, dy = r - ci*3;
            float v = 0.f;
            int gx = xb - 1 + col;
            int gy = y + dy - 1;
            if (col < 130 && (unsigned)gx < 256u && (unsigned)gy < 256u)
                v = in[((size_t)(b*64 + c0 + ci)*256 + gy)*256 + gx];
            sX3[ci][dy][col] = f2tf(v);
        }
        __syncthreads();

#pragma unroll
        for (int tap = 0; tap < 9; tap++) {
            const int dy = tap / 3, dx = tap - 3*dy;
            unsigned a0 = sW3[tig    ][tap][ow + gid];
            unsigned a1 = sW3[tig    ][tap][ow + gid + 8];
            unsigned a2 = sW3[tig + 4][tap][ow + gid];
            unsigned a3 = sW3[tig + 4][tap][ow + gid + 8];
            const unsigned* br0 = &sX3[tig    ][dy][dx + pw + gid];
            const unsigned* br1 = &sX3[tig + 4][dy][dx + pw + gid];
#pragma unroll
            for (int t = 0; t < 8; t++) {
                unsigned b0 = br0[t*8];
                unsigned b1 = br1[t*8];
                asm("mma.sync.aligned.m16n8k8.row.col.f32.tf32.tf32.f32 "
                    "{%0,%1,%2,%3}, {%4,%5,%6,%7}, {%8,%9}, {%0,%1,%2,%3};"
                    : "+f"(c[t][0]), "+f"(c[t][1]), "+f"(c[t][2]), "+f"(c[t][3])
                    : "r"(a0), "r"(a1), "r"(a2), "r"(a3), "r"(b0), "r"(b1));
            }
        }
        __syncthreads();
    }

    int o0 = ow + gid;
    int o1 = o0 + 8;
    float bs0 = bias[o0], bs1 = bias[o1];
    size_t r0base = ((size_t)(b*64 + o0)*256 + y)*256 + xb + pw;
    size_t r1base = ((size_t)(b*64 + o1)*256 + y)*256 + xb + pw;
#pragma unroll
    for (int t = 0; t < 8; t++) {
        int p = t*8 + 2*tig;
        float v00 = c[t][0] + bs0, v01 = c[t][1] + bs0;
        float v10 = c[t][2] + bs1, v11 = c[t][3] + bs1;
        if (relu) {
            v00 = fmaxf(v00, 0.f); v01 = fmaxf(v01, 0.f);
            v10 = fmaxf(v10, 0.f); v11 = fmaxf(v11, 0.f);
        }
        if (residual) {
            float2 r0 = *(const float2*)&residual[r0base + p];
            float2 r1 = *(const float2*)&residual[r1base + p];
            v00 += r0.x; v01 += r0.y; v10 += r1.x; v11 += r1.y;
        }
        *(float2*)&out[r0base + p] = make_float2(v00, v01);
        *(float2*)&out[r1base + p] = make_float2(v10, v11);
    }
}

// ---------------- TF32 tensor-core 1x1 conv ----------------
__global__ void __launch_bounds__(256, 2)
conv1x1_mma_kernel(const float* __restrict__ in, float* __restrict__ out,
                   const float* __restrict__ W, const float* __restrict__ bias,
                   const float* __restrict__ residual,
                   int Cin, int CinTot, int cInOff,
                   int CoutTot, int cOutOff,
                   int P, int act, int perBatchW)
{
    __shared__ unsigned sW[32][72];    // [k][o]
    __shared__ unsigned sX[32][136];   // [k][p]
    int b  = blockIdx.z;
    int og = blockIdx.y * 64;
    int pb = blockIdx.x * 128;
    const float* Wb = W + (perBatchW ? (size_t)b*64*gridDim.y*Cin : 0);
    int tid  = threadIdx.x;
    int warp = tid >> 5, lane = tid & 31;
    int gid = lane >> 2, tig = lane & 3;
    int ow = (warp & 3) * 16, pw = (warp >> 2) * 64;

    float c[8][4];
#pragma unroll
    for (int t = 0; t < 8; t++)
#pragma unroll
        for (int i = 0; i < 4; i++) c[t][i] = 0.f;

    int wo = tid >> 2, wk = (tid & 3) * 8;
    int xk = tid >> 3, xp = (tid & 7) * 16;

    for (int k0 = 0; k0 < Cin; k0 += 32) {
        const float* wp = &Wb[(size_t)(og + wo)*Cin + k0 + wk];
        float4 w0 = *(const float4*)wp;
        float4 w1 = *(const float4*)(wp + 4);
        sW[wk+0][wo] = f2tf(w0.x); sW[wk+1][wo] = f2tf(w0.y);
        sW[wk+2][wo] = f2tf(w0.z); sW[wk+3][wo] = f2tf(w0.w);
        sW[wk+4][wo] = f2tf(w1.x); sW[wk+5][wo] = f2tf(w1.y);
        sW[wk+6][wo] = f2tf(w1.z); sW[wk+7][wo] = f2tf(w1.w);

        const float* xpt = &in[((size_t)b*CinTot + cInOff + k0 + xk)*P + pb + xp];
#pragma unroll
        for (int q = 0; q < 4; q++) {
            float4 v = *(const float4*)(xpt + 4*q);
            uint4 u = make_uint4(f2tf(v.x), f2tf(v.y), f2tf(v.z), f2tf(v.w));
            *(uint4*)&sX[xk][xp + 4*q] = u;
        }
        __syncthreads();

#pragma unroll
        for (int ks = 0; ks < 4; ks++) {
            int kk = ks * 8;
            unsigned a0 = sW[kk + tig    ][ow + gid];
            unsigned a1 = sW[kk + tig    ][ow + gid + 8];
            unsigned a2 = sW[kk + tig + 4][ow + gid];
            unsigned a3 = sW[kk + tig + 4][ow + gid + 8];
#pragma unroll
            for (int t = 0; t < 8; t++) {
                unsigned b0 = sX[kk + tig    ][pw + t*8 + gid];
                unsigned b1 = sX[kk + tig + 4][pw + t*8 + gid];
                asm("mma.sync.aligned.m16n8k8.row.col.f32.tf32.tf32.f32 "
                    "{%0,%1,%2,%3}, {%4,%5,%6,%7}, {%8,%9}, {%0,%1,%2,%3};"
                    : "+f"(c[t][0]), "+f"(c[t][1]), "+f"(c[t][2]), "+f"(c[t][3])
                    : "r"(a0), "r"(a1), "r"(a2), "r"(a3), "r"(b0), "r"(b1));
            }
        }
        __syncthreads();
    }

    int o0 = og + ow + gid;
    int o1 = o0 + 8;
    float bs0 = bias ? bias[o0] : 0.f;
    float bs1 = bias ? bias[o1] : 0.f;
    size_t r0base = ((size_t)b*CoutTot + cOutOff + o0)*P + pb + pw;
    size_t r1base = ((size_t)b*CoutTot + cOutOff + o1)*P + pb + pw;
#pragma unroll
    for (int t = 0; t < 8; t++) {
        int p = t*8 + 2*tig;
        float v00 = c[t][0] + bs0, v01 = c[t][1] + bs0;
        float v10 = c[t][2] + bs1, v11 = c[t][3] + bs1;
        if (act == 1) {
            v00 = fmaxf(v00, 0.f); v01 = fmaxf(v01, 0.f);
            v10 = fmaxf(v10, 0.f); v11 = fmaxf(v11, 0.f);
        }
        if (residual) {
            float2 r0 = *(const float2*)&residual[r0base + p];
            float2 r1 = *(const float2*)&residual[r1base + p];
            v00 += r0.x; v01 += r0.y; v10 += r1.x; v11 += r1.y;
        }
        *(float2*)&out[r0base + p] = make_float2(v00, v01);
        *(float2*)&out[r1base + p] = make_float2(v10, v11);
    }
}

// ---------------- fused: f2_pw conv (64->128) + sigmoid + gate + nan_to_num ----------------
__global__ void __launch_bounds__(256, 2)
conv1x1_gate_kernel(const float* __restrict__ in, const float* __restrict__ W,
                    const float* __restrict__ bias,
                    const float* __restrict__ fre, const float* __restrict__ spa,
                    float* __restrict__ out)
{
    __shared__ float sA[16][132];
    __shared__ float sB[16][128];
    int b  = blockIdx.z;
    int pb = blockIdx.x * 128;
    int tid = threadIdx.x;
    int lo = tid & 127, lk8 = (tid >> 7) * 8;
    int rB = tid >> 4, fB = tid & 15;
    int p0 = (tid & 15) << 2;
    int ox0 = (tid >> 4) << 2;

    float acc[8][8];
#pragma unroll
    for (int j = 0; j < 8; j++)
#pragma unroll
        for (int i = 0; i < 8; i++) acc[j][i] = 0.f;

    for (int k0 = 0; k0 < 64; k0 += 16) {
        float4 w0 = *(const float4*)&W[(size_t)lo*64 + k0 + lk8];
        float4 w1 = *(const float4*)&W[(size_t)lo*64 + k0 + lk8 + 4];
        sA[lk8+0][lo]=w0.x; sA[lk8+1][lo]=w0.y; sA[lk8+2][lo]=w0.z; sA[lk8+3][lo]=w0.w;
        sA[lk8+4][lo]=w1.x; sA[lk8+5][lo]=w1.y; sA[lk8+6][lo]=w1.z; sA[lk8+7][lo]=w1.w;
        const float* bp = in + ((size_t)b*64 + k0 + rB)*HW + pb + fB*8;
        *(float4*)&sB[rB][fB*8]     = *(const float4*)bp;
        *(float4*)&sB[rB][fB*8 + 4] = *(const float4*)(bp + 4);
        __syncthreads();
#pragma unroll
        for (int k = 0; k < 16; k++) {
            float vv[8];
            *(float4*)&vv[0] = *(const float4*)&sB[k][p0];
            *(float4*)&vv[4] = *(const float4*)&sB[k][p0+64];
            float aL[4], aH[4];
            *(float4*)&aL[0] = *(const float4*)&sA[k][ox0];
            *(float4*)&aH[0] = *(const float4*)&sA[k][ox0+64];
#pragma unroll
            for (int j = 0; j < 4; j++)
#pragma unroll
                for (int i = 0; i < 8; i++) {
                    acc[j][i]   += aL[j]*vv[i];
                    acc[4+j][i] += aH[j]*vv[i];
                }
        }
        __syncthreads();
    }

#pragma unroll
    for (int j = 0; j < 4; j++) {
        int c = ox0 + j;
        float bL = bias[c], bH = bias[c + 64];
        size_t base = ((size_t)b*64 + c)*HW + pb + p0;
#pragma unroll
        for (int ch = 0; ch < 2; ch++) {
            float4 f4 = *(const float4*)&fre[base + 64*ch];
            float4 s4 = *(const float4*)&spa[base + 64*ch];
            float fv[4] = {f4.x, f4.y, f4.z, f4.w};
            float sv[4] = {s4.x, s4.y, s4.z, s4.w};
            float o4[4];
#pragma unroll
            for (int i = 0; i < 4; i++) {
                float gf = 1.f/(1.f + expf(-(acc[j][ch*4+i]   + bL)));
                float gs = 1.f/(1.f + expf(-(acc[4+j][ch*4+i] + bH)));
                float v = fv[i]*gf + sv[i]*gs;
                if (isnan(v) || isinf(v)) v = 1e-5f;
                o4[i] = v;
            }
            *(float4*)&out[base + 64*ch] = make_float4(o4[0],o4[1],o4[2],o4[3]);
        }
    }
}

// ---------------- depthwise 3x3 (pad 1) on 256x256 ----------------
__global__ void dw3x3_kernel(const float* __restrict__ in, float* __restrict__ out,
                             const float* __restrict__ w, const float* __restrict__ bias,
                             int CinTot, int cInOff, int CoutTot, int cOutOff)
{
    int b = blockIdx.z, c = blockIdx.y;
    int p = blockIdx.x*256 + threadIdx.x;
    int y = p >> 8, x = p & 255;
    const float* ip = in + ((size_t)b*CinTot + cInOff + c)*HW;
    float acc = bias ? bias[c] : 0.f;
#pragma unroll
    for (int dy = 0; dy < 3; dy++) {
        int gy = y + dy - 1;
        if ((unsigned)gy >= 256u) continue;
#pragma unroll
        for (int dx = 0; dx < 3; dx++) {
            int gx = x + dx - 1;
            if ((unsigned)gx >= 256u) continue;
            acc += w[c*9 + dy*3 + dx] * ip[gy*256 + gx];
        }
    }
    out[((size_t)b*CoutTot + cOutOff + c)*HW + p] = acc;
}

// ---------------- twiddle-table 256-pt FFT ----------------
__device__ __forceinline__ void make_twiddle(float* twr, float* twi, int tid, int nthr, float dir)
{
    for (int i = tid; i < 256; i += nthr) {
        float c = 1.f, s = 0.f;
        if (i > 0) {
            int half = 1 << (31 - __clz((unsigned)i));
            float theta = dir * 3.14159265358979323846f * (float)(i - half) / (float)half;
            __sincosf(theta, &s, &c);
        }
        twr[i] = c; twi[i] = s;
    }
}

__device__ __forceinline__ void fft256_tw(float* sr, float* si, int tid,
                                          const float* twr, const float* twi)
{
    __syncthreads();
    for (int k = tid; k < 256; k += 128) {
        int r = __brev((unsigned)k) >> 24;
        if (r > k) {
            float a = sr[k]; sr[k] = sr[r]; sr[r] = a;
            a = si[k]; si[k] = si[r]; si[r] = a;
        }
    }
    __syncthreads();
#pragma unroll
    for (int s = 0; s < 8; s++) {
        int half = 1 << s;
        int pidx = tid & (half - 1);
        int i0 = ((tid >> s) << (s + 1)) + pidx;
        int i1 = i0 + half;
        float wr = twr[half + pidx], wi = twi[half + pidx];
        float ar = sr[i1], ai = si[i1];
        float tr = wr*ar - wi*ai, ti = wr*ai + wi*ar;
        float br = sr[i0], bi = si[i0];
        sr[i0] = br + tr; si[i0] = bi + ti;
        sr[i1] = br - tr; si[i1] = bi - ti;
        __syncthreads();
    }
}

// forward row rFFT, two real rows (channel pair) packed as one complex FFT
__global__ void fft_row_fwd(const float* __restrict__ x, float* __restrict__ fq)
{
    __shared__ float sr[256], si[256], twr[256], twi[256];
    int blk = blockIdx.x;
    int b = blk >> 13, c2 = (blk >> 8) & 31, h = blk & 255;
    int tid = threadIdx.x;
    const float* xa = x + ((size_t)(b*64 + 2*c2)*256 + h)*256;
    const float* xb = xa + 65536;
    for (int w = tid; w < 256; w += 128) { sr[w] = xa[w]; si[w] = xb[w]; }
    make_twiddle(twr, twi, tid, 128, -1.f);
    fft256_tw(sr, si, tid, twr, twi);
    float* frA = fq + ((size_t)(b*128 + 2*c2)*HH + h)*W129;
    float* fiA = fq + ((size_t)(b*128 + 64 + 2*c2)*HH + h)*W129;
    float* frB = frA + (size_t)HH*W129;
    float* fiB = fiA + (size_t)HH*W129;
    for (int k = tid; k <= 128; k += 128) {
        int km = (256 - k) & 255;
        float xr = sr[k], xi = si[k], yr = sr[km], yi = si[km];
        frA[k] = 0.5f*(xr + yr);
        fiA[k] = 0.5f*(xi - yi);
        frB[k] = 0.5f*(xi + yi);
        fiB[k] = 0.5f*(yr - xr);
    }
}

// inverse row rFFT (imag of DC/Nyquist ignored — pocketfft C2R semantics)
__global__ void ifft_row_real(const float* __restrict__ fq, float* __restrict__ out)
{
    __shared__ float sr[256], si[256], twr[256], twi[256];
    int blk = blockIdx.x;
    int b = blk >> 13, c2 = (blk >> 8) & 31, h = blk & 255;
    int tid = threadIdx.x;
    const float* frA = fq + ((size_t)(b*128 + 2*c2)*HH + h)*W129;
    const float* fiA = fq + ((size_t)(b*128 + 64 + 2*c2)*HH + h)*W129;
    const float* frB = frA + (size_t)HH*W129;
    const float* fiB = fiA + (size_t)HH*W129;
    make_twiddle(twr, twi, tid, 128, +1.f);
    for (int k = tid; k <= 128; k += 128) {
        float Ar = frA[k], Ai = fiA[k], Br = frB[k], Bi = fiB[k];
        if (k == 0 || k == 128) { Ai = 0.f; Bi = 0.f; }
        sr[k] = Ar - Bi;
        si[k] = Ai + Br;
        if (k > 0 && k < 128) {
            sr[256-k] = Ar + Bi;
            si[256-k] = Br - Ai;
        }
    }
    fft256_tw(sr, si, tid, twr, twi);
    float* oa = out + ((size_t)(b*64 + 2*c2)*256 + h)*256;
    float* ob = oa + 65536;
    const float s = 1.f/256.f;
    for (int w = tid; w < 256; w += 128) { oa[w] = sr[w]*s; ob[w] = si[w]*s; }
}

// ---- tiled column FFT: 8 columns per block, 256 threads ----
__global__ void fft_col(float* fq, float dir, float scale)
{
    __shared__ float sr[8*263], si[8*263];
    __shared__ float twr[256], twi[256];
    int b = blockIdx.z, c = blockIdx.y;
    int w0 = blockIdx.x * 8;
    int nw = 129 - w0; if (nw > 8) nw = 8;
    float* fr = fq + ((size_t)(b*128 + c)*HH)*W129;
    float* fi = fq + ((size_t)(b*128 + 64 + c)*HH)*W129;

    make_twiddle(twr, twi, threadIdx.x, 256, dir);
#pragma unroll
    for (int r = 0; r < 8; r++) {
        int l = threadIdx.x + 256*r;
        int h = l >> 3, w = l & 7;
        if (w < nw) {
            sr[w*263 + h] = fr[(size_t)h*W129 + w0 + w];
            si[w*263 + h] = fi[(size_t)h*W129 + w0 + w];
        }
    }
    __syncthreads();

    int col = threadIdx.x & 7;
    int j   = threadIdx.x >> 3;
    float* R = sr + col*263;
    float* I = si + col*263;

    for (int k = j; k < 256; k += 32) {
        int rv = __brev((unsigned)k) >> 24;
        if (rv > k) {
            float t = R[k]; R[k] = R[rv]; R[rv] = t;
            t = I[k]; I[k] = I[rv]; I[rv] = t;
        }
    }
    __syncthreads();

#pragma unroll
    for (int s = 0; s < 8; s++) {
        int half = 1 << s;
#pragma unroll
        for (int m = j; m < 128; m += 32) {
            int pidx = m & (half - 1);
            int i0 = ((m >> s) << (s + 1)) + pidx;
            int i1 = i0 + half;
            float wr = twr[half + pidx], wi = twi[half + pidx];
            float ar = R[i1], ai = I[i1];
            float tr = wr*ar - wi*ai, ti = wr*ai + wi*ar;
            float br = R[i0], bi = I[i0];
            R[i0] = br + tr; I[i0] = bi + ti;
            R[i1] = br - tr; I[i1] = bi - ti;
        }
        __syncthreads();
    }

#pragma unroll
    for (int r = 0; r < 8; r++) {
        int l = threadIdx.x + 256*r;
        int h = l >> 3, w = l & 7;
        if (w < nw) {
            fr[(size_t)h*W129 + w0 + w] = sr[w*263 + h]*scale;
            fi[(size_t)h*W129 + w0 + w] = si[w*263 + h]*scale;
        }
    }
}

// ---------------- attention small kernels ----------------
__global__ void zero_small_kernel()
{
    int t = blockIdx.x*256 + threadIdx.x;
    if (t < 512)  g_sumsq[t] = 0.f;
    if (t < 2048) g_gram[t]  = 0.f;
}

__global__ void gram_kernel(const float* __restrict__ q, const float* __restrict__ k)
{
    int bh = blockIdx.x;
    int b = bh >> 3, head = bh & 7;
    const float* qb = q + ((size_t)b*64  + head*8)*HW;
    const float* kb = k + ((size_t)b*128 + head*8)*HW;
    float acc[64], qs[8], ks[8];
#pragma unroll
    for (int t = 0; t < 64; t++) acc[t] = 0.f;
#pragma unroll
    for (int t = 0; t < 8; t++) { qs[t] = 0.f; ks[t] = 0.f; }
    int start = blockIdx.y*4096;
    for (int n = start + threadIdx.x; n < start + 4096; n += 256) {
        float qv[8], kv[8];
#pragma unroll
        for (int i = 0; i < 8; i++) { qv[i] = qb[(size_t)i*HW + n]; kv[i] = kb[(size_t)i*HW + n]; }
#pragma unroll
        for (int i = 0; i < 8; i++) { qs[i] += qv[i]*qv[i]; ks[i] += kv[i]*kv[i]; }
#pragma unroll
        for (int i = 0; i < 8; i++)
#pragma unroll
            for (int j = 0; j < 8; j++)
                acc[i*8+j] += qv[i]*kv[j];
    }
#pragma unroll
    for (int t = 0; t < 64; t++) {
        float v = acc[t];
#pragma unroll
        for (int off = 16; off > 0; off >>= 1) v += __shfl_down_sync(0xffffffffu, v, off);
        if ((threadIdx.x & 31) == 0) atomicAdd(&g_gram[bh*64 + t], v);
    }
#pragma unroll
    for (int t = 0; t < 8; t++) {
        float v = qs[t];
#pragma unroll
        for (int off = 16; off > 0; off >>= 1) v += __shfl_down_sync(0xffffffffu, v, off);
        if ((threadIdx.x & 31) == 0) atomicAdd(&g_sumsq[b*64 + head*8 + t], v);
        v = ks[t];
#pragma unroll
        for (int off = 16; off > 0; off >>= 1) v += __shfl_down_sync(0xffffffffu, v, off);
        if ((threadIdx.x & 31) == 0) atomicAdd(&g_sumsq[256 + b*64 + head*8 + t], v);
    }
}

__global__ void softmaxM_kernel(const float* __restrict__ temp, const float* __restrict__ proj)
{
    __shared__ float A[512];
    __shared__ float dq[64], dk[64];
    int b = blockIdx.x;
    int tid = threadIdx.x;
    if (tid < 64)              dq[tid]      = fmaxf(sqrtf(g_sumsq[b*64 + tid]), 1e-12f);
    else if (tid < 128)        dk[tid - 64] = fmaxf(sqrtf(g_sumsq[256 + b*64 + tid - 64]), 1e-12f);
    __syncthreads();
    for (int t = tid; t < 512; t += 256) {
        int head = t >> 6, i = (t >> 3) & 7, j = t & 7;
        A[t] = g_gram[b*512 + t] / (dq[head*8 + i]*dk[head*8 + j]) * temp[head];
    }
    __syncthreads();
    if (tid < 64) {
        float m = -1e30f;
#pragma unroll
        for (int j = 0; j < 8; j++) m = fmaxf(m, A[tid*8 + j]);
        float s = 0.f;
        float e[8];
#pragma unroll
        for (int j = 0; j < 8; j++) { e[j] = expf(A[tid*8 + j] - m); s += e[j]; }
        float inv = 1.f/s;
#pragma unroll
        for (int j = 0; j < 8; j++) A[tid*8 + j] = e[j]*inv;
    }
    __syncthreads();
    for (int idx = tid; idx < 4096; idx += 256) {
        int co = idx >> 6, cv = idx & 63;
        int hv = cv >> 3, jv = cv & 7;
        float s = 0.f;
#pragma unroll
        for (int i = 0; i < 8; i++)
            s += proj[co*64 + hv*8 + i] * A[hv*64 + i*8 + jv];
        g_M[b*4096 + idx] = s;
    }
}

// ---------------- host orchestration ----------------
static void run_attention(const float* x, const float* y, float* out_xres,
                          const float* qw, const float* qdw,
                          const float* kvw, const float* kvdw,
                          const float* temp, const float* projw,
                          float* qbuf, float* tA, float* tB, float* M)
{
    conv1x1_mma_kernel<<<dim3(HW/128,1,BB),256>>>(x, tB, qw, nullptr, nullptr,
                                                  64,64,0, 64,0, HW, 0, 0);
    dw3x3_kernel<<<dim3(256,64,BB),256>>>(tB, qbuf, qdw, nullptr, 64,0, 64,0);
    conv1x1_mma_kernel<<<dim3(HW/128,2,BB),256>>>(y, tA, kvw, nullptr, nullptr,
                                                  64,64,0, 128,0, HW, 0, 0);
    dw3x3_kernel<<<dim3(256,128,BB),256>>>(tA, tB, kvdw, nullptr, 128,0, 128,0);
    zero_small_kernel<<<8,256>>>();
    gram_kernel<<<dim3(32,16),256>>>(qbuf, tB);
    softmaxM_kernel<<<BB,256>>>(temp, projw);
    conv1x1_mma_kernel<<<dim3(HW/128,1,BB),256>>>(tB, out_xres, M, nullptr, x,
                                                  64,128,64, 64,0, HW, 0, 1);
}

extern "C" void kernel_launch(void* const* d_in, const int* in_sizes, int n_in,
                              void* d_out, int out_size)
{
    const float* x0      = (const float*)d_in[0];
    const float* x1      = (const float*)d_in[1];
    const float* rl_w1   = (const float*)d_in[2];
    const float* rl_b1   = (const float*)d_in[3];
    const float* rl_w2   = (const float*)d_in[4];
    const float* rl_b2   = (const float*)d_in[5];
    const float* rg_w1   = (const float*)d_in[6];
    const float* rg_w2   = (const float*)d_in[7];
    const float* att_temp= (const float*)d_in[8];
    const float* att_kv_w  = (const float*)d_in[9];
    const float* att_kv_dw = (const float*)d_in[10];
    const float* att_q_w   = (const float*)d_in[11];
    const float* att_q_dw  = (const float*)d_in[12];
    const float* att_proj_w= (const float*)d_in[13];
    const float* f1_dw   = (const float*)d_in[14];
    const float* f1_dwb  = (const float*)d_in[15];
    const float* f1_pw   = (const float*)d_in[16];
    const float* f1_pwb  = (const float*)d_in[17];
    const float* f2_dw   = (const float*)d_in[18];
    const float* f2_dwb  = (const float*)d_in[19];
    const float* f2_pw   = (const float*)d_in[20];
    const float* f2_pwb  = (const float*)d_in[21];
    float* out = (float*)d_out;

    float *fre, *spa, *qb, *tA, *tB, *fqA, *fqB, *M;
    unsigned* w3;
    cudaGetSymbolAddress((void**)&fre, g_fre);
    cudaGetSymbolAddress((void**)&spa, g_spa);
    cudaGetSymbolAddress((void**)&qb,  g_q);
    cudaGetSymbolAddress((void**)&tA,  g_tmpA);
    cudaGetSymbolAddress((void**)&tB,  g_tmpB);
    cudaGetSymbolAddress((void**)&fqA, g_fqA);
    cudaGetSymbolAddress((void**)&fqB, g_fqB);
    cudaGetSymbolAddress((void**)&M,   g_M);
    cudaGetSymbolAddress((void**)&w3,  g_w3);

    // ---- ResBlock_L: fre = relu(conv2(relu(conv1(x0)))) + x0 ----
    prep_w3_kernel<<<144,256>>>(rl_w1, rl_w2);
    conv3x3_mma_kernel<<<dim3(2,256,BB),256>>>(x0, tA, w3,           rl_b1, nullptr, 1);
    conv3x3_mma_kernel<<<dim3(2,256,BB),256>>>(tA, fre, w3 + 64*9*64, rl_b2, x0, 1);

    // ---- ResBlock_G: spa = irfft2(W2 @ relu(W1 @ rfft2(x1))) ----
    fft_row_fwd<<<32768,128>>>(x1, fqA);
    fft_col<<<dim3(17,64,BB),256>>>(fqA, -1.f, 1.f);
    conv1x1_mma_kernel<<<dim3(PF/128,2,BB),256>>>(fqA, fqB, rg_w1, nullptr, nullptr,
                                                  128,128,0, 128,0, PF, 1, 0);
    conv1x1_mma_kernel<<<dim3(PF/128,2,BB),256>>>(fqB, fqA, rg_w2, nullptr, nullptr,
                                                  128,128,0, 128,0, PF, 0, 0);
    fft_col<<<dim3(17,64,BB),256>>>(fqA, +1.f, 1.f/256.f);
    ifft_row_real<<<32768,128>>>(fqA, spa);

    // ---- attention (shared weights), fre then spa, each with residual ----
    run_attention(fre, spa, fre, att_q_w, att_q_dw, att_kv_w, att_kv_dw,
                  att_temp, att_proj_w, qb, tA, tB, M);
    run_attention(spa, fre, spa, att_q_w, att_q_dw, att_kv_w, att_kv_dw,
                  att_temp, att_proj_w, qb, tA, tB, M);

    // ---- fuse ----
    dw3x3_kernel<<<dim3(256,64,BB),256>>>(fre, tA, f1_dw,        f1_dwb,    64,0, 128,0);
    dw3x3_kernel<<<dim3(256,64,BB),256>>>(spa, tA, f1_dw + 64*9, f1_dwb+64, 64,0, 128,64);
    conv1x1_mma_kernel<<<dim3(HW/128,1,BB),256>>>(tA, qb, f1_pw, f1_pwb, nullptr,
                                                  128,128,0, 64,0, HW, 0, 0);
    dw3x3_kernel<<<dim3(256,64,BB),256>>>(qb, tB, f2_dw, f2_dwb, 64,0, 64,0);
    conv1x1_gate_kernel<<<dim3(HW/128,1,BB),256>>>(tB, f2_pw, f2_pwb, fre, spa, out);
}

// round 13
// speedup vs baseline: 2.7324x; 1.2732x over previous
#include <cuda_runtime.h>
#include <math.h>

#define BB 4
#define CC 64
#define HH 256
#define WWD 256
#define HW 65536
#define NF (BB*CC*HW)       /* 16777216 */
#define W129 129
#define PF (HH*W129)        /* 33024 */

// ---------------- scratch ----------------
__device__ __align__(16) float g_fre[NF];
__device__ __align__(16) float g_spa[NF];
__device__ __align__(16) float g_q[NF];
__device__ __align__(16) float g_tmpA[2*NF];
__device__ __align__(16) float g_tmpB[2*NF];
__device__ __align__(16) float g_fqA[(size_t)BB*2*CC*PF];
__device__ __align__(16) float g_fqB[(size_t)BB*2*CC*PF];
__device__ float g_sumsq[2*BB*CC];   // 512: [0..255]=q, [256..511]=k
__device__ float g_gram[BB*8*64];    // 2048
__device__ __align__(16) float g_M[BB*CC*CC];      // 16384
__device__ __align__(16) unsigned g_w3[2][64*9*64]; // conv3x3 weights, [ci][tap][o], tf32

__device__ __forceinline__ unsigned f2tf(float f)
{
    unsigned r; asm("cvt.rna.tf32.f32 %0, %1;" : "=r"(r) : "f"(f)); return r;
}

// ---------------- weight pre-transpose for conv3x3 mma ----------------
__global__ void prep_w3_kernel(const float* __restrict__ w1, const float* __restrict__ w2)
{
    int idx = blockIdx.x*256 + threadIdx.x;
    if (idx >= 64*9*64) return;
    int o = idx & 63;
    int rt = idx >> 6;          // ci*9 + tap
    int ci = rt / 9, tap = rt - ci*9;
    size_t src = ((size_t)o*64 + ci)*9 + tap;
    g_w3[0][idx] = f2tf(w1[src]);
    g_w3[1][idx] = f2tf(w2[src]);
}

// ---------------- TF32 implicit-GEMM 3x3 conv (C=64) ----------------
__global__ void __launch_bounds__(256, 2)
conv3x3_mma_kernel(const float* __restrict__ in, float* __restrict__ out,
                   const unsigned* __restrict__ Wp, const float* __restrict__ bias,
                   const float* __restrict__ residual, int relu)
{
    __shared__ unsigned sW3[8][9][72];   // [ci][tap][o]
    __shared__ unsigned sX3[8][3][132];  // [ci][dy][col]
    int b  = blockIdx.z;
    int y  = blockIdx.y;
    int xb = blockIdx.x * 128;
    int tid  = threadIdx.x;
    int warp = tid >> 5, lane = tid & 31;
    int gid = lane >> 2, tig = lane & 3;
    int ow = (warp & 3) * 16, pw = (warp >> 2) * 64;

    float c[8][4];
#pragma unroll
    for (int t = 0; t < 8; t++)
#pragma unroll
        for (int i = 0; i < 4; i++) c[t][i] = 0.f;

    for (int c0 = 0; c0 < 64; c0 += 8) {
        const unsigned* wsrc = Wp + c0*576;
#pragma unroll
        for (int q = 0; q < 18; q++) {
            int idx = tid + q*256;
            int ci = idx / 576, rem = idx - ci*576;
            int tap = rem >> 6, o = rem & 63;
            sW3[ci][tap][o] = wsrc[idx];
        }
        for (int idx = tid; idx < 3168; idx += 256) {
            int col = idx % 132;
            int r = idx / 132;
            int ci = r / 3, dy = r - ci*3;
            float v = 0.f;
            int gx = xb - 1 + col;
            int gy = y + dy - 1;
            if (col < 130 && (unsigned)gx < 256u && (unsigned)gy < 256u)
                v = in[((size_t)(b*64 + c0 + ci)*256 + gy)*256 + gx];
            sX3[ci][dy][col] = f2tf(v);
        }
        __syncthreads();

#pragma unroll
        for (int tap = 0; tap < 9; tap++) {
            const int dy = tap / 3, dx = tap - 3*dy;
            unsigned a0 = sW3[tig    ][tap][ow + gid];
            unsigned a1 = sW3[tig    ][tap][ow + gid + 8];
            unsigned a2 = sW3[tig + 4][tap][ow + gid];
            unsigned a3 = sW3[tig + 4][tap][ow + gid + 8];
            const unsigned* br0 = &sX3[tig    ][dy][dx + pw + gid];
            const unsigned* br1 = &sX3[tig + 4][dy][dx + pw + gid];
#pragma unroll
            for (int t = 0; t < 8; t++) {
                unsigned b0 = br0[t*8];
                unsigned b1 = br1[t*8];
                asm("mma.sync.aligned.m16n8k8.row.col.f32.tf32.tf32.f32 "
                    "{%0,%1,%2,%3}, {%4,%5,%6,%7}, {%8,%9}, {%0,%1,%2,%3};"
                    : "+f"(c[t][0]), "+f"(c[t][1]), "+f"(c[t][2]), "+f"(c[t][3])
                    : "r"(a0), "r"(a1), "r"(a2), "r"(a3), "r"(b0), "r"(b1));
            }
        }
        __syncthreads();
    }

    int o0 = ow + gid;
    int o1 = o0 + 8;
    float bs0 = bias[o0], bs1 = bias[o1];
    size_t r0base = ((size_t)(b*64 + o0)*256 + y)*256 + xb + pw;
    size_t r1base = ((size_t)(b*64 + o1)*256 + y)*256 + xb + pw;
#pragma unroll
    for (int t = 0; t < 8; t++) {
        int p = t*8 + 2*tig;
        float v00 = c[t][0] + bs0, v01 = c[t][1] + bs0;
        float v10 = c[t][2] + bs1, v11 = c[t][3] + bs1;
        if (relu) {
            v00 = fmaxf(v00, 0.f); v01 = fmaxf(v01, 0.f);
            v10 = fmaxf(v10, 0.f); v11 = fmaxf(v11, 0.f);
        }
        if (residual) {
            float2 r0 = *(const float2*)&residual[r0base + p];
            float2 r1 = *(const float2*)&residual[r1base + p];
            v00 += r0.x; v01 += r0.y; v10 += r1.x; v11 += r1.y;
        }
        *(float2*)&out[r0base + p] = make_float2(v00, v01);
        *(float2*)&out[r1base + p] = make_float2(v10, v11);
    }
}

// ---------------- TF32 tensor-core 1x1 conv ----------------
__global__ void __launch_bounds__(256, 2)
conv1x1_mma_kernel(const float* __restrict__ in, float* __restrict__ out,
                   const float* __restrict__ W, const float* __restrict__ bias,
                   const float* __restrict__ residual,
                   int Cin, int CinTot, int cInOff,
                   int CoutTot, int cOutOff,
                   int P, int act, int perBatchW)
{
    __shared__ unsigned sW[32][72];
    __shared__ unsigned sX[32][136];
    int b  = blockIdx.z;
    int og = blockIdx.y * 64;
    int pb = blockIdx.x * 128;
    const float* Wb = W + (perBatchW ? (size_t)b*64*gridDim.y*Cin : 0);
    int tid  = threadIdx.x;
    int warp = tid >> 5, lane = tid & 31;
    int gid = lane >> 2, tig = lane & 3;
    int ow = (warp & 3) * 16, pw = (warp >> 2) * 64;

    float c[8][4];
#pragma unroll
    for (int t = 0; t < 8; t++)
#pragma unroll
        for (int i = 0; i < 4; i++) c[t][i] = 0.f;

    int wo = tid >> 2, wk = (tid & 3) * 8;
    int xk = tid >> 3, xp = (tid & 7) * 16;

    for (int k0 = 0; k0 < Cin; k0 += 32) {
        const float* wp = &Wb[(size_t)(og + wo)*Cin + k0 + wk];
        float4 w0 = *(const float4*)wp;
        float4 w1 = *(const float4*)(wp + 4);
        sW[wk+0][wo] = f2tf(w0.x); sW[wk+1][wo] = f2tf(w0.y);
        sW[wk+2][wo] = f2tf(w0.z); sW[wk+3][wo] = f2tf(w0.w);
        sW[wk+4][wo] = f2tf(w1.x); sW[wk+5][wo] = f2tf(w1.y);
        sW[wk+6][wo] = f2tf(w1.z); sW[wk+7][wo] = f2tf(w1.w);

        const float* xpt = &in[((size_t)b*CinTot + cInOff + k0 + xk)*P + pb + xp];
#pragma unroll
        for (int q = 0; q < 4; q++) {
            float4 v = *(const float4*)(xpt + 4*q);
            uint4 u = make_uint4(f2tf(v.x), f2tf(v.y), f2tf(v.z), f2tf(v.w));
            *(uint4*)&sX[xk][xp + 4*q] = u;
        }
        __syncthreads();

#pragma unroll
        for (int ks = 0; ks < 4; ks++) {
            int kk = ks * 8;
            unsigned a0 = sW[kk + tig    ][ow + gid];
            unsigned a1 = sW[kk + tig    ][ow + gid + 8];
            unsigned a2 = sW[kk + tig + 4][ow + gid];
            unsigned a3 = sW[kk + tig + 4][ow + gid + 8];
#pragma unroll
            for (int t = 0; t < 8; t++) {
                unsigned b0 = sX[kk + tig    ][pw + t*8 + gid];
                unsigned b1 = sX[kk + tig + 4][pw + t*8 + gid];
                asm("mma.sync.aligned.m16n8k8.row.col.f32.tf32.tf32.f32 "
                    "{%0,%1,%2,%3}, {%4,%5,%6,%7}, {%8,%9}, {%0,%1,%2,%3};"
                    : "+f"(c[t][0]), "+f"(c[t][1]), "+f"(c[t][2]), "+f"(c[t][3])
                    : "r"(a0), "r"(a1), "r"(a2), "r"(a3), "r"(b0), "r"(b1));
            }
        }
        __syncthreads();
    }

    int o0 = og + ow + gid;
    int o1 = o0 + 8;
    float bs0 = bias ? bias[o0] : 0.f;
    float bs1 = bias ? bias[o1] : 0.f;
    size_t r0base = ((size_t)b*CoutTot + cOutOff + o0)*P + pb + pw;
    size_t r1base = ((size_t)b*CoutTot + cOutOff + o1)*P + pb + pw;
#pragma unroll
    for (int t = 0; t < 8; t++) {
        int p = t*8 + 2*tig;
        float v00 = c[t][0] + bs0, v01 = c[t][1] + bs0;
        float v10 = c[t][2] + bs1, v11 = c[t][3] + bs1;
        if (act == 1) {
            v00 = fmaxf(v00, 0.f); v01 = fmaxf(v01, 0.f);
            v10 = fmaxf(v10, 0.f); v11 = fmaxf(v11, 0.f);
        }
        if (residual) {
            float2 r0 = *(const float2*)&residual[r0base + p];
            float2 r1 = *(const float2*)&residual[r1base + p];
            v00 += r0.x; v01 += r0.y; v10 += r1.x; v11 += r1.y;
        }
        *(float2*)&out[r0base + p] = make_float2(v00, v01);
        *(float2*)&out[r1base + p] = make_float2(v10, v11);
    }
}

// ---------------- fused: f2_pw conv (64->128) + sigmoid + gate + nan_to_num ----------------
__global__ void __launch_bounds__(256, 2)
conv1x1_gate_kernel(const float* __restrict__ in, const float* __restrict__ W,
                    const float* __restrict__ bias,
                    const float* __restrict__ fre, const float* __restrict__ spa,
                    float* __restrict__ out)
{
    __shared__ float sA[16][132];
    __shared__ float sB[16][128];
    int b  = blockIdx.z;
    int pb = blockIdx.x * 128;
    int tid = threadIdx.x;
    int lo = tid & 127, lk8 = (tid >> 7) * 8;
    int rB = tid >> 4, fB = tid & 15;
    int p0 = (tid & 15) << 2;
    int ox0 = (tid >> 4) << 2;

    float acc[8][8];
#pragma unroll
    for (int j = 0; j < 8; j++)
#pragma unroll
        for (int i = 0; i < 8; i++) acc[j][i] = 0.f;

    for (int k0 = 0; k0 < 64; k0 += 16) {
        float4 w0 = *(const float4*)&W[(size_t)lo*64 + k0 + lk8];
        float4 w1 = *(const float4*)&W[(size_t)lo*64 + k0 + lk8 + 4];
        sA[lk8+0][lo]=w0.x; sA[lk8+1][lo]=w0.y; sA[lk8+2][lo]=w0.z; sA[lk8+3][lo]=w0.w;
        sA[lk8+4][lo]=w1.x; sA[lk8+5][lo]=w1.y; sA[lk8+6][lo]=w1.z; sA[lk8+7][lo]=w1.w;
        const float* bp = in + ((size_t)b*64 + k0 + rB)*HW + pb + fB*8;
        *(float4*)&sB[rB][fB*8]     = *(const float4*)bp;
        *(float4*)&sB[rB][fB*8 + 4] = *(const float4*)(bp + 4);
        __syncthreads();
#pragma unroll
        for (int k = 0; k < 16; k++) {
            float vv[8];
            *(float4*)&vv[0] = *(const float4*)&sB[k][p0];
            *(float4*)&vv[4] = *(const float4*)&sB[k][p0+64];
            float aL[4], aH[4];
            *(float4*)&aL[0] = *(const float4*)&sA[k][ox0];
            *(float4*)&aH[0] = *(const float4*)&sA[k][ox0+64];
#pragma unroll
            for (int j = 0; j < 4; j++)
#pragma unroll
                for (int i = 0; i < 8; i++) {
                    acc[j][i]   += aL[j]*vv[i];
                    acc[4+j][i] += aH[j]*vv[i];
                }
        }
        __syncthreads();
    }

#pragma unroll
    for (int j = 0; j < 4; j++) {
        int c = ox0 + j;
        float bL = bias[c], bH = bias[c + 64];
        size_t base = ((size_t)b*64 + c)*HW + pb + p0;
#pragma unroll
        for (int ch = 0; ch < 2; ch++) {
            float4 f4 = *(const float4*)&fre[base + 64*ch];
            float4 s4 = *(const float4*)&spa[base + 64*ch];
            float fv[4] = {f4.x, f4.y, f4.z, f4.w};
            float sv[4] = {s4.x, s4.y, s4.z, s4.w};
            float o4[4];
#pragma unroll
            for (int i = 0; i < 4; i++) {
                float gf = 1.f/(1.f + expf(-(acc[j][ch*4+i]   + bL)));
                float gs = 1.f/(1.f + expf(-(acc[4+j][ch*4+i] + bH)));
                float v = fv[i]*gf + sv[i]*gs;
                if (isnan(v) || isinf(v)) v = 1e-5f;
                o4[i] = v;
            }
            *(float4*)&out[base + 64*ch] = make_float4(o4[0],o4[1],o4[2],o4[3]);
        }
    }
}

// ---------------- depthwise 3x3 (pad 1), 4 px/thread vectorized ----------------
__global__ void dw3x3_kernel(const float* __restrict__ in, float* __restrict__ out,
                             const float* __restrict__ w, const float* __restrict__ bias,
                             int CinTot, int cInOff, int CoutTot, int cOutOff)
{
    int b = blockIdx.z, c = blockIdx.y;
    int p4 = (blockIdx.x*256 + threadIdx.x) * 4;
    int y = p4 >> 8, x = p4 & 255;
    const float* ip = in + ((size_t)b*CinTot + cInOff + c)*HW;
    float bs = bias ? bias[c] : 0.f;
    float a0 = bs, a1 = bs, a2 = bs, a3 = bs;
#pragma unroll
    for (int dy = 0; dy < 3; dy++) {
        int gy = y + dy - 1;
        if ((unsigned)gy >= 256u) continue;
        const float* row = ip + gy*256 + x;
        float4 f = *(const float4*)row;
        float l = (x > 0)   ? row[-1] : 0.f;
        float r = (x < 252) ? row[4]  : 0.f;
        float wA = w[c*9 + dy*3], wB = w[c*9 + dy*3 + 1], wC = w[c*9 + dy*3 + 2];
        a0 += wA*l   + wB*f.x + wC*f.y;
        a1 += wA*f.x + wB*f.y + wC*f.z;
        a2 += wA*f.y + wB*f.z + wC*f.w;
        a3 += wA*f.z + wB*f.w + wC*r;
    }
    *(float4*)&out[((size_t)b*CoutTot + cOutOff + c)*HW + p4] = make_float4(a0,a1,a2,a3);
}

// ---------------- radix-4 256-pt FFT (skewed smem, digit-reversed input) ----------------
__device__ __forceinline__ int SK(int p) { return p + (p >> 5); }
__device__ __forceinline__ int DR4(int p)
{
    return ((p & 3) << 6) | (((p >> 2) & 3) << 4) | (((p >> 4) & 3) << 2) | ((p >> 6) & 3);
}

__device__ __forceinline__ void make_tw256(float* twr, float* twi, int tid, int nthr, float dir)
{
    for (int m = tid; m < 256; m += nthr) {
        float s, c;
        __sincosf(dir * 6.283185307179586f * (float)m * (1.f/256.f), &s, &c);
        twr[m] = c; twi[m] = s;
    }
}

__device__ __forceinline__ void bf4(float* sr, float* si,
                                    int i0, int i1, int i2, int i3,
                                    float w1r, float w1i, float w2r, float w2i,
                                    float w3r, float w3i, float dir, bool usetw)
{
    float x0r = sr[i0], x0i = si[i0];
    float x1r = sr[i1], x1i = si[i1];
    float x2r = sr[i2], x2i = si[i2];
    float x3r = sr[i3], x3i = si[i3];
    float t1r, t1i, t2r, t2i, t3r, t3i;
    if (usetw) {
        t1r = x1r*w1r - x1i*w1i; t1i = x1r*w1i + x1i*w1r;
        t2r = x2r*w2r - x2i*w2i; t2i = x2r*w2i + x2i*w2r;
        t3r = x3r*w3r - x3i*w3i; t3i = x3r*w3i + x3i*w3r;
    } else {
        t1r = x1r; t1i = x1i; t2r = x2r; t2i = x2i; t3r = x3r; t3i = x3i;
    }
    float ar = x0r + t2r, ai = x0i + t2i;
    float br = x0r - t2r, bi = x0i - t2i;
    float cr = t1r + t3r, ci = t1i + t3i;
    float dr = t1r - t3r, di = t1i - t3i;
    sr[i0] = ar + cr;        si[i0] = ai + ci;
    sr[i2] = ar - cr;        si[i2] = ai - ci;
    sr[i1] = br - dir*di;    si[i1] = bi + dir*dr;
    sr[i3] = br + dir*di;    si[i3] = bi - dir*dr;
}

// 64 threads per FFT (j = 0..63). Input must be stored at SK(DR4(pos)).
__device__ __forceinline__ void fft256_r4(float* sr, float* si, int j,
                                          const float* twr, const float* twi, float dir)
{
    __syncthreads();
    {   // stage 0: half=1, no twiddle, in place (input pre-permuted)
        int base = 4*j;
        bf4(sr, si, SK(base), SK(base+1), SK(base+2), SK(base+3),
            0.f,0.f,0.f,0.f,0.f,0.f, dir, false);
    }
    __syncthreads();
    {   // stage 1: half=4, L=16, tw step 16
        int jj = j & 3, g = j >> 2;
        int base = g*16 + jj;
        bf4(sr, si, SK(base), SK(base+4), SK(base+8), SK(base+12),
            twr[16*jj], twi[16*jj], twr[32*jj], twi[32*jj], twr[48*jj], twi[48*jj],
            dir, true);
    }
    __syncthreads();
    {   // stage 2: half=16, L=64, tw step 4
        int jj = j & 15, g = j >> 4;
        int base = g*64 + jj;
        bf4(sr, si, SK(base), SK(base+16), SK(base+32), SK(base+48),
            twr[4*jj], twi[4*jj], twr[8*jj], twi[8*jj], twr[12*jj], twi[12*jj],
            dir, true);
    }
    __syncthreads();
    {   // stage 3: half=64, L=256, tw step 1
        bf4(sr, si, SK(j), SK(j+64), SK(j+128), SK(j+192),
            twr[j], twi[j], twr[2*j], twi[2*j], twr[3*j], twi[3*j],
            dir, true);
    }
    __syncthreads();
}

// forward row rFFT: 2 packed complex FFTs per block (4 channels), 128 threads
__global__ void fft_row_fwd(const float* __restrict__ x, float* __restrict__ fq)
{
    __shared__ float sr[2][264], si[2][264], twr[256], twi[256];
    int blk = blockIdx.x;                // 16384: b*16*256 + c4*256 + h
    int b = blk >> 12, c4 = (blk >> 8) & 15, h = blk & 255;
    int tid = threadIdx.x;
    int fid = tid >> 6, j = tid & 63;
    int cA = c4*4 + fid*2;
    const float* xa = x + ((size_t)(b*64 + cA)*256 + h)*256;
    const float* xb = xa + 65536;
    make_tw256(twr, twi, tid, 128, -1.f);
    float* R = sr[fid]; float* I = si[fid];
    for (int w = j; w < 256; w += 64) {
        int d = SK(DR4(w));
        R[d] = xa[w]; I[d] = xb[w];
    }
    fft256_r4(R, I, j, twr, twi, -1.f);
    float* frA = fq + ((size_t)(b*128 + cA)*HH + h)*W129;
    float* fiA = fq + ((size_t)(b*128 + 64 + cA)*HH + h)*W129;
    float* frB = frA + (size_t)HH*W129;
    float* fiB = fiA + (size_t)HH*W129;
    for (int k = j; k <= 128; k += 64) {
        int km = (256 - k) & 255;
        float xr = R[SK(k)], xi = I[SK(k)], yr = R[SK(km)], yi = I[SK(km)];
        frA[k] = 0.5f*(xr + yr);
        fiA[k] = 0.5f*(xi - yi);
        frB[k] = 0.5f*(xi + yi);
        fiB[k] = 0.5f*(yr - xr);
    }
}

// inverse row rFFT (imag of DC/Nyquist ignored — pocketfft C2R semantics)
__global__ void ifft_row_real(const float* __restrict__ fq, float* __restrict__ out)
{
    __shared__ float sr[2][264], si[2][264], twr[256], twi[256];
    int blk = blockIdx.x;
    int b = blk >> 12, c4 = (blk >> 8) & 15, h = blk & 255;
    int tid = threadIdx.x;
    int fid = tid >> 6, j = tid & 63;
    int cA = c4*4 + fid*2;
    const float* frA = fq + ((size_t)(b*128 + cA)*HH + h)*W129;
    const float* fiA = fq + ((size_t)(b*128 + 64 + cA)*HH + h)*W129;
    const float* frB = frA + (size_t)HH*W129;
    const float* fiB = fiA + (size_t)HH*W129;
    make_tw256(twr, twi, tid, 128, +1.f);
    float* R = sr[fid]; float* I = si[fid];
    for (int k = j; k <= 128; k += 64) {
        float Ar = frA[k], Ai = fiA[k], Br = frB[k], Bi = fiB[k];
        if (k == 0 || k == 128) { Ai = 0.f; Bi = 0.f; }
        int d = SK(DR4(k));
        R[d] = Ar - Bi; I[d] = Ai + Br;
        if (k > 0 && k < 128) {
            int d2 = SK(DR4(256 - k));
            R[d2] = Ar + Bi; I[d2] = Br - Ai;
        }
    }
    fft256_r4(R, I, j, twr, twi, +1.f);
    float* oa = out + ((size_t)(b*64 + cA)*256 + h)*256;
    float* ob = oa + 65536;
    const float s = 1.f/256.f;
    for (int w = j; w < 256; w += 64) { oa[w] = R[SK(w)]*s; ob[w] = I[SK(w)]*s; }
}

// tiled column FFT: 8 columns per block, 512 threads (one 64-thread FFT per column)
__global__ void __launch_bounds__(512)
fft_col(float* fq, float dir, float scale)
{
    __shared__ float sr[8*264], si[8*264];
    __shared__ float twr[256], twi[256];
    int b = blockIdx.z, c = blockIdx.y;
    int w0 = blockIdx.x * 8;
    int nw = 129 - w0; if (nw > 8) nw = 8;
    float* fr = fq + ((size_t)(b*128 + c)*HH)*W129;
    float* fi = fq + ((size_t)(b*128 + 64 + c)*HH)*W129;
    int tid = threadIdx.x;

    make_tw256(twr, twi, tid, 512, dir);
#pragma unroll
    for (int r = 0; r < 4; r++) {
        int l = tid + 512*r;
        int h = l >> 3, w = l & 7;
        if (w < nw) {
            int d = w*264 + SK(DR4(h));
            sr[d] = fr[(size_t)h*W129 + w0 + w];
            si[d] = fi[(size_t)h*W129 + w0 + w];
        }
    }
    int col = tid >> 6, j = tid & 63;
    fft256_r4(sr + col*264, si + col*264, j, twr, twi, dir);
#pragma unroll
    for (int r = 0; r < 4; r++) {
        int l = tid + 512*r;
        int h = l >> 3, w = l & 7;
        if (w < nw) {
            fr[(size_t)h*W129 + w0 + w] = sr[w*264 + SK(h)]*scale;
            fi[(size_t)h*W129 + w0 + w] = si[w*264 + SK(h)]*scale;
        }
    }
}

// ---------------- attention small kernels ----------------
__global__ void zero_small_kernel()
{
    int t = blockIdx.x*256 + threadIdx.x;
    if (t < 512)  g_sumsq[t] = 0.f;
    if (t < 2048) g_gram[t]  = 0.f;
}

__global__ void gram_kernel(const float* __restrict__ q, const float* __restrict__ k)
{
    int bh = blockIdx.x;
    int b = bh >> 3, head = bh & 7;
    const float* qb = q + ((size_t)b*64  + head*8)*HW;
    const float* kb = k + ((size_t)b*128 + head*8)*HW;
    float acc[64], qs[8], ks[8];
#pragma unroll
    for (int t = 0; t < 64; t++) acc[t] = 0.f;
#pragma unroll
    for (int t = 0; t < 8; t++) { qs[t] = 0.f; ks[t] = 0.f; }
    int start = blockIdx.y*4096;
    for (int n = start + threadIdx.x; n < start + 4096; n += 256) {
        float qv[8], kv[8];
#pragma unroll
        for (int i = 0; i < 8; i++) { qv[i] = qb[(size_t)i*HW + n]; kv[i] = kb[(size_t)i*HW + n]; }
#pragma unroll
        for (int i = 0; i < 8; i++) { qs[i] += qv[i]*qv[i]; ks[i] += kv[i]*kv[i]; }
#pragma unroll
        for (int i = 0; i < 8; i++)
#pragma unroll
            for (int j = 0; j < 8; j++)
                acc[i*8+j] += qv[i]*kv[j];
    }
#pragma unroll
    for (int t = 0; t < 64; t++) {
        float v = acc[t];
#pragma unroll
        for (int off = 16; off > 0; off >>= 1) v += __shfl_down_sync(0xffffffffu, v, off);
        if ((threadIdx.x & 31) == 0) atomicAdd(&g_gram[bh*64 + t], v);
    }
#pragma unroll
    for (int t = 0; t < 8; t++) {
        float v = qs[t];
#pragma unroll
        for (int off = 16; off > 0; off >>= 1) v += __shfl_down_sync(0xffffffffu, v, off);
        if ((threadIdx.x & 31) == 0) atomicAdd(&g_sumsq[b*64 + head*8 + t], v);
        v = ks[t];
#pragma unroll
        for (int off = 16; off > 0; off >>= 1) v += __shfl_down_sync(0xffffffffu, v, off);
        if ((threadIdx.x & 31) == 0) atomicAdd(&g_sumsq[256 + b*64 + head*8 + t], v);
    }
}

__global__ void softmaxM_kernel(const float* __restrict__ temp, const float* __restrict__ proj)
{
    __shared__ float A[512];
    __shared__ float dq[64], dk[64];
    int b = blockIdx.x;
    int tid = threadIdx.x;
    if (tid < 64)              dq[tid]      = fmaxf(sqrtf(g_sumsq[b*64 + tid]), 1e-12f);
    else if (tid < 128)        dk[tid - 64] = fmaxf(sqrtf(g_sumsq[256 + b*64 + tid - 64]), 1e-12f);
    __syncthreads();
    for (int t = tid; t < 512; t += 256) {
        int head = t >> 6, i = (t >> 3) & 7, j = t & 7;
        A[t] = g_gram[b*512 + t] / (dq[head*8 + i]*dk[head*8 + j]) * temp[head];
    }
    __syncthreads();
    if (tid < 64) {
        float m = -1e30f;
#pragma unroll
        for (int j = 0; j < 8; j++) m = fmaxf(m, A[tid*8 + j]);
        float s = 0.f;
        float e[8];
#pragma unroll
        for (int j = 0; j < 8; j++) { e[j] = expf(A[tid*8 + j] - m); s += e[j]; }
        float inv = 1.f/s;
#pragma unroll
        for (int j = 0; j < 8; j++) A[tid*8 + j] = e[j]*inv;
    }
    __syncthreads();
    for (int idx = tid; idx < 4096; idx += 256) {
        int co = idx >> 6, cv = idx & 63;
        int hv = cv >> 3, jv = cv & 7;
        float s = 0.f;
#pragma unroll
        for (int i = 0; i < 8; i++)
            s += proj[co*64 + hv*8 + i] * A[hv*64 + i*8 + jv];
        g_M[b*4096 + idx] = s;
    }
}

// ---------------- host orchestration ----------------
static void run_attention(const float* x, const float* y, float* out_xres,
                          const float* qw, const float* qdw,
                          const float* kvw, const float* kvdw,
                          const float* temp, const float* projw,
                          float* qbuf, float* tA, float* tB, float* M)
{
    conv1x1_mma_kernel<<<dim3(HW/128,1,BB),256>>>(x, tB, qw, nullptr, nullptr,
                                                  64,64,0, 64,0, HW, 0, 0);
    dw3x3_kernel<<<dim3(64,64,BB),256>>>(tB, qbuf, qdw, nullptr, 64,0, 64,0);
    conv1x1_mma_kernel<<<dim3(HW/128,2,BB),256>>>(y, tA, kvw, nullptr, nullptr,
                                                  64,64,0, 128,0, HW, 0, 0);
    dw3x3_kernel<<<dim3(64,128,BB),256>>>(tA, tB, kvdw, nullptr, 128,0, 128,0);
    zero_small_kernel<<<8,256>>>();
    gram_kernel<<<dim3(32,16),256>>>(qbuf, tB);
    softmaxM_kernel<<<BB,256>>>(temp, projw);
    conv1x1_mma_kernel<<<dim3(HW/128,1,BB),256>>>(tB, out_xres, M, nullptr, x,
                                                  64,128,64, 64,0, HW, 0, 1);
}

extern "C" void kernel_launch(void* const* d_in, const int* in_sizes, int n_in,
                              void* d_out, int out_size)
{
    const float* x0      = (const float*)d_in[0];
    const float* x1      = (const float*)d_in[1];
    const float* rl_w1   = (const float*)d_in[2];
    const float* rl_b1   = (const float*)d_in[3];
    const float* rl_w2   = (const float*)d_in[4];
    const float* rl_b2   = (const float*)d_in[5];
    const float* rg_w1   = (const float*)d_in[6];
    const float* rg_w2   = (const float*)d_in[7];
    const float* att_temp= (const float*)d_in[8];
    const float* att_kv_w  = (const float*)d_in[9];
    const float* att_kv_dw = (const float*)d_in[10];
    const float* att_q_w   = (const float*)d_in[11];
    const float* att_q_dw  = (const float*)d_in[12];
    const float* att_proj_w= (const float*)d_in[13];
    const float* f1_dw   = (const float*)d_in[14];
    const float* f1_dwb  = (const float*)d_in[15];
    const float* f1_pw   = (const float*)d_in[16];
    const float* f1_pwb  = (const float*)d_in[17];
    const float* f2_dw   = (const float*)d_in[18];
    const float* f2_dwb  = (const float*)d_in[19];
    const float* f2_pw   = (const float*)d_in[20];
    const float* f2_pwb  = (const float*)d_in[21];
    float* out = (float*)d_out;

    float *fre, *spa, *qb, *tA, *tB, *fqA, *fqB, *M;
    unsigned* w3;
    cudaGetSymbolAddress((void**)&fre, g_fre);
    cudaGetSymbolAddress((void**)&spa, g_spa);
    cudaGetSymbolAddress((void**)&qb,  g_q);
    cudaGetSymbolAddress((void**)&tA,  g_tmpA);
    cudaGetSymbolAddress((void**)&tB,  g_tmpB);
    cudaGetSymbolAddress((void**)&fqA, g_fqA);
    cudaGetSymbolAddress((void**)&fqB, g_fqB);
    cudaGetSymbolAddress((void**)&M,   g_M);
    cudaGetSymbolAddress((void**)&w3,  g_w3);

    // ---- ResBlock_L: fre = relu(conv2(relu(conv1(x0)))) + x0 ----
    prep_w3_kernel<<<144,256>>>(rl_w1, rl_w2);
    conv3x3_mma_kernel<<<dim3(2,256,BB),256>>>(x0, tA, w3,            rl_b1, nullptr, 1);
    conv3x3_mma_kernel<<<dim3(2,256,BB),256>>>(tA, fre, w3 + 64*9*64, rl_b2, x0, 1);

    // ---- ResBlock_G: spa = irfft2(W2 @ relu(W1 @ rfft2(x1))) ----
    fft_row_fwd<<<16384,128>>>(x1, fqA);
    fft_col<<<dim3(17,64,BB),512>>>(fqA, -1.f, 1.f);
    conv1x1_mma_kernel<<<dim3(PF/128,2,BB),256>>>(fqA, fqB, rg_w1, nullptr, nullptr,
                                                  128,128,0, 128,0, PF, 1, 0);
    conv1x1_mma_kernel<<<dim3(PF/128,2,BB),256>>>(fqB, fqA, rg_w2, nullptr, nullptr,
                                                  128,128,0, 128,0, PF, 0, 0);
    fft_col<<<dim3(17,64,BB),512>>>(fqA, +1.f, 1.f/256.f);
    ifft_row_real<<<16384,128>>>(fqA, spa);

    // ---- attention (shared weights), fre then spa, each with residual ----
    run_attention(fre, spa, fre, att_q_w, att_q_dw, att_kv_w, att_kv_dw,
                  att_temp, att_proj_w, qb, tA, tB, M);
    run_attention(spa, fre, spa, att_q_w, att_q_dw, att_kv_w, att_kv_dw,
                  att_temp, att_proj_w, qb, tA, tB, M);

    // ---- fuse ----
    dw3x3_kernel<<<dim3(64,64,BB),256>>>(fre, tA, f1_dw,        f1_dwb,    64,0, 128,0);
    dw3x3_kernel<<<dim3(64,64,BB),256>>>(spa, tA, f1_dw + 64*9, f1_dwb+64, 64,0, 128,64);
    conv1x1_mma_kernel<<<dim3(HW/128,1,BB),256>>>(tA, qb, f1_pw, f1_pwb, nullptr,
                                                  128,128,0, 64,0, HW, 0, 0);
    dw3x3_kernel<<<dim3(64,64,BB),256>>>(qb, tB, f2_dw, f2_dwb, 64,0, 64,0);
    conv1x1_gate_kernel<<<dim3(HW/128,1,BB),256>>>(tB, f2_pw, f2_pwb, fre, spa, out);
}

// round 14
// speedup vs baseline: 2.8107x; 1.0286x over previous
#include <cuda_runtime.h>
#include <cuda_bf16.h>
#include <math.h>

#define BB 4
#define CC 64
#define HH 256
#define WWD 256
#define HW 65536
#define NF (BB*CC*HW)       /* 16777216 */
#define W129 129
#define PF (HH*W129)        /* 33024 */

// ---------------- scratch ----------------
__device__ __align__(16) float g_fre[NF];
__device__ __align__(16) float g_spa[NF];
__device__ __align__(16) float g_q[NF];          // bf16 view used in attention
__device__ __align__(16) float g_tmpA[2*NF];
__device__ __align__(16) float g_tmpB[2*NF];
__device__ __align__(16) float g_fqA[(size_t)BB*2*CC*PF];
__device__ __align__(16) float g_fqB[(size_t)BB*2*CC*PF];
__device__ float g_sumsq[2*BB*CC];
__device__ float g_gram[BB*8*64];
__device__ __align__(16) float g_M[BB*CC*CC];
__device__ __align__(16) unsigned g_w3[2][64*9*64]; // conv3x3 weights, [ci][tap][o], tf32

__device__ __forceinline__ unsigned f2tf(float f)
{
    unsigned r; asm("cvt.rna.tf32.f32 %0, %1;" : "=r"(r) : "f"(f)); return r;
}

// ---------------- weight pre-transpose for conv3x3 mma ----------------
__global__ void prep_w3_kernel(const float* __restrict__ w1, const float* __restrict__ w2)
{
    int idx = blockIdx.x*256 + threadIdx.x;
    if (idx >= 64*9*64) return;
    int o = idx & 63;
    int rt = idx >> 6;
    int ci = rt / 9, tap = rt - ci*9;
    size_t src = ((size_t)o*64 + ci)*9 + tap;
    g_w3[0][idx] = f2tf(w1[src]);
    g_w3[1][idx] = f2tf(w2[src]);
}

// ---------------- TF32 implicit-GEMM 3x3 conv (C=64) ----------------
__global__ void __launch_bounds__(256, 2)
conv3x3_mma_kernel(const float* __restrict__ in, float* __restrict__ out,
                   const unsigned* __restrict__ Wp, const float* __restrict__ bias,
                   const float* __restrict__ residual, int relu)
{
    __shared__ unsigned sW3[8][9][72];
    __shared__ unsigned sX3[8][3][132];
    int b  = blockIdx.z;
    int y  = blockIdx.y;
    int xb = blockIdx.x * 128;
    int tid  = threadIdx.x;
    int warp = tid >> 5, lane = tid & 31;
    int gid = lane >> 2, tig = lane & 3;
    int ow = (warp & 3) * 16, pw = (warp >> 2) * 64;

    float c[8][4];
#pragma unroll
    for (int t = 0; t < 8; t++)
#pragma unroll
        for (int i = 0; i < 4; i++) c[t][i] = 0.f;

    for (int c0 = 0; c0 < 64; c0 += 8) {
        const unsigned* wsrc = Wp + c0*576;
#pragma unroll
        for (int q = 0; q < 18; q++) {
            int idx = tid + q*256;
            int ci = idx / 576, rem = idx - ci*576;
            int tap = rem >> 6, o = rem & 63;
            sW3[ci][tap][o] = wsrc[idx];
        }
        for (int idx = tid; idx < 3168; idx += 256) {
            int col = idx % 132;
            int r = idx / 132;
            int ci = r / 3, dy = r - ci*3;
            float v = 0.f;
            int gx = xb - 1 + col;
            int gy = y + dy - 1;
            if (col < 130 && (unsigned)gx < 256u && (unsigned)gy < 256u)
                v = in[((size_t)(b*64 + c0 + ci)*256 + gy)*256 + gx];
            sX3[ci][dy][col] = f2tf(v);
        }
        __syncthreads();

#pragma unroll
        for (int tap = 0; tap < 9; tap++) {
            const int dy = tap / 3, dx = tap - 3*dy;
            unsigned a0 = sW3[tig    ][tap][ow + gid];
            unsigned a1 = sW3[tig    ][tap][ow + gid + 8];
            unsigned a2 = sW3[tig + 4][tap][ow + gid];
            unsigned a3 = sW3[tig + 4][tap][ow + gid + 8];
            const unsigned* br0 = &sX3[tig    ][dy][dx + pw + gid];
            const unsigned* br1 = &sX3[tig + 4][dy][dx + pw + gid];
#pragma unroll
            for (int t = 0; t < 8; t++) {
                unsigned b0 = br0[t*8];
                unsigned b1 = br1[t*8];
                asm("mma.sync.aligned.m16n8k8.row.col.f32.tf32.tf32.f32 "
                    "{%0,%1,%2,%3}, {%4,%5,%6,%7}, {%8,%9}, {%0,%1,%2,%3};"
                    : "+f"(c[t][0]), "+f"(c[t][1]), "+f"(c[t][2]), "+f"(c[t][3])
                    : "r"(a0), "r"(a1), "r"(a2), "r"(a3), "r"(b0), "r"(b1));
            }
        }
        __syncthreads();
    }

    int o0 = ow + gid;
    int o1 = o0 + 8;
    float bs0 = bias[o0], bs1 = bias[o1];
    size_t r0base = ((size_t)(b*64 + o0)*256 + y)*256 + xb + pw;
    size_t r1base = ((size_t)(b*64 + o1)*256 + y)*256 + xb + pw;
#pragma unroll
    for (int t = 0; t < 8; t++) {
        int p = t*8 + 2*tig;
        float v00 = c[t][0] + bs0, v01 = c[t][1] + bs0;
        float v10 = c[t][2] + bs1, v11 = c[t][3] + bs1;
        if (relu) {
            v00 = fmaxf(v00, 0.f); v01 = fmaxf(v01, 0.f);
            v10 = fmaxf(v10, 0.f); v11 = fmaxf(v11, 0.f);
        }
        if (residual) {
            float2 r0 = *(const float2*)&residual[r0base + p];
            float2 r1 = *(const float2*)&residual[r1base + p];
            v00 += r0.x; v01 += r0.y; v10 += r1.x; v11 += r1.y;
        }
        *(float2*)&out[r0base + p] = make_float2(v00, v01);
        *(float2*)&out[r1base + p] = make_float2(v10, v11);
    }
}

// ---------------- TF32 tensor-core 1x1 conv, fp32/bf16 in & out ----------------
__global__ void __launch_bounds__(256, 2)
conv1x1_mma_kernel(const void* __restrict__ in, void* __restrict__ out,
                   const float* __restrict__ W, const float* __restrict__ bias,
                   const float* __restrict__ residual,
                   int Cin, int CinTot, int cInOff,
                   int CoutTot, int cOutOff,
                   int P, int act, int perBatchW, int inBF, int outBF)
{
    __shared__ unsigned sW[32][72];
    __shared__ unsigned sX[32][136];
    int b  = blockIdx.z;
    int og = blockIdx.y * 64;
    int pb = blockIdx.x * 128;
    const float* Wb = W + (perBatchW ? (size_t)b*64*gridDim.y*Cin : 0);
    int tid  = threadIdx.x;
    int warp = tid >> 5, lane = tid & 31;
    int gid = lane >> 2, tig = lane & 3;
    int ow = (warp & 3) * 16, pw = (warp >> 2) * 64;

    float c[8][4];
#pragma unroll
    for (int t = 0; t < 8; t++)
#pragma unroll
        for (int i = 0; i < 4; i++) c[t][i] = 0.f;

    int wo = tid >> 2, wk = (tid & 3) * 8;
    int xk = tid >> 3, xp = (tid & 7) * 16;

    for (int k0 = 0; k0 < Cin; k0 += 32) {
        const float* wp = &Wb[(size_t)(og + wo)*Cin + k0 + wk];
        float4 w0 = *(const float4*)wp;
        float4 w1 = *(const float4*)(wp + 4);
        sW[wk+0][wo] = f2tf(w0.x); sW[wk+1][wo] = f2tf(w0.y);
        sW[wk+2][wo] = f2tf(w0.z); sW[wk+3][wo] = f2tf(w0.w);
        sW[wk+4][wo] = f2tf(w1.x); sW[wk+5][wo] = f2tf(w1.y);
        sW[wk+6][wo] = f2tf(w1.z); sW[wk+7][wo] = f2tf(w1.w);

        size_t xbase = ((size_t)b*CinTot + cInOff + k0 + xk)*P + pb + xp;
        if (inBF) {
            const __nv_bfloat16* xpt = (const __nv_bfloat16*)in + xbase;
#pragma unroll
            for (int q = 0; q < 2; q++) {
                uint4 raw = *(const uint4*)(xpt + 8*q);
                const __nv_bfloat162* h = (const __nv_bfloat162*)&raw;
                unsigned u[8];
#pragma unroll
                for (int i = 0; i < 4; i++) {
                    float2 f = __bfloat1622float2(h[i]);
                    u[2*i]   = __float_as_uint(f.x);   // bf16->fp32 exact, valid tf32
                    u[2*i+1] = __float_as_uint(f.y);
                }
                *(uint4*)&sX[xk][xp + 8*q]     = *(uint4*)&u[0];
                *(uint4*)&sX[xk][xp + 8*q + 4] = *(uint4*)&u[4];
            }
        } else {
            const float* xpt = (const float*)in + xbase;
#pragma unroll
            for (int q = 0; q < 4; q++) {
                float4 v = *(const float4*)(xpt + 4*q);
                uint4 u = make_uint4(f2tf(v.x), f2tf(v.y), f2tf(v.z), f2tf(v.w));
                *(uint4*)&sX[xk][xp + 4*q] = u;
            }
        }
        __syncthreads();

#pragma unroll
        for (int ks = 0; ks < 4; ks++) {
            int kk = ks * 8;
            unsigned a0 = sW[kk + tig    ][ow + gid];
            unsigned a1 = sW[kk + tig    ][ow + gid + 8];
            unsigned a2 = sW[kk + tig + 4][ow + gid];
            unsigned a3 = sW[kk + tig + 4][ow + gid + 8];
#pragma unroll
            for (int t = 0; t < 8; t++) {
                unsigned b0 = sX[kk + tig    ][pw + t*8 + gid];
                unsigned b1 = sX[kk + tig + 4][pw + t*8 + gid];
                asm("mma.sync.aligned.m16n8k8.row.col.f32.tf32.tf32.f32 "
                    "{%0,%1,%2,%3}, {%4,%5,%6,%7}, {%8,%9}, {%0,%1,%2,%3};"
                    : "+f"(c[t][0]), "+f"(c[t][1]), "+f"(c[t][2]), "+f"(c[t][3])
                    : "r"(a0), "r"(a1), "r"(a2), "r"(a3), "r"(b0), "r"(b1));
            }
        }
        __syncthreads();
    }

    int o0 = og + ow + gid;
    int o1 = o0 + 8;
    float bs0 = bias ? bias[o0] : 0.f;
    float bs1 = bias ? bias[o1] : 0.f;
    size_t r0base = ((size_t)b*CoutTot + cOutOff + o0)*P + pb + pw;
    size_t r1base = ((size_t)b*CoutTot + cOutOff + o1)*P + pb + pw;
#pragma unroll
    for (int t = 0; t < 8; t++) {
        int p = t*8 + 2*tig;
        float v00 = c[t][0] + bs0, v01 = c[t][1] + bs0;
        float v10 = c[t][2] + bs1, v11 = c[t][3] + bs1;
        if (act == 1) {
            v00 = fmaxf(v00, 0.f); v01 = fmaxf(v01, 0.f);
            v10 = fmaxf(v10, 0.f); v11 = fmaxf(v11, 0.f);
        }
        if (residual) {
            float2 r0 = *(const float2*)&residual[r0base + p];
            float2 r1 = *(const float2*)&residual[r1base + p];
            v00 += r0.x; v01 += r0.y; v10 += r1.x; v11 += r1.y;
        }
        if (outBF) {
            __nv_bfloat16* ob = (__nv_bfloat16*)out;
            *(__nv_bfloat162*)&ob[r0base + p] = __floats2bfloat162_rn(v00, v01);
            *(__nv_bfloat162*)&ob[r1base + p] = __floats2bfloat162_rn(v10, v11);
        } else {
            float* of = (float*)out;
            *(float2*)&of[r0base + p] = make_float2(v00, v01);
            *(float2*)&of[r1base + p] = make_float2(v10, v11);
        }
    }
}

// ---------------- fused: f2_pw conv (64->128, bf16 in) + sigmoid + gate + nan_to_num ----
__global__ void __launch_bounds__(256, 2)
conv1x1_gate_kernel(const __nv_bfloat16* __restrict__ in, const float* __restrict__ W,
                    const float* __restrict__ bias,
                    const float* __restrict__ fre, const float* __restrict__ spa,
                    float* __restrict__ out)
{
    __shared__ float sA[16][132];
    __shared__ float sB[16][128];
    int b  = blockIdx.z;
    int pb = blockIdx.x * 128;
    int tid = threadIdx.x;
    int lo = tid & 127, lk8 = (tid >> 7) * 8;
    int rB = tid >> 4, fB = tid & 15;
    int p0 = (tid & 15) << 2;
    int ox0 = (tid >> 4) << 2;

    float acc[8][8];
#pragma unroll
    for (int j = 0; j < 8; j++)
#pragma unroll
        for (int i = 0; i < 8; i++) acc[j][i] = 0.f;

    for (int k0 = 0; k0 < 64; k0 += 16) {
        float4 w0 = *(const float4*)&W[(size_t)lo*64 + k0 + lk8];
        float4 w1 = *(const float4*)&W[(size_t)lo*64 + k0 + lk8 + 4];
        sA[lk8+0][lo]=w0.x; sA[lk8+1][lo]=w0.y; sA[lk8+2][lo]=w0.z; sA[lk8+3][lo]=w0.w;
        sA[lk8+4][lo]=w1.x; sA[lk8+5][lo]=w1.y; sA[lk8+6][lo]=w1.z; sA[lk8+7][lo]=w1.w;
        const __nv_bfloat16* bp = in + ((size_t)b*64 + k0 + rB)*HW + pb + fB*8;
        uint4 raw = *(const uint4*)bp;
        const __nv_bfloat162* h = (const __nv_bfloat162*)&raw;
#pragma unroll
        for (int i = 0; i < 4; i++) {
            float2 f = __bfloat1622float2(h[i]);
            sB[rB][fB*8 + 2*i]     = f.x;
            sB[rB][fB*8 + 2*i + 1] = f.y;
        }
        __syncthreads();
#pragma unroll
        for (int k = 0; k < 16; k++) {
            float vv[8];
            *(float4*)&vv[0] = *(const float4*)&sB[k][p0];
            *(float4*)&vv[4] = *(const float4*)&sB[k][p0+64];
            float aL[4], aH[4];
            *(float4*)&aL[0] = *(const float4*)&sA[k][ox0];
            *(float4*)&aH[0] = *(const float4*)&sA[k][ox0+64];
#pragma unroll
            for (int j = 0; j < 4; j++)
#pragma unroll
                for (int i = 0; i < 8; i++) {
                    acc[j][i]   += aL[j]*vv[i];
                    acc[4+j][i] += aH[j]*vv[i];
                }
        }
        __syncthreads();
    }

#pragma unroll
    for (int j = 0; j < 4; j++) {
        int c = ox0 + j;
        float bL = bias[c], bH = bias[c + 64];
        size_t base = ((size_t)b*64 + c)*HW + pb + p0;
#pragma unroll
        for (int ch = 0; ch < 2; ch++) {
            float4 f4 = *(const float4*)&fre[base + 64*ch];
            float4 s4 = *(const float4*)&spa[base + 64*ch];
            float fv[4] = {f4.x, f4.y, f4.z, f4.w};
            float sv[4] = {s4.x, s4.y, s4.z, s4.w};
            float o4[4];
#pragma unroll
            for (int i = 0; i < 4; i++) {
                float gf = 1.f/(1.f + expf(-(acc[j][ch*4+i]   + bL)));
                float gs = 1.f/(1.f + expf(-(acc[4+j][ch*4+i] + bH)));
                float v = fv[i]*gf + sv[i]*gs;
                if (isnan(v) || isinf(v)) v = 1e-5f;
                o4[i] = v;
            }
            *(float4*)&out[base + 64*ch] = make_float4(o4[0],o4[1],o4[2],o4[3]);
        }
    }
}

// ---------------- depthwise 3x3 (pad 1), 4 px/thread, fp32/bf16 in & out ----------------
__global__ void dw3x3_kernel(const void* __restrict__ in, void* __restrict__ out,
                             const float* __restrict__ w, const float* __restrict__ bias,
                             int CinTot, int cInOff, int CoutTot, int cOutOff,
                             int inBF, int outBF)
{
    int b = blockIdx.z, c = blockIdx.y;
    int p4 = (blockIdx.x*256 + threadIdx.x) * 4;
    int y = p4 >> 8, x = p4 & 255;
    size_t ibase = ((size_t)b*CinTot + cInOff + c)*HW;
    float bs = bias ? bias[c] : 0.f;
    float a0 = bs, a1 = bs, a2 = bs, a3 = bs;
#pragma unroll
    for (int dy = 0; dy < 3; dy++) {
        int gy = y + dy - 1;
        if ((unsigned)gy >= 256u) continue;
        float fx, fy, fz, fw, l, r;
        if (inBF) {
            const __nv_bfloat16* row = (const __nv_bfloat16*)in + ibase + gy*256 + x;
            __nv_bfloat162 h0 = *(const __nv_bfloat162*)row;
            __nv_bfloat162 h1 = *(const __nv_bfloat162*)(row + 2);
            float2 f0 = __bfloat1622float2(h0);
            float2 f1 = __bfloat1622float2(h1);
            fx = f0.x; fy = f0.y; fz = f1.x; fw = f1.y;
            l = (x > 0)   ? __bfloat162float(row[-1]) : 0.f;
            r = (x < 252) ? __bfloat162float(row[4])  : 0.f;
        } else {
            const float* row = (const float*)in + ibase + gy*256 + x;
            float4 f = *(const float4*)row;
            fx = f.x; fy = f.y; fz = f.z; fw = f.w;
            l = (x > 0)   ? row[-1] : 0.f;
            r = (x < 252) ? row[4]  : 0.f;
        }
        float wA = w[c*9 + dy*3], wB = w[c*9 + dy*3 + 1], wC = w[c*9 + dy*3 + 2];
        a0 += wA*l  + wB*fx + wC*fy;
        a1 += wA*fx + wB*fy + wC*fz;
        a2 += wA*fy + wB*fz + wC*fw;
        a3 += wA*fz + wB*fw + wC*r;
    }
    size_t obase = ((size_t)b*CoutTot + cOutOff + c)*HW + p4;
    if (outBF) {
        __nv_bfloat16* ob = (__nv_bfloat16*)out;
        *(__nv_bfloat162*)&ob[obase]     = __floats2bfloat162_rn(a0, a1);
        *(__nv_bfloat162*)&ob[obase + 2] = __floats2bfloat162_rn(a2, a3);
    } else {
        *(float4*)&((float*)out)[obase] = make_float4(a0,a1,a2,a3);
    }
}

// ---------------- radix-4 256-pt FFT (skewed smem, digit-reversed input) ----------------
__device__ __forceinline__ int SK(int p) { return p + (p >> 5); }
__device__ __forceinline__ int DR4(int p)
{
    return ((p & 3) << 6) | (((p >> 2) & 3) << 4) | (((p >> 4) & 3) << 2) | ((p >> 6) & 3);
}

__device__ __forceinline__ void make_tw256(float* twr, float* twi, int tid, int nthr, float dir)
{
    for (int m = tid; m < 256; m += nthr) {
        float s, c;
        __sincosf(dir * 6.283185307179586f * (float)m * (1.f/256.f), &s, &c);
        twr[m] = c; twi[m] = s;
    }
}

__device__ __forceinline__ void bf4(float* sr, float* si,
                                    int i0, int i1, int i2, int i3,
                                    float w1r, float w1i, float w2r, float w2i,
                                    float w3r, float w3i, float dir, bool usetw)
{
    float x0r = sr[i0], x0i = si[i0];
    float x1r = sr[i1], x1i = si[i1];
    float x2r = sr[i2], x2i = si[i2];
    float x3r = sr[i3], x3i = si[i3];
    float t1r, t1i, t2r, t2i, t3r, t3i;
    if (usetw) {
        t1r = x1r*w1r - x1i*w1i; t1i = x1r*w1i + x1i*w1r;
        t2r = x2r*w2r - x2i*w2i; t2i = x2r*w2i + x2i*w2r;
        t3r = x3r*w3r - x3i*w3i; t3i = x3r*w3i + x3i*w3r;
    } else {
        t1r = x1r; t1i = x1i; t2r = x2r; t2i = x2i; t3r = x3r; t3i = x3i;
    }
    float ar = x0r + t2r, ai = x0i + t2i;
    float br = x0r - t2r, bi = x0i - t2i;
    float cr = t1r + t3r, ci = t1i + t3i;
    float dr = t1r - t3r, di = t1i - t3i;
    sr[i0] = ar + cr;        si[i0] = ai + ci;
    sr[i2] = ar - cr;        si[i2] = ai - ci;
    sr[i1] = br - dir*di;    si[i1] = bi + dir*dr;
    sr[i3] = br + dir*di;    si[i3] = bi - dir*dr;
}

__device__ __forceinline__ void fft256_r4(float* sr, float* si, int j,
                                          const float* twr, const float* twi, float dir)
{
    __syncthreads();
    {
        int base = 4*j;
        bf4(sr, si, SK(base), SK(base+1), SK(base+2), SK(base+3),
            0.f,0.f,0.f,0.f,0.f,0.f, dir, false);
    }
    __syncthreads();
    {
        int jj = j & 3, g = j >> 2;
        int base = g*16 + jj;
        bf4(sr, si, SK(base), SK(base+4), SK(base+8), SK(base+12),
            twr[16*jj], twi[16*jj], twr[32*jj], twi[32*jj], twr[48*jj], twi[48*jj],
            dir, true);
    }
    __syncthreads();
    {
        int jj = j & 15, g = j >> 4;
        int base = g*64 + jj;
        bf4(sr, si, SK(base), SK(base+16), SK(base+32), SK(base+48),
            twr[4*jj], twi[4*jj], twr[8*jj], twi[8*jj], twr[12*jj], twi[12*jj],
            dir, true);
    }
    __syncthreads();
    {
        bf4(sr, si, SK(j), SK(j+64), SK(j+128), SK(j+192),
            twr[j], twi[j], twr[2*j], twi[2*j], twr[3*j], twi[3*j],
            dir, true);
    }
    __syncthreads();
}

// forward row rFFT: 2 packed complex FFTs per block (4 channels), 128 threads
__global__ void fft_row_fwd(const float* __restrict__ x, float* __restrict__ fq)
{
    __shared__ float sr[2][264], si[2][264], twr[256], twi[256];
    int blk = blockIdx.x;
    int b = blk >> 12, c4 = (blk >> 8) & 15, h = blk & 255;
    int tid = threadIdx.x;
    int fid = tid >> 6, j = tid & 63;
    int cA = c4*4 + fid*2;
    const float* xa = x + ((size_t)(b*64 + cA)*256 + h)*256;
    const float* xb = xa + 65536;
    make_tw256(twr, twi, tid, 128, -1.f);
    float* R = sr[fid]; float* I = si[fid];
    for (int w = j; w < 256; w += 64) {
        int d = SK(DR4(w));
        R[d] = xa[w]; I[d] = xb[w];
    }
    fft256_r4(R, I, j, twr, twi, -1.f);
    float* frA = fq + ((size_t)(b*128 + cA)*HH + h)*W129;
    float* fiA = fq + ((size_t)(b*128 + 64 + cA)*HH + h)*W129;
    float* frB = frA + (size_t)HH*W129;
    float* fiB = fiA + (size_t)HH*W129;
    for (int k = j; k <= 128; k += 64) {
        int km = (256 - k) & 255;
        float xr = R[SK(k)], xi = I[SK(k)], yr = R[SK(km)], yi = I[SK(km)];
        frA[k] = 0.5f*(xr + yr);
        fiA[k] = 0.5f*(xi - yi);
        frB[k] = 0.5f*(xi + yi);
        fiB[k] = 0.5f*(yr - xr);
    }
}

// inverse row rFFT (imag of DC/Nyquist ignored — pocketfft C2R semantics)
__global__ void ifft_row_real(const float* __restrict__ fq, float* __restrict__ out)
{
    __shared__ float sr[2][264], si[2][264], twr[256], twi[256];
    int blk = blockIdx.x;
    int b = blk >> 12, c4 = (blk >> 8) & 15, h = blk & 255;
    int tid = threadIdx.x;
    int fid = tid >> 6, j = tid & 63;
    int cA = c4*4 + fid*2;
    const float* frA = fq + ((size_t)(b*128 + cA)*HH + h)*W129;
    const float* fiA = fq + ((size_t)(b*128 + 64 + cA)*HH + h)*W129;
    const float* frB = frA + (size_t)HH*W129;
    const float* fiB = fiA + (size_t)HH*W129;
    make_tw256(twr, twi, tid, 128, +1.f);
    float* R = sr[fid]; float* I = si[fid];
    for (int k = j; k <= 128; k += 64) {
        float Ar = frA[k], Ai = fiA[k], Br = frB[k], Bi = fiB[k];
        if (k == 0 || k == 128) { Ai = 0.f; Bi = 0.f; }
        int d = SK(DR4(k));
        R[d] = Ar - Bi; I[d] = Ai + Br;
        if (k > 0 && k < 128) {
            int d2 = SK(DR4(256 - k));
            R[d2] = Ar + Bi; I[d2] = Br - Ai;
        }
    }
    fft256_r4(R, I, j, twr, twi, +1.f);
    float* oa = out + ((size_t)(b*64 + cA)*256 + h)*256;
    float* ob = oa + 65536;
    const float s = 1.f/256.f;
    for (int w = j; w < 256; w += 64) { oa[w] = R[SK(w)]*s; ob[w] = I[SK(w)]*s; }
}

// tiled column FFT: 8 columns per block, 512 threads
__global__ void __launch_bounds__(512)
fft_col(float* fq, float dir, float scale)
{
    __shared__ float sr[8*264], si[8*264];
    __shared__ float twr[256], twi[256];
    int b = blockIdx.z, c = blockIdx.y;
    int w0 = blockIdx.x * 8;
    int nw = 129 - w0; if (nw > 8) nw = 8;
    float* fr = fq + ((size_t)(b*128 + c)*HH)*W129;
    float* fi = fq + ((size_t)(b*128 + 64 + c)*HH)*W129;
    int tid = threadIdx.x;

    make_tw256(twr, twi, tid, 512, dir);
#pragma unroll
    for (int r = 0; r < 4; r++) {
        int l = tid + 512*r;
        int h = l >> 3, w = l & 7;
        if (w < nw) {
            int d = w*264 + SK(DR4(h));
            sr[d] = fr[(size_t)h*W129 + w0 + w];
            si[d] = fi[(size_t)h*W129 + w0 + w];
        }
    }
    int col = tid >> 6, j = tid & 63;
    fft256_r4(sr + col*264, si + col*264, j, twr, twi, dir);
#pragma unroll
    for (int r = 0; r < 4; r++) {
        int l = tid + 512*r;
        int h = l >> 3, w = l & 7;
        if (w < nw) {
            fr[(size_t)h*W129 + w0 + w] = sr[w*264 + SK(h)]*scale;
            fi[(size_t)h*W129 + w0 + w] = si[w*264 + SK(h)]*scale;
        }
    }
}

// ---------------- attention small kernels ----------------
__global__ void zero_small_kernel()
{
    int t = blockIdx.x*256 + threadIdx.x;
    if (t < 512)  g_sumsq[t] = 0.f;
    if (t < 2048) g_gram[t]  = 0.f;
}

// fused gram + sumsq, bf16 inputs
__global__ void gram_kernel(const __nv_bfloat16* __restrict__ q,
                            const __nv_bfloat16* __restrict__ k)
{
    int bh = blockIdx.x;
    int b = bh >> 3, head = bh & 7;
    const __nv_bfloat16* qb = q + ((size_t)b*64  + head*8)*HW;
    const __nv_bfloat16* kb = k + ((size_t)b*128 + head*8)*HW;
    float acc[64], qs[8], ks[8];
#pragma unroll
    for (int t = 0; t < 64; t++) acc[t] = 0.f;
#pragma unroll
    for (int t = 0; t < 8; t++) { qs[t] = 0.f; ks[t] = 0.f; }
    int start = blockIdx.y*4096;
    for (int n = start + threadIdx.x; n < start + 4096; n += 256) {
        float qv[8], kv[8];
#pragma unroll
        for (int i = 0; i < 8; i++) {
            qv[i] = __bfloat162float(qb[(size_t)i*HW + n]);
            kv[i] = __bfloat162float(kb[(size_t)i*HW + n]);
        }
#pragma unroll
        for (int i = 0; i < 8; i++) { qs[i] += qv[i]*qv[i]; ks[i] += kv[i]*kv[i]; }
#pragma unroll
        for (int i = 0; i < 8; i++)
#pragma unroll
            for (int j = 0; j < 8; j++)
                acc[i*8+j] += qv[i]*kv[j];
    }
#pragma unroll
    for (int t = 0; t < 64; t++) {
        float v = acc[t];
#pragma unroll
        for (int off = 16; off > 0; off >>= 1) v += __shfl_down_sync(0xffffffffu, v, off);
        if ((threadIdx.x & 31) == 0) atomicAdd(&g_gram[bh*64 + t], v);
    }
#pragma unroll
    for (int t = 0; t < 8; t++) {
        float v = qs[t];
#pragma unroll
        for (int off = 16; off > 0; off >>= 1) v += __shfl_down_sync(0xffffffffu, v, off);
        if ((threadIdx.x & 31) == 0) atomicAdd(&g_sumsq[b*64 + head*8 + t], v);
        v = ks[t];
#pragma unroll
        for (int off = 16; off > 0; off >>= 1) v += __shfl_down_sync(0xffffffffu, v, off);
        if ((threadIdx.x & 31) == 0) atomicAdd(&g_sumsq[256 + b*64 + head*8 + t], v);
    }
}

__global__ void softmaxM_kernel(const float* __restrict__ temp, const float* __restrict__ proj)
{
    __shared__ float A[512];
    __shared__ float dq[64], dk[64];
    int b = blockIdx.x;
    int tid = threadIdx.x;
    if (tid < 64)              dq[tid]      = fmaxf(sqrtf(g_sumsq[b*64 + tid]), 1e-12f);
    else if (tid < 128)        dk[tid - 64] = fmaxf(sqrtf(g_sumsq[256 + b*64 + tid - 64]), 1e-12f);
    __syncthreads();
    for (int t = tid; t < 512; t += 256) {
        int head = t >> 6, i = (t >> 3) & 7, j = t & 7;
        A[t] = g_gram[b*512 + t] / (dq[head*8 + i]*dk[head*8 + j]) * temp[head];
    }
    __syncthreads();
    if (tid < 64) {
        float m = -1e30f;
#pragma unroll
        for (int j = 0; j < 8; j++) m = fmaxf(m, A[tid*8 + j]);
        float s = 0.f;
        float e[8];
#pragma unroll
        for (int j = 0; j < 8; j++) { e[j] = expf(A[tid*8 + j] - m); s += e[j]; }
        float inv = 1.f/s;
#pragma unroll
        for (int j = 0; j < 8; j++) A[tid*8 + j] = e[j]*inv;
    }
    __syncthreads();
    for (int idx = tid; idx < 4096; idx += 256) {
        int co = idx >> 6, cv = idx & 63;
        int hv = cv >> 3, jv = cv & 7;
        float s = 0.f;
#pragma unroll
        for (int i = 0; i < 8; i++)
            s += proj[co*64 + hv*8 + i] * A[hv*64 + i*8 + jv];
        g_M[b*4096 + idx] = s;
    }
}

// ---------------- host orchestration ----------------
static void run_attention(const float* x, const float* y, float* out_xres,
                          const float* qw, const float* qdw,
                          const float* kvw, const float* kvdw,
                          const float* temp, const float* projw,
                          void* qbuf, void* tA, void* tB, float* M)
{
    // q path: 1x1 (fp32 in -> bf16 out) then dw3x3 (bf16 -> bf16)
    conv1x1_mma_kernel<<<dim3(HW/128,1,BB),256>>>(x, tB, qw, nullptr, nullptr,
                                                  64,64,0, 64,0, HW, 0, 0, 0, 1);
    dw3x3_kernel<<<dim3(64,64,BB),256>>>(tB, qbuf, qdw, nullptr, 64,0, 64,0, 1, 1);
    // kv path
    conv1x1_mma_kernel<<<dim3(HW/128,2,BB),256>>>(y, tA, kvw, nullptr, nullptr,
                                                  64,64,0, 128,0, HW, 0, 0, 0, 1);
    dw3x3_kernel<<<dim3(64,128,BB),256>>>(tA, tB, kvdw, nullptr, 128,0, 128,0, 1, 1);
    zero_small_kernel<<<8,256>>>();
    gram_kernel<<<dim3(32,16),256>>>((const __nv_bfloat16*)qbuf, (const __nv_bfloat16*)tB);
    softmaxM_kernel<<<BB,256>>>(temp, projw);
    // out = M[b] @ v + x   (v = tB bf16 channels 64..127), fp32 out
    conv1x1_mma_kernel<<<dim3(HW/128,1,BB),256>>>(tB, out_xres, M, nullptr, x,
                                                  64,128,64, 64,0, HW, 0, 1, 1, 0);
}

extern "C" void kernel_launch(void* const* d_in, const int* in_sizes, int n_in,
                              void* d_out, int out_size)
{
    const float* x0      = (const float*)d_in[0];
    const float* x1      = (const float*)d_in[1];
    const float* rl_w1   = (const float*)d_in[2];
    const float* rl_b1   = (const float*)d_in[3];
    const float* rl_w2   = (const float*)d_in[4];
    const float* rl_b2   = (const float*)d_in[5];
    const float* rg_w1   = (const float*)d_in[6];
    const float* rg_w2   = (const float*)d_in[7];
    const float* att_temp= (const float*)d_in[8];
    const float* att_kv_w  = (const float*)d_in[9];
    const float* att_kv_dw = (const float*)d_in[10];
    const float* att_q_w   = (const float*)d_in[11];
    const float* att_q_dw  = (const float*)d_in[12];
    const float* att_proj_w= (const float*)d_in[13];
    const float* f1_dw   = (const float*)d_in[14];
    const float* f1_dwb  = (const float*)d_in[15];
    const float* f1_pw   = (const float*)d_in[16];
    const float* f1_pwb  = (const float*)d_in[17];
    const float* f2_dw   = (const float*)d_in[18];
    const float* f2_dwb  = (const float*)d_in[19];
    const float* f2_pw   = (const float*)d_in[20];
    const float* f2_pwb  = (const float*)d_in[21];
    float* out = (float*)d_out;

    float *fre, *spa, *qb, *tA, *tB, *fqA, *fqB, *M;
    unsigned* w3;
    cudaGetSymbolAddress((void**)&fre, g_fre);
    cudaGetSymbolAddress((void**)&spa, g_spa);
    cudaGetSymbolAddress((void**)&qb,  g_q);
    cudaGetSymbolAddress((void**)&tA,  g_tmpA);
    cudaGetSymbolAddress((void**)&tB,  g_tmpB);
    cudaGetSymbolAddress((void**)&fqA, g_fqA);
    cudaGetSymbolAddress((void**)&fqB, g_fqB);
    cudaGetSymbolAddress((void**)&M,   g_M);
    cudaGetSymbolAddress((void**)&w3,  g_w3);

    // ---- ResBlock_L: fre = relu(conv2(relu(conv1(x0)))) + x0 ----
    prep_w3_kernel<<<144,256>>>(rl_w1, rl_w2);
    conv3x3_mma_kernel<<<dim3(2,256,BB),256>>>(x0, tA, w3,            rl_b1, nullptr, 1);
    conv3x3_mma_kernel<<<dim3(2,256,BB),256>>>(tA, fre, w3 + 64*9*64, rl_b2, x0, 1);

    // ---- ResBlock_G: spa = irfft2(W2 @ relu(W1 @ rfft2(x1))) ----
    fft_row_fwd<<<16384,128>>>(x1, fqA);
    fft_col<<<dim3(17,64,BB),512>>>(fqA, -1.f, 1.f);
    conv1x1_mma_kernel<<<dim3(PF/128,2,BB),256>>>(fqA, fqB, rg_w1, nullptr, nullptr,
                                                  128,128,0, 128,0, PF, 1, 0, 0, 0);
    conv1x1_mma_kernel<<<dim3(PF/128,2,BB),256>>>(fqB, fqA, rg_w2, nullptr, nullptr,
                                                  128,128,0, 128,0, PF, 0, 0, 0, 0);
    fft_col<<<dim3(17,64,BB),512>>>(fqA, +1.f, 1.f/256.f);
    ifft_row_real<<<16384,128>>>(fqA, spa);

    // ---- attention (shared weights), fre then spa, each with residual ----
    run_attention(fre, spa, fre, att_q_w, att_q_dw, att_kv_w, att_kv_dw,
                  att_temp, att_proj_w, qb, tA, tB, M);
    run_attention(spa, fre, spa, att_q_w, att_q_dw, att_kv_w, att_kv_dw,
                  att_temp, att_proj_w, qb, tA, tB, M);

    // ---- fuse ----
    dw3x3_kernel<<<dim3(64,64,BB),256>>>(fre, tA, f1_dw,        f1_dwb,    64,0, 128,0,  0, 1);
    dw3x3_kernel<<<dim3(64,64,BB),256>>>(spa, tA, f1_dw + 64*9, f1_dwb+64, 64,0, 128,64, 0, 1);
    conv1x1_mma_kernel<<<dim3(HW/128,1,BB),256>>>(tA, qb, f1_pw, f1_pwb, nullptr,
                                                  128,128,0, 64,0, HW, 0, 0, 1, 1);
    dw3x3_kernel<<<dim3(64,64,BB),256>>>(qb, tB, f2_dw, f2_dwb, 64,0, 64,0, 1, 1);
    conv1x1_gate_kernel<<<dim3(HW/128,1,BB),256>>>((const __nv_bfloat16*)tB, f2_pw, f2_pwb,
                                                   fre, spa, out);
}